// round 2
// baseline (speedup 1.0000x reference)
#include <cuda_runtime.h>
#include <cuda_bf16.h>
#include <cstdint>

// Problem constants
#define Bc   8
#define Tc   1024
#define Dc   1024
#define NHc  16
#define DKc  64
#define D3c  3072

// Scratch (device globals — allocation-free rule)
__device__ float g_qkv[(size_t)Bc * Tc * D3c];   // 96 MB  [b*T+t][3D]
__device__ float g_ctx[(size_t)Bc * Tc * Dc];    // 32 MB  [b*T+t][D]

// ---------------------------------------------------------------------------
// Generic tiled SGEMM with bias: C[M,N] = A[M,K] @ B[K,N] + bias[N]
// BM=BN=128, BK=8, 256 threads, 8x8 micro-tile. All dims divisible.
// ---------------------------------------------------------------------------
__global__ __launch_bounds__(256) void sgemm_bias_kernel(
    const float* __restrict__ A, const float* __restrict__ Bm,
    const float* __restrict__ bias, float* __restrict__ C,
    int M, int N, int K)
{
    __shared__ float As[8][128];
    __shared__ float Bs[8][128];

    const int tid = threadIdx.x;
    const int tx  = tid & 15;       // 0..15 -> col group
    const int ty  = tid >> 4;       // 0..15 -> row group

    const int rowBase = blockIdx.y * 128;
    const int colBase = blockIdx.x * 128;

    const int aRow = tid >> 1;            // 0..127
    const int aCol = (tid & 1) * 4;       // 0 or 4
    const int bRow = tid >> 5;            // 0..7
    const int bCol = (tid & 31) * 4;      // 0..124

    const float* Aptr = A + (size_t)rowBase * K;
    const float* Bptr = Bm + colBase;

    float acc[8][8];
#pragma unroll
    for (int i = 0; i < 8; i++)
#pragma unroll
        for (int j = 0; j < 8; j++) acc[i][j] = 0.f;

    for (int k0 = 0; k0 < K; k0 += 8) {
        float4 av = *(const float4*)(Aptr + (size_t)aRow * K + k0 + aCol);
        As[aCol + 0][aRow] = av.x;
        As[aCol + 1][aRow] = av.y;
        As[aCol + 2][aRow] = av.z;
        As[aCol + 3][aRow] = av.w;
        float4 bv = *(const float4*)(Bptr + (size_t)(k0 + bRow) * N + bCol);
        *(float4*)&Bs[bRow][bCol] = bv;
        __syncthreads();

#pragma unroll
        for (int kk = 0; kk < 8; kk++) {
            float rm[8], rn[8];
            *(float4*)&rm[0] = *(float4*)&As[kk][ty * 8];
            *(float4*)&rm[4] = *(float4*)&As[kk][ty * 8 + 4];
            *(float4*)&rn[0] = *(float4*)&Bs[kk][tx * 8];
            *(float4*)&rn[4] = *(float4*)&Bs[kk][tx * 8 + 4];
#pragma unroll
            for (int i = 0; i < 8; i++)
#pragma unroll
                for (int j = 0; j < 8; j++)
                    acc[i][j] = fmaf(rm[i], rn[j], acc[i][j]);
        }
        __syncthreads();
    }

#pragma unroll
    for (int i = 0; i < 8; i++) {
        const int r = rowBase + ty * 8 + i;
#pragma unroll
        for (int j = 0; j < 8; j += 4) {
            const int c = colBase + tx * 8 + j;
            float4 o;
            o.x = acc[i][j + 0] + bias[c + 0];
            o.y = acc[i][j + 1] + bias[c + 1];
            o.z = acc[i][j + 2] + bias[c + 2];
            o.w = acc[i][j + 3] + bias[c + 3];
            *(float4*)(C + (size_t)r * N + c) = o;
        }
    }
}

// ---------------------------------------------------------------------------
// Scores: logits[bh][q][k] = (Q[bh][q] . K[bh][k]) / 8, masked -> -inf
// Block = (bh, q-tile of 64). Tiles K in chunks of 64.
// mask is int32 (jax bool -> harness int32): nonzero = keep.
// ---------------------------------------------------------------------------
__global__ __launch_bounds__(256) void scores_kernel(
    const float* __restrict__ qkv, const int* __restrict__ mask,
    float* __restrict__ logits)
{
    __shared__ float Qs[64][68];   // [d][q]  (pad 68: float4-aligned rows)
    __shared__ float Ks[64][68];   // [d][k]

    const int bh = blockIdx.x;             // 0..127
    const int b  = bh >> 4;
    const int h  = bh & 15;
    const int q0 = blockIdx.y * 64;

    const int tid = threadIdx.x;
    const int tx  = tid & 15;
    const int ty  = tid >> 4;

    // Load Q tile (transposed into [d][q])
    {
        const int r = tid >> 4;            // 0..15
        const int c = (tid & 15) * 4;      // 0..60
#pragma unroll
        for (int p = 0; p < 4; p++) {
            const int q = r + p * 16;
            float4 v = *(const float4*)(qkv + ((size_t)(b * Tc + q0 + q)) * D3c + h * DKc + c);
            Qs[c + 0][q] = v.x; Qs[c + 1][q] = v.y;
            Qs[c + 2][q] = v.z; Qs[c + 3][q] = v.w;
        }
    }

    float* out = logits + ((size_t)bh * Tc + q0) * Tc;
    const float NEG_INF = __int_as_float(0xff800000);

    for (int k0 = 0; k0 < Tc; k0 += 64) {
        __syncthreads();   // protect Ks reuse (also covers initial Q load)
        {
            const int r = tid >> 4;
            const int c = (tid & 15) * 4;
#pragma unroll
            for (int p = 0; p < 4; p++) {
                const int kk = r + p * 16;
                float4 v = *(const float4*)(qkv + ((size_t)(b * Tc + k0 + kk)) * D3c + Dc + h * DKc + c);
                Ks[c + 0][kk] = v.x; Ks[c + 1][kk] = v.y;
                Ks[c + 2][kk] = v.z; Ks[c + 3][kk] = v.w;
            }
        }
        __syncthreads();

        float acc[4][4];
#pragma unroll
        for (int i = 0; i < 4; i++)
#pragma unroll
            for (int j = 0; j < 4; j++) acc[i][j] = 0.f;

#pragma unroll 8
        for (int d = 0; d < 64; d++) {
            float rq[4], rk[4];
            *(float4*)rq = *(float4*)&Qs[d][ty * 4];
            *(float4*)rk = *(float4*)&Ks[d][tx * 4];
#pragma unroll
            for (int i = 0; i < 4; i++)
#pragma unroll
                for (int j = 0; j < 4; j++)
                    acc[i][j] = fmaf(rq[i], rk[j], acc[i][j]);
        }

#pragma unroll
        for (int i = 0; i < 4; i++) {
            const int ql = ty * 4 + i;
            float4 o;
            float s[4];
#pragma unroll
            for (int j = 0; j < 4; j++) {
                const int key = k0 + tx * 4 + j;
                float v = acc[i][j] * 0.125f;          // 1/sqrt(64)
                if (mask[b * Tc + key] == 0) v = NEG_INF;
                s[j] = v;
            }
            o.x = s[0]; o.y = s[1]; o.z = s[2]; o.w = s[3];
            *(float4*)(out + (size_t)ql * Tc + k0 + tx * 4) = o;
        }
    }
}

// ---------------------------------------------------------------------------
// Softmax in place over last dim (row length 1024). One block per row.
// ---------------------------------------------------------------------------
__global__ __launch_bounds__(256) void softmax_kernel(float* __restrict__ w)
{
    __shared__ float red[256];
    float* p = w + (size_t)blockIdx.x * 1024;
    const int tid = threadIdx.x;

    float4 v = ((const float4*)p)[tid];
    float m = fmaxf(fmaxf(v.x, v.y), fmaxf(v.z, v.w));
    red[tid] = m;
    __syncthreads();
    for (int s = 128; s > 0; s >>= 1) {
        if (tid < s) red[tid] = fmaxf(red[tid], red[tid + s]);
        __syncthreads();
    }
    m = red[0];
    __syncthreads();

    float4 e;
    e.x = __expf(v.x - m);
    e.y = __expf(v.y - m);
    e.z = __expf(v.z - m);
    e.w = __expf(v.w - m);
    red[tid] = e.x + e.y + e.z + e.w;
    __syncthreads();
    for (int s = 128; s > 0; s >>= 1) {
        if (tid < s) red[tid] += red[tid + s];
        __syncthreads();
    }
    const float inv = 1.0f / red[0];

    e.x *= inv; e.y *= inv; e.z *= inv; e.w *= inv;
    ((float4*)p)[tid] = e;
}

// ---------------------------------------------------------------------------
// ctx[bh][q][dk] = sum_k weights[bh][q][k] * V[bh][k][dk]
// Block = (bh, q-tile of 128). BK=32. 256 threads, 8x4 micro-tile.
// ---------------------------------------------------------------------------
__global__ __launch_bounds__(256) void ctx_kernel(
    const float* __restrict__ weights, const float* __restrict__ qkv,
    float* __restrict__ ctx)
{
    __shared__ float WsT[32][132];   // [k][q]
    __shared__ float Vs[32][68];     // [k][dk]

    const int bh = blockIdx.x;
    const int b  = bh >> 4;
    const int h  = bh & 15;
    const int q0 = blockIdx.y * 128;

    const int tid = threadIdx.x;
    const int tx  = tid & 15;        // col group (dk)
    const int ty  = tid >> 4;        // row group (q)

    const float* wrow = weights + ((size_t)bh * Tc + q0) * Tc;

    float acc[8][4];
#pragma unroll
    for (int i = 0; i < 8; i++)
#pragma unroll
        for (int j = 0; j < 4; j++) acc[i][j] = 0.f;

    for (int k0 = 0; k0 < Tc; k0 += 32) {
        __syncthreads();
        // W tile: 128 q x 32 k, stored transposed
        {
            const int r = tid >> 3;          // 0..31 (rows per pass)
            const int c = (tid & 7) * 4;     // 0..28
#pragma unroll
            for (int p = 0; p < 4; p++) {
                const int q = r + p * 32;
                float4 v = *(const float4*)(wrow + (size_t)q * Tc + k0 + c);
                WsT[c + 0][q] = v.x; WsT[c + 1][q] = v.y;
                WsT[c + 2][q] = v.z; WsT[c + 3][q] = v.w;
            }
        }
        // V tile: 32 k x 64 dk
        {
            const int r = tid >> 4;          // 0..15
            const int c = (tid & 15) * 4;
#pragma unroll
            for (int p = 0; p < 2; p++) {
                const int kk = r + p * 16;
                float4 v = *(const float4*)(qkv + ((size_t)(b * Tc + k0 + kk)) * D3c + 2 * Dc + h * DKc + c);
                *(float4*)&Vs[kk][c] = v;
            }
        }
        __syncthreads();

#pragma unroll 4
        for (int kk = 0; kk < 32; kk++) {
            float rw[8], rv[4];
            *(float4*)&rw[0] = *(float4*)&WsT[kk][ty * 8];
            *(float4*)&rw[4] = *(float4*)&WsT[kk][ty * 8 + 4];
            *(float4*)rv = *(float4*)&Vs[kk][tx * 4];
#pragma unroll
            for (int i = 0; i < 8; i++)
#pragma unroll
                for (int j = 0; j < 4; j++)
                    acc[i][j] = fmaf(rw[i], rv[j], acc[i][j]);
        }
    }

#pragma unroll
    for (int i = 0; i < 8; i++) {
        const int q = q0 + ty * 8 + i;
        float4 o;
        o.x = acc[i][0]; o.y = acc[i][1]; o.z = acc[i][2]; o.w = acc[i][3];
        *(float4*)(ctx + ((size_t)(b * Tc + q)) * Dc + h * DKc + tx * 4) = o;
    }
}

// ---------------------------------------------------------------------------
extern "C" void kernel_launch(void* const* d_in, const int* in_sizes, int n_in,
                              void* d_out, int out_size)
{
    const float* x    = (const float*)d_in[0];
    const int*   mask = (const int*)d_in[1];      // jax bool -> int32
    const float* Wqkv = (const float*)d_in[2];
    const float* bqkv = (const float*)d_in[3];
    const float* Wo   = (const float*)d_in[4];
    const float* bo   = (const float*)d_in[5];

    float* out     = (float*)d_out;
    float* weights = out + (size_t)Bc * Tc * Dc;   // second tuple element

    float* qkv;  cudaGetSymbolAddress((void**)&qkv, g_qkv);
    float* ctx;  cudaGetSymbolAddress((void**)&ctx, g_ctx);

    // 1) QKV projection: [8192,1024] @ [1024,3072] + bias
    sgemm_bias_kernel<<<dim3(D3c / 128, (Bc * Tc) / 128), 256>>>(
        x, Wqkv, bqkv, qkv, Bc * Tc, D3c, Dc);

    // 2) masked scaled logits -> weights region (raw)
    scores_kernel<<<dim3(Bc * NHc, Tc / 64), 256>>>(qkv, mask, weights);

    // 3) softmax in place
    softmax_kernel<<<Bc * NHc * Tc, 256>>>(weights);

    // 4) ctx = weights @ V
    ctx_kernel<<<dim3(Bc * NHc, Tc / 128), 256>>>(weights, qkv, ctx);

    // 5) output projection: [8192,1024] @ [1024,1024] + bias
    sgemm_bias_kernel<<<dim3(Dc / 128, (Bc * Tc) / 128), 256>>>(
        ctx, Wo, bo, out, Bc * Tc, Dc, Dc);
}

// round 5
// speedup vs baseline: 1.5657x; 1.5657x over previous
#include <cuda_runtime.h>
#include <cuda_bf16.h>
#include <cstdint>

// Problem constants
#define Bc   8
#define Tc   1024
#define Dc   1024
#define NHc  16
#define DKc  64
#define D3c  3072

// ---------------------------------------------------------------------------
// Scratch (device globals — allocation-free rule)
// ---------------------------------------------------------------------------
__device__ float g_qkv[(size_t)Bc * Tc * D3c];          // 96 MB fp32 qkv
__device__ float g_ctx[(size_t)Bc * Tc * Dc];           // 32 MB fp32 ctx
__device__ __nv_bfloat16 g_xhi[(size_t)Bc * Tc * Dc];   // x split
__device__ __nv_bfloat16 g_xlo[(size_t)Bc * Tc * Dc];
__device__ __nv_bfloat16 g_ctxhi[(size_t)Bc * Tc * Dc]; // ctx split
__device__ __nv_bfloat16 g_ctxlo[(size_t)Bc * Tc * Dc];
__device__ __nv_bfloat16 g_wqkvthi[(size_t)D3c * Dc];   // Wqkv^T [N=3072][K=1024]
__device__ __nv_bfloat16 g_wqkvtlo[(size_t)D3c * Dc];
__device__ __nv_bfloat16 g_wothi[(size_t)Dc * Dc];      // Wo^T [N=1024][K=1024]
__device__ __nv_bfloat16 g_wotlo[(size_t)Dc * Dc];

// ---------------------------------------------------------------------------
// sm_80-era primitives (legal on plain sm_103 target — NO tcgen05 anywhere)
// ---------------------------------------------------------------------------
__device__ __forceinline__ uint32_t smem_u32(const void* p) {
    uint32_t a;
    asm("{ .reg .u64 t; cvta.to.shared.u64 t, %1; cvt.u32.u64 %0, t; }"
        : "=r"(a) : "l"(p));
    return a;
}

__device__ __forceinline__ void cpasync16(uint32_t dst_smem, const void* src) {
    asm volatile("cp.async.cg.shared.global [%0], [%1], 16;"
                 :: "r"(dst_smem), "l"(src));
}

__device__ __forceinline__ void ldm_x4(uint32_t* r, uint32_t addr) {
    asm volatile("ldmatrix.sync.aligned.m8n8.x4.shared.b16 {%0,%1,%2,%3}, [%4];"
                 : "=r"(r[0]), "=r"(r[1]), "=r"(r[2]), "=r"(r[3]) : "r"(addr));
}

__device__ __forceinline__ void mma_bf16(float* d, const uint32_t* a, const uint32_t* b) {
    asm volatile(
        "mma.sync.aligned.m16n8k16.row.col.f32.bf16.bf16.f32 "
        "{%0,%1,%2,%3}, {%4,%5,%6,%7}, {%8,%9}, {%0,%1,%2,%3};"
        : "+f"(d[0]), "+f"(d[1]), "+f"(d[2]), "+f"(d[3])
        : "r"(a[0]), "r"(a[1]), "r"(a[2]), "r"(a[3]), "r"(b[0]), "r"(b[1]));
}

// ---------------------------------------------------------------------------
// Conversion kernels: fp32 -> bf16 hi/lo split
// ---------------------------------------------------------------------------
__global__ __launch_bounds__(256) void split_kernel(
    const float* __restrict__ in, __nv_bfloat16* __restrict__ hi,
    __nv_bfloat16* __restrict__ lo, int n4)
{
    int i = blockIdx.x * 256 + threadIdx.x;
    if (i >= n4) return;
    float4 v = ((const float4*)in)[i];
    __nv_bfloat16 h0 = __float2bfloat16(v.x);
    __nv_bfloat16 h1 = __float2bfloat16(v.y);
    __nv_bfloat16 h2 = __float2bfloat16(v.z);
    __nv_bfloat16 h3 = __float2bfloat16(v.w);
    __nv_bfloat16 l0 = __float2bfloat16(v.x - __bfloat162float(h0));
    __nv_bfloat16 l1 = __float2bfloat16(v.y - __bfloat162float(h1));
    __nv_bfloat16 l2 = __float2bfloat16(v.z - __bfloat162float(h2));
    __nv_bfloat16 l3 = __float2bfloat16(v.w - __bfloat162float(h3));
    ushort4 hp, lp;
    hp.x = *(unsigned short*)&h0; hp.y = *(unsigned short*)&h1;
    hp.z = *(unsigned short*)&h2; hp.w = *(unsigned short*)&h3;
    lp.x = *(unsigned short*)&l0; lp.y = *(unsigned short*)&l1;
    lp.z = *(unsigned short*)&l2; lp.w = *(unsigned short*)&l3;
    ((ushort4*)hi)[i] = hp;
    ((ushort4*)lo)[i] = lp;
}

// W [K,N] fp32 row-major  ->  T [N,K] bf16 hi/lo (transpose + split)
__global__ __launch_bounds__(256) void transpose_split_kernel(
    const float* __restrict__ W, __nv_bfloat16* __restrict__ Thi,
    __nv_bfloat16* __restrict__ Tlo, int K, int N)
{
    __shared__ float t[32][33];
    const int n0 = blockIdx.x * 32;
    const int k0 = blockIdx.y * 32;
    const int tx = threadIdx.x & 31;
    const int ty = threadIdx.x >> 5;       // 0..7
    for (int j = ty; j < 32; j += 8)
        t[j][tx] = W[(size_t)(k0 + j) * N + n0 + tx];
    __syncthreads();
    for (int j = ty; j < 32; j += 8) {
        float v = t[tx][j];                // = W[k0+tx][n0+j]
        __nv_bfloat16 h = __float2bfloat16(v);
        __nv_bfloat16 l = __float2bfloat16(v - __bfloat162float(h));
        Thi[(size_t)(n0 + j) * K + k0 + tx] = h;
        Tlo[(size_t)(n0 + j) * K + k0 + tx] = l;
    }
}

// ---------------------------------------------------------------------------
// mma.sync split-bf16 GEMM:  C[M,N] = A[M,K] @ Bt[N,K]^T + bias
// 3-term emulation: AhiBhi + AhiBlo + AloBhi  (residual ~2^-16).
// Block 128x128, 8 warps (warp tile 64x32), K-chunk 32, cp.async double buffer.
// ---------------------------------------------------------------------------
#define TBM 128
#define TBN 128
#define TBK 32
#define ROW_B    80u            // smem row stride bytes (32 bf16 + 8 pad)
#define T_BYTES  10240u         // one 128-row tensor tile: 128*80
#define BUF_BYTES (4u * T_BYTES) // Ahi,Alo,Bhi,Blo = 40960
#define GSMEM    (2 * BUF_BYTES) // 81920

__device__ __forceinline__ void stage_chunk(
    uint32_t sbase, const __nv_bfloat16* Ahi, const __nv_bfloat16* Alo,
    const __nv_bfloat16* Bhi, const __nv_bfloat16* Blo,
    int rowBase, int colBase, int K, int k0, int tid)
{
    const int quad = tid & 3;          // 16B segment within 64B row
    const int r0   = tid >> 2;         // 0..63
#pragma unroll
    for (int p = 0; p < 2; p++) {
        const int row = r0 + p * 64;
        const uint32_t d = (uint32_t)row * ROW_B + quad * 16;
        const size_t ga = (size_t)(rowBase + row) * K + k0 + quad * 8;
        const size_t gb = (size_t)(colBase + row) * K + k0 + quad * 8;
        cpasync16(sbase + d,               Ahi + ga);
        cpasync16(sbase + T_BYTES + d,     Alo + ga);
        cpasync16(sbase + 2 * T_BYTES + d, Bhi + gb);
        cpasync16(sbase + 3 * T_BYTES + d, Blo + gb);
    }
    asm volatile("cp.async.commit_group;" ::: "memory");
}

__global__ __launch_bounds__(256) void gemm_mma_split_kernel(
    const __nv_bfloat16* __restrict__ Ahi, const __nv_bfloat16* __restrict__ Alo,
    const __nv_bfloat16* __restrict__ Bhi, const __nv_bfloat16* __restrict__ Blo,
    const float* __restrict__ bias, float* __restrict__ C, int N, int K)
{
    extern __shared__ __align__(128) char smem[];
    const uint32_t sbase = smem_u32(smem);

    const int tid    = threadIdx.x;
    const int lane   = tid & 31;
    const int wid    = tid >> 5;
    const int warp_m = wid >> 2;       // 0..1  (64 rows each)
    const int warp_n = wid & 3;        // 0..3  (32 cols each)

    const int rowBase = blockIdx.y * TBM;
    const int colBase = blockIdx.x * TBN;

    float acc[4][4][4];
#pragma unroll
    for (int i = 0; i < 4; i++)
#pragma unroll
        for (int j = 0; j < 4; j++)
#pragma unroll
            for (int k = 0; k < 4; k++) acc[i][j][k] = 0.f;

    const int nchunks = K / TBK;
    stage_chunk(sbase, Ahi, Alo, Bhi, Blo, rowBase, colBase, K, 0, tid);

    for (int ch = 0; ch < nchunks; ch++) {
        asm volatile("cp.async.wait_group 0;" ::: "memory");
        __syncthreads();
        if (ch + 1 < nchunks)
            stage_chunk(sbase + ((ch + 1) & 1) * BUF_BYTES, Ahi, Alo, Bhi, Blo,
                        rowBase, colBase, K, (ch + 1) * TBK, tid);

        const uint32_t cb = sbase + (ch & 1) * BUF_BYTES;
#pragma unroll
        for (int ks = 0; ks < 2; ks++) {
            uint32_t ahi[4][4], alo[4][4], bhi[4][2], blo[4][2];
#pragma unroll
            for (int mt = 0; mt < 4; mt++) {
                const uint32_t addr = cb
                    + (uint32_t)(warp_m * 64 + mt * 16 + (lane & 15)) * ROW_B
                    + ks * 32 + (lane >> 4) * 16;
                ldm_x4(ahi[mt], addr);
                ldm_x4(alo[mt], addr + T_BYTES);
            }
#pragma unroll
            for (int pr = 0; pr < 2; pr++) {
                uint32_t tmp[4];
                const uint32_t addr = cb + 2 * T_BYTES
                    + (uint32_t)(warp_n * 32 + pr * 16 + (lane >> 4) * 8 + (lane & 7)) * ROW_B
                    + ks * 32 + ((lane >> 3) & 1) * 16;
                ldm_x4(tmp, addr);
                bhi[pr * 2 + 0][0] = tmp[0]; bhi[pr * 2 + 0][1] = tmp[1];
                bhi[pr * 2 + 1][0] = tmp[2]; bhi[pr * 2 + 1][1] = tmp[3];
                ldm_x4(tmp, addr + T_BYTES);
                blo[pr * 2 + 0][0] = tmp[0]; blo[pr * 2 + 0][1] = tmp[1];
                blo[pr * 2 + 1][0] = tmp[2]; blo[pr * 2 + 1][1] = tmp[3];
            }
#pragma unroll
            for (int mt = 0; mt < 4; mt++)
#pragma unroll
                for (int nt = 0; nt < 4; nt++) {
                    mma_bf16(acc[mt][nt], ahi[mt], bhi[nt]);
                    mma_bf16(acc[mt][nt], ahi[mt], blo[nt]);
                    mma_bf16(acc[mt][nt], alo[mt], bhi[nt]);
                }
        }
    }

    // Epilogue: fragment -> global + bias
    const int tr = lane >> 2;
    const int tc = (lane & 3) * 2;
#pragma unroll
    for (int mt = 0; mt < 4; mt++) {
        const int r0 = rowBase + warp_m * 64 + mt * 16 + tr;
#pragma unroll
        for (int nt = 0; nt < 4; nt++) {
            const int c = colBase + warp_n * 32 + nt * 8 + tc;
            const float b0 = bias[c], b1 = bias[c + 1];
            float2 v0, v1;
            v0.x = acc[mt][nt][0] + b0; v0.y = acc[mt][nt][1] + b1;
            v1.x = acc[mt][nt][2] + b0; v1.y = acc[mt][nt][3] + b1;
            *(float2*)(C + (size_t)r0 * N + c) = v0;
            *(float2*)(C + (size_t)(r0 + 8) * N + c) = v1;
        }
    }
}

// ---------------------------------------------------------------------------
// Scores: logits[bh][q][k] = (Q.K)/8, masked -> -inf  (fp32)
// ---------------------------------------------------------------------------
__global__ __launch_bounds__(256) void scores_kernel(
    const float* __restrict__ qkv, const int* __restrict__ mask,
    float* __restrict__ logits)
{
    __shared__ float Qs[64][68];
    __shared__ float Ks[64][68];

    const int bh = blockIdx.x;
    const int b  = bh >> 4;
    const int h  = bh & 15;
    const int q0 = blockIdx.y * 64;

    const int tid = threadIdx.x;
    const int tx  = tid & 15;
    const int ty  = tid >> 4;

    {
        const int r = tid >> 4;
        const int c = (tid & 15) * 4;
#pragma unroll
        for (int p = 0; p < 4; p++) {
            const int q = r + p * 16;
            float4 v = *(const float4*)(qkv + ((size_t)(b * Tc + q0 + q)) * D3c + h * DKc + c);
            Qs[c + 0][q] = v.x; Qs[c + 1][q] = v.y;
            Qs[c + 2][q] = v.z; Qs[c + 3][q] = v.w;
        }
    }

    float* out = logits + ((size_t)bh * Tc + q0) * Tc;
    const float NEG_INF = __int_as_float(0xff800000);

    for (int k0 = 0; k0 < Tc; k0 += 64) {
        __syncthreads();
        {
            const int r = tid >> 4;
            const int c = (tid & 15) * 4;
#pragma unroll
            for (int p = 0; p < 4; p++) {
                const int kk = r + p * 16;
                float4 v = *(const float4*)(qkv + ((size_t)(b * Tc + k0 + kk)) * D3c + Dc + h * DKc + c);
                Ks[c + 0][kk] = v.x; Ks[c + 1][kk] = v.y;
                Ks[c + 2][kk] = v.z; Ks[c + 3][kk] = v.w;
            }
        }
        __syncthreads();

        float acc[4][4];
#pragma unroll
        for (int i = 0; i < 4; i++)
#pragma unroll
            for (int j = 0; j < 4; j++) acc[i][j] = 0.f;

#pragma unroll 8
        for (int d = 0; d < 64; d++) {
            float rq[4], rk[4];
            *(float4*)rq = *(float4*)&Qs[d][ty * 4];
            *(float4*)rk = *(float4*)&Ks[d][tx * 4];
#pragma unroll
            for (int i = 0; i < 4; i++)
#pragma unroll
                for (int j = 0; j < 4; j++)
                    acc[i][j] = fmaf(rq[i], rk[j], acc[i][j]);
        }

#pragma unroll
        for (int i = 0; i < 4; i++) {
            const int ql = ty * 4 + i;
            float s[4];
#pragma unroll
            for (int j = 0; j < 4; j++) {
                const int key = k0 + tx * 4 + j;
                float v = acc[i][j] * 0.125f;
                if (mask[b * Tc + key] == 0) v = NEG_INF;
                s[j] = v;
            }
            float4 o; o.x = s[0]; o.y = s[1]; o.z = s[2]; o.w = s[3];
            *(float4*)(out + (size_t)ql * Tc + k0 + tx * 4) = o;
        }
    }
}

// ---------------------------------------------------------------------------
// Softmax in place (row length 1024), one block per row
// ---------------------------------------------------------------------------
__global__ __launch_bounds__(256) void softmax_kernel(float* __restrict__ w)
{
    __shared__ float red[256];
    float* p = w + (size_t)blockIdx.x * 1024;
    const int tid = threadIdx.x;

    float4 v = ((const float4*)p)[tid];
    float m = fmaxf(fmaxf(v.x, v.y), fmaxf(v.z, v.w));
    red[tid] = m;
    __syncthreads();
    for (int s = 128; s > 0; s >>= 1) {
        if (tid < s) red[tid] = fmaxf(red[tid], red[tid + s]);
        __syncthreads();
    }
    m = red[0];
    __syncthreads();

    float4 e;
    e.x = __expf(v.x - m);
    e.y = __expf(v.y - m);
    e.z = __expf(v.z - m);
    e.w = __expf(v.w - m);
    red[tid] = e.x + e.y + e.z + e.w;
    __syncthreads();
    for (int s = 128; s > 0; s >>= 1) {
        if (tid < s) red[tid] += red[tid + s];
        __syncthreads();
    }
    const float inv = 1.0f / red[0];

    e.x *= inv; e.y *= inv; e.z *= inv; e.w *= inv;
    ((float4*)p)[tid] = e;
}

// ---------------------------------------------------------------------------
// ctx = weights @ V  (fp32)
// ---------------------------------------------------------------------------
__global__ __launch_bounds__(256) void ctx_kernel(
    const float* __restrict__ weights, const float* __restrict__ qkv,
    float* __restrict__ ctx)
{
    __shared__ float WsT[32][132];
    __shared__ float Vs[32][68];

    const int bh = blockIdx.x;
    const int b  = bh >> 4;
    const int h  = bh & 15;
    const int q0 = blockIdx.y * 128;

    const int tid = threadIdx.x;
    const int tx  = tid & 15;
    const int ty  = tid >> 4;

    const float* wrow = weights + ((size_t)bh * Tc + q0) * Tc;

    float acc[8][4];
#pragma unroll
    for (int i = 0; i < 8; i++)
#pragma unroll
        for (int j = 0; j < 4; j++) acc[i][j] = 0.f;

    for (int k0 = 0; k0 < Tc; k0 += 32) {
        __syncthreads();
        {
            const int r = tid >> 3;
            const int c = (tid & 7) * 4;
#pragma unroll
            for (int p = 0; p < 4; p++) {
                const int q = r + p * 32;
                float4 v = *(const float4*)(wrow + (size_t)q * Tc + k0 + c);
                WsT[c + 0][q] = v.x; WsT[c + 1][q] = v.y;
                WsT[c + 2][q] = v.z; WsT[c + 3][q] = v.w;
            }
        }
        {
            const int r = tid >> 4;
            const int c = (tid & 15) * 4;
#pragma unroll
            for (int p = 0; p < 2; p++) {
                const int kk = r + p * 16;
                float4 v = *(const float4*)(qkv + ((size_t)(b * Tc + k0 + kk)) * D3c + 2 * Dc + h * DKc + c);
                *(float4*)&Vs[kk][c] = v;
            }
        }
        __syncthreads();

#pragma unroll 4
        for (int kk = 0; kk < 32; kk++) {
            float rw[8], rv[4];
            *(float4*)&rw[0] = *(float4*)&WsT[kk][ty * 8];
            *(float4*)&rw[4] = *(float4*)&WsT[kk][ty * 8 + 4];
            *(float4*)rv = *(float4*)&Vs[kk][tx * 4];
#pragma unroll
            for (int i = 0; i < 8; i++)
#pragma unroll
                for (int j = 0; j < 4; j++)
                    acc[i][j] = fmaf(rw[i], rv[j], acc[i][j]);
        }
    }

#pragma unroll
    for (int i = 0; i < 8; i++) {
        const int q = q0 + ty * 8 + i;
        float4 o;
        o.x = acc[i][0]; o.y = acc[i][1]; o.z = acc[i][2]; o.w = acc[i][3];
        *(float4*)(ctx + ((size_t)(b * Tc + q)) * Dc + h * DKc + tx * 4) = o;
    }
}

// ---------------------------------------------------------------------------
extern "C" void kernel_launch(void* const* d_in, const int* in_sizes, int n_in,
                              void* d_out, int out_size)
{
    const float* x    = (const float*)d_in[0];
    const int*   mask = (const int*)d_in[1];      // jax bool -> int32
    const float* Wqkv = (const float*)d_in[2];
    const float* bqkv = (const float*)d_in[3];
    const float* Wo   = (const float*)d_in[4];
    const float* bo   = (const float*)d_in[5];

    float* out     = (float*)d_out;
    float* weights = out + (size_t)Bc * Tc * Dc;

    float* qkv;  cudaGetSymbolAddress((void**)&qkv, g_qkv);
    float* ctx;  cudaGetSymbolAddress((void**)&ctx, g_ctx);
    __nv_bfloat16 *xhi, *xlo, *ctxhi, *ctxlo, *wqhi, *wqlo, *wohi, *wolo;
    cudaGetSymbolAddress((void**)&xhi, g_xhi);
    cudaGetSymbolAddress((void**)&xlo, g_xlo);
    cudaGetSymbolAddress((void**)&ctxhi, g_ctxhi);
    cudaGetSymbolAddress((void**)&ctxlo, g_ctxlo);
    cudaGetSymbolAddress((void**)&wqhi, g_wqkvthi);
    cudaGetSymbolAddress((void**)&wqlo, g_wqkvtlo);
    cudaGetSymbolAddress((void**)&wohi, g_wothi);
    cudaGetSymbolAddress((void**)&wolo, g_wotlo);

    static int smem_set = 0;
    if (!smem_set) {
        cudaFuncSetAttribute(gemm_mma_split_kernel,
                             cudaFuncAttributeMaxDynamicSharedMemorySize, GSMEM);
        smem_set = 1;
    }

    const int nx4 = (Bc * Tc * Dc) / 4;   // 2M float4s

    // 0) splits / transposes
    split_kernel<<<(nx4 + 255) / 256, 256>>>(x, xhi, xlo, nx4);
    transpose_split_kernel<<<dim3(D3c / 32, Dc / 32), 256>>>(Wqkv, wqhi, wqlo, Dc, D3c);
    transpose_split_kernel<<<dim3(Dc / 32, Dc / 32), 256>>>(Wo, wohi, wolo, Dc, Dc);

    // 1) QKV projection on tensor cores (mma.sync): [8192,1024]@[1024,3072]+bias
    gemm_mma_split_kernel<<<dim3(D3c / TBN, (Bc * Tc) / TBM), 256, GSMEM>>>(
        xhi, xlo, wqhi, wqlo, bqkv, qkv, D3c, Dc);

    // 2) masked scaled logits -> weights region
    scores_kernel<<<dim3(Bc * NHc, Tc / 64), 256>>>(qkv, mask, weights);

    // 3) softmax in place
    softmax_kernel<<<Bc * NHc * Tc, 256>>>(weights);

    // 4) ctx = weights @ V
    ctx_kernel<<<dim3(Bc * NHc, Tc / 128), 256>>>(weights, qkv, ctx);

    // 5) output projection on tensor cores
    split_kernel<<<(nx4 + 255) / 256, 256>>>(ctx, ctxhi, ctxlo, nx4);
    gemm_mma_split_kernel<<<dim3(Dc / TBN, (Bc * Tc) / TBM), 256, GSMEM>>>(
        ctxhi, ctxlo, wohi, wolo, bo, out, Dc, Dc);
}

// round 7
// speedup vs baseline: 2.1886x; 1.3978x over previous
#include <cuda_runtime.h>
#include <cuda_bf16.h>
#include <cstdint>

// Problem constants
#define Bc   8
#define Tc   1024
#define Dc   1024
#define NHc  16
#define DKc  64
#define D3c  3072

// ---------------------------------------------------------------------------
// Scratch (device globals — allocation-free rule)
// ---------------------------------------------------------------------------
__device__ __nv_bfloat16 g_xhi[(size_t)Bc * Tc * Dc];
__device__ __nv_bfloat16 g_xlo[(size_t)Bc * Tc * Dc];
__device__ __nv_bfloat16 g_wqkvthi[(size_t)D3c * Dc];   // Wqkv^T [N=3072][K=1024]
__device__ __nv_bfloat16 g_wqkvtlo[(size_t)D3c * Dc];
__device__ __nv_bfloat16 g_wothi[(size_t)Dc * Dc];      // Wo^T [N=1024][K=1024]
__device__ __nv_bfloat16 g_wotlo[(size_t)Dc * Dc];
// head-major splits produced by QKV epilogue: [bh][t][64]
__device__ __nv_bfloat16 g_qhi[(size_t)128 * Tc * DKc];
__device__ __nv_bfloat16 g_qlo[(size_t)128 * Tc * DKc];
__device__ __nv_bfloat16 g_khi[(size_t)128 * Tc * DKc];
__device__ __nv_bfloat16 g_klo[(size_t)128 * Tc * DKc];
__device__ __nv_bfloat16 g_vhi[(size_t)128 * Tc * DKc];
__device__ __nv_bfloat16 g_vlo[(size_t)128 * Tc * DKc];
// softmaxed weights splits: [bh][q][k]
__device__ __nv_bfloat16 g_whi[(size_t)128 * Tc * Tc];
__device__ __nv_bfloat16 g_wlo[(size_t)128 * Tc * Tc];
// ctx splits: [b*T+t][D]
__device__ __nv_bfloat16 g_ctxhi[(size_t)Bc * Tc * Dc];
__device__ __nv_bfloat16 g_ctxlo[(size_t)Bc * Tc * Dc];

// ---------------------------------------------------------------------------
// sm_80-era primitives (legal on plain sm_103 target)
// ---------------------------------------------------------------------------
__device__ __forceinline__ uint32_t smem_u32(const void* p) {
    uint32_t a;
    asm("{ .reg .u64 t; cvta.to.shared.u64 t, %1; cvt.u32.u64 %0, t; }"
        : "=r"(a) : "l"(p));
    return a;
}
__device__ __forceinline__ void cpasync16(uint32_t dst_smem, const void* src) {
    asm volatile("cp.async.cg.shared.global [%0], [%1], 16;"
                 :: "r"(dst_smem), "l"(src));
}
__device__ __forceinline__ void ldm_x4(uint32_t* r, uint32_t addr) {
    asm volatile("ldmatrix.sync.aligned.m8n8.x4.shared.b16 {%0,%1,%2,%3}, [%4];"
                 : "=r"(r[0]), "=r"(r[1]), "=r"(r[2]), "=r"(r[3]) : "r"(addr));
}
__device__ __forceinline__ void ldm_x4_trans(uint32_t* r, uint32_t addr) {
    asm volatile("ldmatrix.sync.aligned.m8n8.x4.trans.shared.b16 {%0,%1,%2,%3}, [%4];"
                 : "=r"(r[0]), "=r"(r[1]), "=r"(r[2]), "=r"(r[3]) : "r"(addr));
}
__device__ __forceinline__ void mma_bf16(float* d, const uint32_t* a, const uint32_t* b) {
    asm volatile(
        "mma.sync.aligned.m16n8k16.row.col.f32.bf16.bf16.f32 "
        "{%0,%1,%2,%3}, {%4,%5,%6,%7}, {%8,%9}, {%0,%1,%2,%3};"
        : "+f"(d[0]), "+f"(d[1]), "+f"(d[2]), "+f"(d[3])
        : "r"(a[0]), "r"(a[1]), "r"(a[2]), "r"(a[3]), "r"(b[0]), "r"(b[1]));
}

__device__ __forceinline__ void split_store2(
    __nv_bfloat16* hi, __nv_bfloat16* lo, size_t idx, float f0, float f1)
{
    __nv_bfloat16 h0 = __float2bfloat16(f0);
    __nv_bfloat16 h1 = __float2bfloat16(f1);
    __nv_bfloat16 l0 = __float2bfloat16(f0 - __bfloat162float(h0));
    __nv_bfloat16 l1 = __float2bfloat16(f1 - __bfloat162float(h1));
    ushort2 hp, lp;
    hp.x = *(unsigned short*)&h0; hp.y = *(unsigned short*)&h1;
    lp.x = *(unsigned short*)&l0; lp.y = *(unsigned short*)&l1;
    *(ushort2*)(hi + idx) = hp;
    *(ushort2*)(lo + idx) = lp;
}

// ---------------------------------------------------------------------------
// Conversion kernels
// ---------------------------------------------------------------------------
__global__ __launch_bounds__(256) void split_kernel(
    const float* __restrict__ in, __nv_bfloat16* __restrict__ hi,
    __nv_bfloat16* __restrict__ lo, int n4)
{
    int i = blockIdx.x * 256 + threadIdx.x;
    if (i >= n4) return;
    float4 v = ((const float4*)in)[i];
    __nv_bfloat16 h0 = __float2bfloat16(v.x);
    __nv_bfloat16 h1 = __float2bfloat16(v.y);
    __nv_bfloat16 h2 = __float2bfloat16(v.z);
    __nv_bfloat16 h3 = __float2bfloat16(v.w);
    __nv_bfloat16 l0 = __float2bfloat16(v.x - __bfloat162float(h0));
    __nv_bfloat16 l1 = __float2bfloat16(v.y - __bfloat162float(h1));
    __nv_bfloat16 l2 = __float2bfloat16(v.z - __bfloat162float(h2));
    __nv_bfloat16 l3 = __float2bfloat16(v.w - __bfloat162float(h3));
    ushort4 hp, lp;
    hp.x = *(unsigned short*)&h0; hp.y = *(unsigned short*)&h1;
    hp.z = *(unsigned short*)&h2; hp.w = *(unsigned short*)&h3;
    lp.x = *(unsigned short*)&l0; lp.y = *(unsigned short*)&l1;
    lp.z = *(unsigned short*)&l2; lp.w = *(unsigned short*)&l3;
    ((ushort4*)hi)[i] = hp;
    ((ushort4*)lo)[i] = lp;
}

__global__ __launch_bounds__(256) void transpose_split_kernel(
    const float* __restrict__ W, __nv_bfloat16* __restrict__ Thi,
    __nv_bfloat16* __restrict__ Tlo, int K, int N)
{
    __shared__ float t[32][33];
    const int n0 = blockIdx.x * 32;
    const int k0 = blockIdx.y * 32;
    const int tx = threadIdx.x & 31;
    const int ty = threadIdx.x >> 5;
    for (int j = ty; j < 32; j += 8)
        t[j][tx] = W[(size_t)(k0 + j) * N + n0 + tx];
    __syncthreads();
    for (int j = ty; j < 32; j += 8) {
        float v = t[tx][j];
        __nv_bfloat16 h = __float2bfloat16(v);
        __nv_bfloat16 l = __float2bfloat16(v - __bfloat162float(h));
        Thi[(size_t)(n0 + j) * K + k0 + tx] = h;
        Tlo[(size_t)(n0 + j) * K + k0 + tx] = l;
    }
}

// ---------------------------------------------------------------------------
// Shared GEMM mainloop config (128x128 block, 8 warps 64x32, K-chunk 32)
// ---------------------------------------------------------------------------
#define TBM 128
#define TBN 128
#define TBK 32
#define ROW_B    80u
#define T_BYTES  10240u
#define BUF_BYTES (4u * T_BYTES)
#define GSMEM    (2 * BUF_BYTES)

__device__ __forceinline__ void stage_chunk(
    uint32_t sbase, const __nv_bfloat16* Ahi, const __nv_bfloat16* Alo,
    const __nv_bfloat16* Bhi, const __nv_bfloat16* Blo,
    int rowBase, int colBase, int K, int k0, int tid)
{
    const int quad = tid & 3;
    const int r0   = tid >> 2;
#pragma unroll
    for (int p = 0; p < 2; p++) {
        const int row = r0 + p * 64;
        const uint32_t d = (uint32_t)row * ROW_B + quad * 16;
        const size_t ga = (size_t)(rowBase + row) * K + k0 + quad * 8;
        const size_t gb = (size_t)(colBase + row) * K + k0 + quad * 8;
        cpasync16(sbase + d,               Ahi + ga);
        cpasync16(sbase + T_BYTES + d,     Alo + ga);
        cpasync16(sbase + 2 * T_BYTES + d, Bhi + gb);
        cpasync16(sbase + 3 * T_BYTES + d, Blo + gb);
    }
    asm volatile("cp.async.commit_group;" ::: "memory");
}

// Mainloop macro body used by both projection GEMMs
#define GEMM_MAINLOOP(ACC)                                                    \
    const int nchunks = K / TBK;                                              \
    stage_chunk(sbase, Ahi, Alo, Bhi, Blo, rowBase, colBase, K, 0, tid);      \
    for (int ch = 0; ch < nchunks; ch++) {                                    \
        asm volatile("cp.async.wait_group 0;" ::: "memory");                  \
        __syncthreads();                                                      \
        if (ch + 1 < nchunks)                                                 \
            stage_chunk(sbase + ((ch + 1) & 1) * BUF_BYTES, Ahi, Alo, Bhi,    \
                        Blo, rowBase, colBase, K, (ch + 1) * TBK, tid);       \
        const uint32_t cb = sbase + (ch & 1) * BUF_BYTES;                     \
        _Pragma("unroll")                                                     \
        for (int ks = 0; ks < 2; ks++) {                                      \
            uint32_t ahi[4][4], alo[4][4], bhi[4][2], blo[4][2];              \
            _Pragma("unroll")                                                 \
            for (int mt = 0; mt < 4; mt++) {                                  \
                const uint32_t addr = cb                                      \
                    + (uint32_t)(warp_m * 64 + mt * 16 + (lane & 15)) * ROW_B \
                    + ks * 32 + (lane >> 4) * 16;                             \
                ldm_x4(ahi[mt], addr);                                        \
                ldm_x4(alo[mt], addr + T_BYTES);                              \
            }                                                                 \
            _Pragma("unroll")                                                 \
            for (int pr = 0; pr < 2; pr++) {                                  \
                uint32_t tmp[4];                                              \
                const uint32_t addr = cb + 2 * T_BYTES                        \
                    + (uint32_t)(warp_n * 32 + pr * 16 + (lane >> 4) * 8      \
                                 + (lane & 7)) * ROW_B                        \
                    + ks * 32 + ((lane >> 3) & 1) * 16;                       \
                ldm_x4(tmp, addr);                                            \
                bhi[pr * 2 + 0][0] = tmp[0]; bhi[pr * 2 + 0][1] = tmp[1];     \
                bhi[pr * 2 + 1][0] = tmp[2]; bhi[pr * 2 + 1][1] = tmp[3];     \
                ldm_x4(tmp, addr + T_BYTES);                                  \
                blo[pr * 2 + 0][0] = tmp[0]; blo[pr * 2 + 0][1] = tmp[1];     \
                blo[pr * 2 + 1][0] = tmp[2]; blo[pr * 2 + 1][1] = tmp[3];     \
            }                                                                 \
            _Pragma("unroll")                                                 \
            for (int mt = 0; mt < 4; mt++)                                    \
                _Pragma("unroll")                                             \
                for (int nt = 0; nt < 4; nt++) {                              \
                    mma_bf16(ACC[mt][nt], ahi[mt], bhi[nt]);                  \
                    mma_bf16(ACC[mt][nt], ahi[mt], blo[nt]);                  \
                    mma_bf16(ACC[mt][nt], alo[mt], bhi[nt]);                  \
                }                                                             \
        }                                                                     \
    }

// ---------------------------------------------------------------------------
// QKV GEMM: [8192,1024] @ Wqkv^T[3072,1024]^T + bias -> bf16 hi/lo splits in
// head-major [bh][t][64] layout for q, k, v (no fp32 intermediate).
// ---------------------------------------------------------------------------
__global__ __launch_bounds__(256) void gemm_qkv_kernel(
    const __nv_bfloat16* __restrict__ Ahi, const __nv_bfloat16* __restrict__ Alo,
    const __nv_bfloat16* __restrict__ Bhi, const __nv_bfloat16* __restrict__ Blo,
    const float* __restrict__ bias,
    __nv_bfloat16* __restrict__ qhi, __nv_bfloat16* __restrict__ qlo,
    __nv_bfloat16* __restrict__ khi, __nv_bfloat16* __restrict__ klo,
    __nv_bfloat16* __restrict__ vhi, __nv_bfloat16* __restrict__ vlo,
    int K)
{
    extern __shared__ __align__(128) char smem[];
    const uint32_t sbase = smem_u32(smem);
    const int tid    = threadIdx.x;
    const int lane   = tid & 31;
    const int wid    = tid >> 5;
    const int warp_m = wid >> 2;
    const int warp_n = wid & 3;
    const int rowBase = blockIdx.y * TBM;
    const int colBase = blockIdx.x * TBN;

    float acc[4][4][4];
#pragma unroll
    for (int i = 0; i < 4; i++)
#pragma unroll
        for (int j = 0; j < 4; j++)
#pragma unroll
            for (int k = 0; k < 4; k++) acc[i][j][k] = 0.f;

    GEMM_MAINLOOP(acc)

    // epilogue: split + scatter to head-major layout
    const int region = colBase >> 10;          // 0=q,1=k,2=v (tile within one)
    __nv_bfloat16* dsthi = (region == 0) ? qhi : ((region == 1) ? khi : vhi);
    __nv_bfloat16* dstlo = (region == 0) ? qlo : ((region == 1) ? klo : vlo);
    const int b  = rowBase >> 10;              // 128-row tile within one batch
    const int tr = lane >> 2;
    const int tc = (lane & 3) * 2;
#pragma unroll
    for (int mt = 0; mt < 4; mt++) {
        const int t0 = (rowBase & 1023) + warp_m * 64 + mt * 16 + tr;
#pragma unroll
        for (int nt = 0; nt < 4; nt++) {
            const int c = colBase + warp_n * 32 + nt * 8 + tc;
            const int head = (c & 1023) >> 6;
            const int dk   = c & 63;
            const float b0 = bias[c], b1 = bias[c + 1];
            const size_t rowb = (size_t)(b * 16 + head) * Tc;
            split_store2(dsthi, dstlo, (rowb + t0) * 64 + dk,
                         acc[mt][nt][0] + b0, acc[mt][nt][1] + b1);
            split_store2(dsthi, dstlo, (rowb + t0 + 8) * 64 + dk,
                         acc[mt][nt][2] + b0, acc[mt][nt][3] + b1);
        }
    }
}

// ---------------------------------------------------------------------------
// Output projection GEMM (fp32 out + bias), mainloop shared
// ---------------------------------------------------------------------------
__global__ __launch_bounds__(256) void gemm_mma_split_kernel(
    const __nv_bfloat16* __restrict__ Ahi, const __nv_bfloat16* __restrict__ Alo,
    const __nv_bfloat16* __restrict__ Bhi, const __nv_bfloat16* __restrict__ Blo,
    const float* __restrict__ bias, float* __restrict__ C, int N, int K)
{
    extern __shared__ __align__(128) char smem[];
    const uint32_t sbase = smem_u32(smem);
    const int tid    = threadIdx.x;
    const int lane   = tid & 31;
    const int wid    = tid >> 5;
    const int warp_m = wid >> 2;
    const int warp_n = wid & 3;
    const int rowBase = blockIdx.y * TBM;
    const int colBase = blockIdx.x * TBN;

    float acc[4][4][4];
#pragma unroll
    for (int i = 0; i < 4; i++)
#pragma unroll
        for (int j = 0; j < 4; j++)
#pragma unroll
            for (int k = 0; k < 4; k++) acc[i][j][k] = 0.f;

    GEMM_MAINLOOP(acc)

    const int tr = lane >> 2;
    const int tc = (lane & 3) * 2;
#pragma unroll
    for (int mt = 0; mt < 4; mt++) {
        const int r0 = rowBase + warp_m * 64 + mt * 16 + tr;
#pragma unroll
        for (int nt = 0; nt < 4; nt++) {
            const int c = colBase + warp_n * 32 + nt * 8 + tc;
            const float b0 = bias[c], b1 = bias[c + 1];
            float2 v0, v1;
            v0.x = acc[mt][nt][0] + b0; v0.y = acc[mt][nt][1] + b1;
            v1.x = acc[mt][nt][2] + b0; v1.y = acc[mt][nt][3] + b1;
            *(float2*)(C + (size_t)r0 * N + c) = v0;
            *(float2*)(C + (size_t)(r0 + 8) * N + c) = v1;
        }
    }
}

// ---------------------------------------------------------------------------
// Scores via mma: S[bh][q][k] = (Q.K^T)/8 masked -> fp32 logits
// CTA = (ktile, qtile, bh); tiles 128x128, K-dim 64 (one pass), 3-term split.
// ---------------------------------------------------------------------------
#define SROW     144u
#define S_TILE   (128u * SROW)       // 18432
#define SM_SCORES (4u * S_TILE)      // 73728

__global__ __launch_bounds__(256) void scores_mma_kernel(
    const __nv_bfloat16* __restrict__ qhi, const __nv_bfloat16* __restrict__ qlo,
    const __nv_bfloat16* __restrict__ khi, const __nv_bfloat16* __restrict__ klo,
    const int* __restrict__ mask, float* __restrict__ logits)
{
    extern __shared__ __align__(128) char smem[];
    const uint32_t sbase = smem_u32(smem);
    const int tid    = threadIdx.x;
    const int lane   = tid & 31;
    const int wid    = tid >> 5;
    const int warp_m = wid >> 2;
    const int warp_n = wid & 3;

    const int k0 = blockIdx.x * 128;
    const int q0 = blockIdx.y * 128;
    const int bh = blockIdx.z;
    const int b  = bh >> 4;

    // stage Q and K tiles (128 rows x 64 dk each, hi+lo)
    for (int i = tid; i < 1024; i += 256) {
        const int row = i >> 3;
        const int seg = i & 7;
        const uint32_t d = (uint32_t)row * SROW + seg * 16;
        const size_t gq = ((size_t)bh * Tc + q0 + row) * 64 + seg * 8;
        const size_t gk = ((size_t)bh * Tc + k0 + row) * 64 + seg * 8;
        cpasync16(sbase + d,              qhi + gq);
        cpasync16(sbase + S_TILE + d,     qlo + gq);
        cpasync16(sbase + 2 * S_TILE + d, khi + gk);
        cpasync16(sbase + 3 * S_TILE + d, klo + gk);
    }
    asm volatile("cp.async.commit_group;" ::: "memory");
    asm volatile("cp.async.wait_group 0;" ::: "memory");
    __syncthreads();

    float acc[4][4][4];
#pragma unroll
    for (int i = 0; i < 4; i++)
#pragma unroll
        for (int j = 0; j < 4; j++)
#pragma unroll
            for (int k = 0; k < 4; k++) acc[i][j][k] = 0.f;

#pragma unroll
    for (int ks = 0; ks < 4; ks++) {
        uint32_t ahi[4][4], alo[4][4], bhi[4][2], blo[4][2];
#pragma unroll
        for (int mt = 0; mt < 4; mt++) {
            const uint32_t addr = sbase
                + (uint32_t)(warp_m * 64 + mt * 16 + (lane & 15)) * SROW
                + ks * 32 + (lane >> 4) * 16;
            ldm_x4(ahi[mt], addr);
            ldm_x4(alo[mt], addr + S_TILE);
        }
#pragma unroll
        for (int pr = 0; pr < 2; pr++) {
            uint32_t tmp[4];
            const uint32_t addr = sbase + 2 * S_TILE
                + (uint32_t)(warp_n * 32 + pr * 16 + (lane >> 4) * 8 + (lane & 7)) * SROW
                + ks * 32 + ((lane >> 3) & 1) * 16;
            ldm_x4(tmp, addr);
            bhi[pr * 2 + 0][0] = tmp[0]; bhi[pr * 2 + 0][1] = tmp[1];
            bhi[pr * 2 + 1][0] = tmp[2]; bhi[pr * 2 + 1][1] = tmp[3];
            ldm_x4(tmp, addr + S_TILE);
            blo[pr * 2 + 0][0] = tmp[0]; blo[pr * 2 + 0][1] = tmp[1];
            blo[pr * 2 + 1][0] = tmp[2]; blo[pr * 2 + 1][1] = tmp[3];
        }
#pragma unroll
        for (int mt = 0; mt < 4; mt++)
#pragma unroll
            for (int nt = 0; nt < 4; nt++) {
                mma_bf16(acc[mt][nt], ahi[mt], bhi[nt]);
                mma_bf16(acc[mt][nt], ahi[mt], blo[nt]);
                mma_bf16(acc[mt][nt], alo[mt], bhi[nt]);
            }
    }

    // epilogue: scale + mask + fp32 store
    const float NEG_INF = __int_as_float(0xff800000);
    const int tr = lane >> 2;
    const int tc = (lane & 3) * 2;
#pragma unroll
    for (int mt = 0; mt < 4; mt++) {
        const int q = q0 + warp_m * 64 + mt * 16 + tr;
#pragma unroll
        for (int nt = 0; nt < 4; nt++) {
            const int c = k0 + warp_n * 32 + nt * 8 + tc;
            const int m0 = mask[b * Tc + c];
            const int m1 = mask[b * Tc + c + 1];
            float2 v0, v1;
            v0.x = m0 ? acc[mt][nt][0] * 0.125f : NEG_INF;
            v0.y = m1 ? acc[mt][nt][1] * 0.125f : NEG_INF;
            v1.x = m0 ? acc[mt][nt][2] * 0.125f : NEG_INF;
            v1.y = m1 ? acc[mt][nt][3] * 0.125f : NEG_INF;
            float* outp = logits + ((size_t)bh * Tc + q) * Tc + c;
            *(float2*)outp = v0;
            *(float2*)(outp + 8 * Tc) = v1;
        }
    }
}

// ---------------------------------------------------------------------------
// Softmax in place + bf16 hi/lo split emit
// ---------------------------------------------------------------------------
__global__ __launch_bounds__(256) void softmax_kernel(
    float* __restrict__ w, __nv_bfloat16* __restrict__ whi,
    __nv_bfloat16* __restrict__ wlo)
{
    __shared__ float red[256];
    const size_t rowoff = (size_t)blockIdx.x * 1024;
    float* p = w + rowoff;
    const int tid = threadIdx.x;

    float4 v = ((const float4*)p)[tid];
    float m = fmaxf(fmaxf(v.x, v.y), fmaxf(v.z, v.w));
    red[tid] = m;
    __syncthreads();
    for (int s = 128; s > 0; s >>= 1) {
        if (tid < s) red[tid] = fmaxf(red[tid], red[tid + s]);
        __syncthreads();
    }
    m = red[0];
    __syncthreads();

    float4 e;
    e.x = __expf(v.x - m);
    e.y = __expf(v.y - m);
    e.z = __expf(v.z - m);
    e.w = __expf(v.w - m);
    red[tid] = e.x + e.y + e.z + e.w;
    __syncthreads();
    for (int s = 128; s > 0; s >>= 1) {
        if (tid < s) red[tid] += red[tid + s];
        __syncthreads();
    }
    const float inv = 1.0f / red[0];

    e.x *= inv; e.y *= inv; e.z *= inv; e.w *= inv;
    ((float4*)p)[tid] = e;

    // split emit
    __nv_bfloat16 h0 = __float2bfloat16(e.x);
    __nv_bfloat16 h1 = __float2bfloat16(e.y);
    __nv_bfloat16 h2 = __float2bfloat16(e.z);
    __nv_bfloat16 h3 = __float2bfloat16(e.w);
    __nv_bfloat16 l0 = __float2bfloat16(e.x - __bfloat162float(h0));
    __nv_bfloat16 l1 = __float2bfloat16(e.y - __bfloat162float(h1));
    __nv_bfloat16 l2 = __float2bfloat16(e.z - __bfloat162float(h2));
    __nv_bfloat16 l3 = __float2bfloat16(e.w - __bfloat162float(h3));
    ushort4 hp, lp;
    hp.x = *(unsigned short*)&h0; hp.y = *(unsigned short*)&h1;
    hp.z = *(unsigned short*)&h2; hp.w = *(unsigned short*)&h3;
    lp.x = *(unsigned short*)&l0; lp.y = *(unsigned short*)&l1;
    lp.z = *(unsigned short*)&l2; lp.w = *(unsigned short*)&l3;
    ((ushort4*)(whi + rowoff))[tid] = hp;
    ((ushort4*)(wlo + rowoff))[tid] = lp;
}

// ---------------------------------------------------------------------------
// ctx via mma: ctx[bh][q][dk] = W[bh][q][:] @ V[bh][:][dk]
// CTA = (qtile 128, bh). K loop over seq in chunks of 64, double buffered.
// A = W splits (K-major), B = V splits via ldmatrix.trans from [t][dk].
// Epilogue writes ctx hi/lo splits in [b*T+t][D] layout.
// ---------------------------------------------------------------------------
#define CW_TILE  (128u * SROW)       // 18432
#define CV_TILE  (64u * SROW)        // 9216
#define C_BUF    (2u * CW_TILE + 2u * CV_TILE)   // 55296
#define SM_CTX   (2u * C_BUF)                    // 110592

__global__ __launch_bounds__(256) void ctx_mma_kernel(
    const __nv_bfloat16* __restrict__ whi, const __nv_bfloat16* __restrict__ wlo,
    const __nv_bfloat16* __restrict__ vhi, const __nv_bfloat16* __restrict__ vlo,
    __nv_bfloat16* __restrict__ ctxhi, __nv_bfloat16* __restrict__ ctxlo)
{
    extern __shared__ __align__(128) char smem[];
    const uint32_t sbase = smem_u32(smem);
    const int tid  = threadIdx.x;
    const int lane = tid & 31;
    const int wid  = tid >> 5;            // warp tile: 16 q-rows x 64 dk

    const int q0 = blockIdx.x * 128;
    const int bh = blockIdx.y;
    const int b  = bh >> 4;
    const int h  = bh & 15;

    float acc[8][4];
#pragma unroll
    for (int i = 0; i < 8; i++)
#pragma unroll
        for (int j = 0; j < 4; j++) acc[i][j] = 0.f;

    // stage helper (inline)
    auto stage = [&](uint32_t sb, int k0) {
        for (int i = tid; i < 1024; i += 256) {         // W tiles
            const int row = i >> 3;
            const int seg = i & 7;
            const uint32_t d = (uint32_t)row * SROW + seg * 16;
            const size_t g = ((size_t)bh * Tc + q0 + row) * Tc + k0 + seg * 8;
            cpasync16(sb + d,           whi + g);
            cpasync16(sb + CW_TILE + d, wlo + g);
        }
        for (int i = tid; i < 512; i += 256) {          // V tiles (64 rows)
            const int row = i >> 3;
            const int seg = i & 7;
            const uint32_t d = (uint32_t)row * SROW + seg * 16;
            const size_t g = ((size_t)bh * Tc + k0 + row) * 64 + seg * 8;
            cpasync16(sb + 2 * CW_TILE + d,           vhi + g);
            cpasync16(sb + 2 * CW_TILE + CV_TILE + d, vlo + g);
        }
        asm volatile("cp.async.commit_group;" ::: "memory");
    };

    stage(sbase, 0);
    for (int ch = 0; ch < 16; ch++) {
        asm volatile("cp.async.wait_group 0;" ::: "memory");
        __syncthreads();
        if (ch + 1 < 16)
            stage(sbase + ((ch + 1) & 1) * C_BUF, (ch + 1) * 64);

        const uint32_t cb = sbase + (ch & 1) * C_BUF;
#pragma unroll
        for (int ks = 0; ks < 4; ks++) {
            uint32_t ahi[4], alo[4], bhi[8][2], blo[8][2];
            {
                const uint32_t addr = cb
                    + (uint32_t)(wid * 16 + (lane & 15)) * SROW
                    + ks * 32 + (lane >> 4) * 16;
                ldm_x4(ahi, addr);
                ldm_x4(alo, addr + CW_TILE);
            }
#pragma unroll
            for (int nc = 0; nc < 4; nc++) {
                uint32_t tmp[4];
                const uint32_t addr = cb + 2 * CW_TILE
                    + (uint32_t)(ks * 16 + (lane & 7) + ((lane >> 3) & 1) * 8) * SROW
                    + nc * 32 + (lane >> 4) * 16;
                ldm_x4_trans(tmp, addr);
                bhi[nc * 2 + 0][0] = tmp[0]; bhi[nc * 2 + 0][1] = tmp[1];
                bhi[nc * 2 + 1][0] = tmp[2]; bhi[nc * 2 + 1][1] = tmp[3];
                ldm_x4_trans(tmp, addr + CV_TILE);
                blo[nc * 2 + 0][0] = tmp[0]; blo[nc * 2 + 0][1] = tmp[1];
                blo[nc * 2 + 1][0] = tmp[2]; blo[nc * 2 + 1][1] = tmp[3];
            }
#pragma unroll
            for (int nt = 0; nt < 8; nt++) {
                mma_bf16(acc[nt], ahi, bhi[nt]);
                mma_bf16(acc[nt], ahi, blo[nt]);
                mma_bf16(acc[nt], alo, bhi[nt]);
            }
        }
    }

    // epilogue: split-store ctx in [b*T+t][D] layout
    const int tr = lane >> 2;
    const int tc = (lane & 3) * 2;
    const int t0 = q0 + wid * 16 + tr;
#pragma unroll
    for (int nt = 0; nt < 8; nt++) {
        const int dk = nt * 8 + tc;
        const size_t i0 = ((size_t)(b * Tc + t0)) * Dc + h * 64 + dk;
        const size_t i1 = ((size_t)(b * Tc + t0 + 8)) * Dc + h * 64 + dk;
        split_store2(ctxhi, ctxlo, i0, acc[nt][0], acc[nt][1]);
        split_store2(ctxhi, ctxlo, i1, acc[nt][2], acc[nt][3]);
    }
}

// ---------------------------------------------------------------------------
extern "C" void kernel_launch(void* const* d_in, const int* in_sizes, int n_in,
                              void* d_out, int out_size)
{
    const float* x    = (const float*)d_in[0];
    const int*   mask = (const int*)d_in[1];      // jax bool -> int32
    const float* Wqkv = (const float*)d_in[2];
    const float* bqkv = (const float*)d_in[3];
    const float* Wo   = (const float*)d_in[4];
    const float* bo   = (const float*)d_in[5];

    float* out     = (float*)d_out;
    float* weights = out + (size_t)Bc * Tc * Dc;

    __nv_bfloat16 *xhi, *xlo, *wqhi, *wqlo, *wohi, *wolo;
    __nv_bfloat16 *qhi, *qlo, *khi, *klo, *vhi, *vlo, *whi, *wlo, *ctxhi, *ctxlo;
    cudaGetSymbolAddress((void**)&xhi, g_xhi);
    cudaGetSymbolAddress((void**)&xlo, g_xlo);
    cudaGetSymbolAddress((void**)&wqhi, g_wqkvthi);
    cudaGetSymbolAddress((void**)&wqlo, g_wqkvtlo);
    cudaGetSymbolAddress((void**)&wohi, g_wothi);
    cudaGetSymbolAddress((void**)&wolo, g_wotlo);
    cudaGetSymbolAddress((void**)&qhi, g_qhi);
    cudaGetSymbolAddress((void**)&qlo, g_qlo);
    cudaGetSymbolAddress((void**)&khi, g_khi);
    cudaGetSymbolAddress((void**)&klo, g_klo);
    cudaGetSymbolAddress((void**)&vhi, g_vhi);
    cudaGetSymbolAddress((void**)&vlo, g_vlo);
    cudaGetSymbolAddress((void**)&whi, g_whi);
    cudaGetSymbolAddress((void**)&wlo, g_wlo);
    cudaGetSymbolAddress((void**)&ctxhi, g_ctxhi);
    cudaGetSymbolAddress((void**)&ctxlo, g_ctxlo);

    static int attr_set = 0;
    if (!attr_set) {
        cudaFuncSetAttribute(gemm_qkv_kernel,
                             cudaFuncAttributeMaxDynamicSharedMemorySize, GSMEM);
        cudaFuncSetAttribute(gemm_mma_split_kernel,
                             cudaFuncAttributeMaxDynamicSharedMemorySize, GSMEM);
        cudaFuncSetAttribute(scores_mma_kernel,
                             cudaFuncAttributeMaxDynamicSharedMemorySize, SM_SCORES);
        cudaFuncSetAttribute(ctx_mma_kernel,
                             cudaFuncAttributeMaxDynamicSharedMemorySize, SM_CTX);
        attr_set = 1;
    }

    const int nx4 = (Bc * Tc * Dc) / 4;

    // 0) input splits / weight transposes
    split_kernel<<<(nx4 + 255) / 256, 256>>>(x, xhi, xlo, nx4);
    transpose_split_kernel<<<dim3(D3c / 32, Dc / 32), 256>>>(Wqkv, wqhi, wqlo, Dc, D3c);
    transpose_split_kernel<<<dim3(Dc / 32, Dc / 32), 256>>>(Wo, wohi, wolo, Dc, Dc);

    // 1) QKV projection -> head-major bf16 splits
    gemm_qkv_kernel<<<dim3(D3c / TBN, (Bc * Tc) / TBM), 256, GSMEM>>>(
        xhi, xlo, wqhi, wqlo, bqkv, qhi, qlo, khi, klo, vhi, vlo, Dc);

    // 2) scores on tensor cores -> masked scaled fp32 logits
    scores_mma_kernel<<<dim3(Tc / 128, Tc / 128, Bc * NHc), 256, SM_SCORES>>>(
        qhi, qlo, khi, klo, mask, weights);

    // 3) softmax in place + weight splits
    softmax_kernel<<<Bc * NHc * Tc, 256>>>(weights, whi, wlo);

    // 4) ctx on tensor cores -> ctx bf16 splits
    ctx_mma_kernel<<<dim3(Tc / 128, Bc * NHc), 256, SM_CTX>>>(
        whi, wlo, vhi, vlo, ctxhi, ctxlo);

    // 5) output projection
    gemm_mma_split_kernel<<<dim3(Dc / TBN, (Bc * Tc) / TBM), 256, GSMEM>>>(
        ctxhi, ctxlo, wohi, wolo, bo, out, Dc, Dc);
}

// round 11
// speedup vs baseline: 2.3360x; 1.0673x over previous
#include <cuda_runtime.h>
#include <cuda_bf16.h>
#include <cstdint>

// Problem constants
#define Bc   8
#define Tc   1024
#define Dc   1024
#define NHc  16
#define DKc  64
#define D3c  3072

// ---------------------------------------------------------------------------
// Scratch (device globals — allocation-free rule)
// ---------------------------------------------------------------------------
__device__ __nv_bfloat16 g_xhi[(size_t)Bc * Tc * Dc];
__device__ __nv_bfloat16 g_xlo[(size_t)Bc * Tc * Dc];
__device__ __nv_bfloat16 g_wqkvthi[(size_t)D3c * Dc];   // Wqkv^T [N=3072][K=1024]
__device__ __nv_bfloat16 g_wqkvtlo[(size_t)D3c * Dc];
__device__ __nv_bfloat16 g_wothi[(size_t)Dc * Dc];      // Wo^T [N=1024][K=1024]
__device__ __nv_bfloat16 g_wotlo[(size_t)Dc * Dc];
// head-major splits produced by QKV epilogue: [bh][t][64]
__device__ __nv_bfloat16 g_qhi[(size_t)128 * Tc * DKc];
__device__ __nv_bfloat16 g_qlo[(size_t)128 * Tc * DKc];
__device__ __nv_bfloat16 g_khi[(size_t)128 * Tc * DKc];
__device__ __nv_bfloat16 g_klo[(size_t)128 * Tc * DKc];
__device__ __nv_bfloat16 g_vhi[(size_t)128 * Tc * DKc];
__device__ __nv_bfloat16 g_vlo[(size_t)128 * Tc * DKc];
// ctx splits: [b*T+t][D]
__device__ __nv_bfloat16 g_ctxhi[(size_t)Bc * Tc * Dc];
__device__ __nv_bfloat16 g_ctxlo[(size_t)Bc * Tc * Dc];

// ---------------------------------------------------------------------------
// sm_80-era primitives (legal on plain sm_103 target)
// ---------------------------------------------------------------------------
__device__ __forceinline__ uint32_t smem_u32(const void* p) {
    uint32_t a;
    asm("{ .reg .u64 t; cvta.to.shared.u64 t, %1; cvt.u32.u64 %0, t; }"
        : "=r"(a) : "l"(p));
    return a;
}
__device__ __forceinline__ void cpasync16(uint32_t dst_smem, const void* src) {
    asm volatile("cp.async.cg.shared.global [%0], [%1], 16;"
                 :: "r"(dst_smem), "l"(src));
}
__device__ __forceinline__ void ldm_x4(uint32_t* r, uint32_t addr) {
    asm volatile("ldmatrix.sync.aligned.m8n8.x4.shared.b16 {%0,%1,%2,%3}, [%4];"
                 : "=r"(r[0]), "=r"(r[1]), "=r"(r[2]), "=r"(r[3]) : "r"(addr));
}
__device__ __forceinline__ void ldm_x4_trans(uint32_t* r, uint32_t addr) {
    asm volatile("ldmatrix.sync.aligned.m8n8.x4.trans.shared.b16 {%0,%1,%2,%3}, [%4];"
                 : "=r"(r[0]), "=r"(r[1]), "=r"(r[2]), "=r"(r[3]) : "r"(addr));
}
__device__ __forceinline__ void mma_bf16(float* d, const uint32_t* a, const uint32_t* b) {
    asm volatile(
        "mma.sync.aligned.m16n8k16.row.col.f32.bf16.bf16.f32 "
        "{%0,%1,%2,%3}, {%4,%5,%6,%7}, {%8,%9}, {%0,%1,%2,%3};"
        : "+f"(d[0]), "+f"(d[1]), "+f"(d[2]), "+f"(d[3])
        : "r"(a[0]), "r"(a[1]), "r"(a[2]), "r"(a[3]), "r"(b[0]), "r"(b[1]));
}

__device__ __forceinline__ void split_store2(
    __nv_bfloat16* hi, __nv_bfloat16* lo, size_t idx, float f0, float f1)
{
    __nv_bfloat16 h0 = __float2bfloat16(f0);
    __nv_bfloat16 h1 = __float2bfloat16(f1);
    __nv_bfloat16 l0 = __float2bfloat16(f0 - __bfloat162float(h0));
    __nv_bfloat16 l1 = __float2bfloat16(f1 - __bfloat162float(h1));
    ushort2 hp, lp;
    hp.x = *(unsigned short*)&h0; hp.y = *(unsigned short*)&h1;
    lp.x = *(unsigned short*)&l0; lp.y = *(unsigned short*)&l1;
    *(ushort2*)(hi + idx) = hp;
    *(ushort2*)(lo + idx) = lp;
}

// pack two floats -> bf16x2 hi reg + bf16x2 lo reg (split)
__device__ __forceinline__ void split_pack2(float f0, float f1,
                                            uint32_t& hi, uint32_t& lo)
{
    __nv_bfloat16 h0 = __float2bfloat16(f0);
    __nv_bfloat16 h1 = __float2bfloat16(f1);
    __nv_bfloat16 l0 = __float2bfloat16(f0 - __bfloat162float(h0));
    __nv_bfloat16 l1 = __float2bfloat16(f1 - __bfloat162float(h1));
    hi = (uint32_t)*(unsigned short*)&h0 | ((uint32_t)*(unsigned short*)&h1 << 16);
    lo = (uint32_t)*(unsigned short*)&l0 | ((uint32_t)*(unsigned short*)&l1 << 16);
}

// ---------------------------------------------------------------------------
// Conversion kernels
// ---------------------------------------------------------------------------
__global__ __launch_bounds__(256) void split_kernel(
    const float* __restrict__ in, __nv_bfloat16* __restrict__ hi,
    __nv_bfloat16* __restrict__ lo, int n4)
{
    int i = blockIdx.x * 256 + threadIdx.x;
    if (i >= n4) return;
    float4 v = ((const float4*)in)[i];
    __nv_bfloat16 h0 = __float2bfloat16(v.x);
    __nv_bfloat16 h1 = __float2bfloat16(v.y);
    __nv_bfloat16 h2 = __float2bfloat16(v.z);
    __nv_bfloat16 h3 = __float2bfloat16(v.w);
    __nv_bfloat16 l0 = __float2bfloat16(v.x - __bfloat162float(h0));
    __nv_bfloat16 l1 = __float2bfloat16(v.y - __bfloat162float(h1));
    __nv_bfloat16 l2 = __float2bfloat16(v.z - __bfloat162float(h2));
    __nv_bfloat16 l3 = __float2bfloat16(v.w - __bfloat162float(h3));
    ushort4 hp, lp;
    hp.x = *(unsigned short*)&h0; hp.y = *(unsigned short*)&h1;
    hp.z = *(unsigned short*)&h2; hp.w = *(unsigned short*)&h3;
    lp.x = *(unsigned short*)&l0; lp.y = *(unsigned short*)&l1;
    lp.z = *(unsigned short*)&l2; lp.w = *(unsigned short*)&l3;
    ((ushort4*)hi)[i] = hp;
    ((ushort4*)lo)[i] = lp;
}

__global__ __launch_bounds__(256) void transpose_split_kernel(
    const float* __restrict__ W, __nv_bfloat16* __restrict__ Thi,
    __nv_bfloat16* __restrict__ Tlo, int K, int N)
{
    __shared__ float t[32][33];
    const int n0 = blockIdx.x * 32;
    const int k0 = blockIdx.y * 32;
    const int tx = threadIdx.x & 31;
    const int ty = threadIdx.x >> 5;
    for (int j = ty; j < 32; j += 8)
        t[j][tx] = W[(size_t)(k0 + j) * N + n0 + tx];
    __syncthreads();
    for (int j = ty; j < 32; j += 8) {
        float v = t[tx][j];
        __nv_bfloat16 h = __float2bfloat16(v);
        __nv_bfloat16 l = __float2bfloat16(v - __bfloat162float(h));
        Thi[(size_t)(n0 + j) * K + k0 + tx] = h;
        Tlo[(size_t)(n0 + j) * K + k0 + tx] = l;
    }
}

// ---------------------------------------------------------------------------
// Shared GEMM mainloop config (128x128 block, 8 warps 64x32, K-chunk 32)
// ---------------------------------------------------------------------------
#define TBM 128
#define TBN 128
#define TBK 32
#define ROW_B    80u
#define T_BYTES  10240u
#define BUF_BYTES (4u * T_BYTES)
#define GSMEM    (2 * BUF_BYTES)

__device__ __forceinline__ void stage_chunk(
    uint32_t sbase, const __nv_bfloat16* Ahi, const __nv_bfloat16* Alo,
    const __nv_bfloat16* Bhi, const __nv_bfloat16* Blo,
    int rowBase, int colBase, int K, int k0, int tid)
{
    const int quad = tid & 3;
    const int r0   = tid >> 2;
#pragma unroll
    for (int p = 0; p < 2; p++) {
        const int row = r0 + p * 64;
        const uint32_t d = (uint32_t)row * ROW_B + quad * 16;
        const size_t ga = (size_t)(rowBase + row) * K + k0 + quad * 8;
        const size_t gb = (size_t)(colBase + row) * K + k0 + quad * 8;
        cpasync16(sbase + d,               Ahi + ga);
        cpasync16(sbase + T_BYTES + d,     Alo + ga);
        cpasync16(sbase + 2 * T_BYTES + d, Bhi + gb);
        cpasync16(sbase + 3 * T_BYTES + d, Blo + gb);
    }
    asm volatile("cp.async.commit_group;" ::: "memory");
}

// Mainloop macro body used by both projection GEMMs
#define GEMM_MAINLOOP(ACC)                                                    \
    const int nchunks = K / TBK;                                              \
    stage_chunk(sbase, Ahi, Alo, Bhi, Blo, rowBase, colBase, K, 0, tid);      \
    for (int ch = 0; ch < nchunks; ch++) {                                    \
        asm volatile("cp.async.wait_group 0;" ::: "memory");                  \
        __syncthreads();                                                      \
        if (ch + 1 < nchunks)                                                 \
            stage_chunk(sbase + ((ch + 1) & 1) * BUF_BYTES, Ahi, Alo, Bhi,    \
                        Blo, rowBase, colBase, K, (ch + 1) * TBK, tid);       \
        const uint32_t cb = sbase + (ch & 1) * BUF_BYTES;                     \
        _Pragma("unroll")                                                     \
        for (int ks = 0; ks < 2; ks++) {                                      \
            uint32_t ahi[4][4], alo[4][4], bhi[4][2], blo[4][2];              \
            _Pragma("unroll")                                                 \
            for (int mt = 0; mt < 4; mt++) {                                  \
                const uint32_t addr = cb                                      \
                    + (uint32_t)(warp_m * 64 + mt * 16 + (lane & 15)) * ROW_B \
                    + ks * 32 + (lane >> 4) * 16;                             \
                ldm_x4(ahi[mt], addr);                                        \
                ldm_x4(alo[mt], addr + T_BYTES);                              \
            }                                                                 \
            _Pragma("unroll")                                                 \
            for (int pr = 0; pr < 2; pr++) {                                  \
                uint32_t tmp[4];                                              \
                const uint32_t addr = cb + 2 * T_BYTES                        \
                    + (uint32_t)(warp_n * 32 + pr * 16 + (lane >> 4) * 8      \
                                 + (lane & 7)) * ROW_B                        \
                    + ks * 32 + ((lane >> 3) & 1) * 16;                       \
                ldm_x4(tmp, addr);                                            \
                bhi[pr * 2 + 0][0] = tmp[0]; bhi[pr * 2 + 0][1] = tmp[1];     \
                bhi[pr * 2 + 1][0] = tmp[2]; bhi[pr * 2 + 1][1] = tmp[3];     \
                ldm_x4(tmp, addr + T_BYTES);                                  \
                blo[pr * 2 + 0][0] = tmp[0]; blo[pr * 2 + 0][1] = tmp[1];     \
                blo[pr * 2 + 1][0] = tmp[2]; blo[pr * 2 + 1][1] = tmp[3];     \
            }                                                                 \
            _Pragma("unroll")                                                 \
            for (int mt = 0; mt < 4; mt++)                                    \
                _Pragma("unroll")                                             \
                for (int nt = 0; nt < 4; nt++) {                              \
                    mma_bf16(ACC[mt][nt], ahi[mt], bhi[nt]);                  \
                    mma_bf16(ACC[mt][nt], ahi[mt], blo[nt]);                  \
                    mma_bf16(ACC[mt][nt], alo[mt], bhi[nt]);                  \
                }                                                             \
        }                                                                     \
    }

// ---------------------------------------------------------------------------
// QKV GEMM -> head-major bf16 hi/lo splits
// ---------------------------------------------------------------------------
__global__ __launch_bounds__(256, 2) void gemm_qkv_kernel(
    const __nv_bfloat16* __restrict__ Ahi, const __nv_bfloat16* __restrict__ Alo,
    const __nv_bfloat16* __restrict__ Bhi, const __nv_bfloat16* __restrict__ Blo,
    const float* __restrict__ bias,
    __nv_bfloat16* __restrict__ qhi, __nv_bfloat16* __restrict__ qlo,
    __nv_bfloat16* __restrict__ khi, __nv_bfloat16* __restrict__ klo,
    __nv_bfloat16* __restrict__ vhi, __nv_bfloat16* __restrict__ vlo,
    int K)
{
    extern __shared__ __align__(128) char smem[];
    const uint32_t sbase = smem_u32(smem);
    const int tid    = threadIdx.x;
    const int lane   = tid & 31;
    const int wid    = tid >> 5;
    const int warp_m = wid >> 2;
    const int warp_n = wid & 3;
    const int rowBase = blockIdx.y * TBM;
    const int colBase = blockIdx.x * TBN;

    float acc[4][4][4];
#pragma unroll
    for (int i = 0; i < 4; i++)
#pragma unroll
        for (int j = 0; j < 4; j++)
#pragma unroll
            for (int k = 0; k < 4; k++) acc[i][j][k] = 0.f;

    GEMM_MAINLOOP(acc)

    // epilogue: split + scatter to head-major layout
    const int region = colBase >> 10;          // 0=q,1=k,2=v
    __nv_bfloat16* dsthi = (region == 0) ? qhi : ((region == 1) ? khi : vhi);
    __nv_bfloat16* dstlo = (region == 0) ? qlo : ((region == 1) ? klo : vlo);
    const int b  = rowBase >> 10;
    const int tr = lane >> 2;
    const int tc = (lane & 3) * 2;
#pragma unroll
    for (int mt = 0; mt < 4; mt++) {
        const int t0 = (rowBase & 1023) + warp_m * 64 + mt * 16 + tr;
#pragma unroll
        for (int nt = 0; nt < 4; nt++) {
            const int c = colBase + warp_n * 32 + nt * 8 + tc;
            const int head = (c & 1023) >> 6;
            const int dk   = c & 63;
            const float b0 = bias[c], b1 = bias[c + 1];
            const size_t rowb = (size_t)(b * 16 + head) * Tc;
            split_store2(dsthi, dstlo, (rowb + t0) * 64 + dk,
                         acc[mt][nt][0] + b0, acc[mt][nt][1] + b1);
            split_store2(dsthi, dstlo, (rowb + t0 + 8) * 64 + dk,
                         acc[mt][nt][2] + b0, acc[mt][nt][3] + b1);
        }
    }
}

// ---------------------------------------------------------------------------
// Output projection GEMM (fp32 out + bias)
// ---------------------------------------------------------------------------
__global__ __launch_bounds__(256, 2) void gemm_mma_split_kernel(
    const __nv_bfloat16* __restrict__ Ahi, const __nv_bfloat16* __restrict__ Alo,
    const __nv_bfloat16* __restrict__ Bhi, const __nv_bfloat16* __restrict__ Blo,
    const float* __restrict__ bias, float* __restrict__ C, int N, int K)
{
    extern __shared__ __align__(128) char smem[];
    const uint32_t sbase = smem_u32(smem);
    const int tid    = threadIdx.x;
    const int lane   = tid & 31;
    const int wid    = tid >> 5;
    const int warp_m = wid >> 2;
    const int warp_n = wid & 3;
    const int rowBase = blockIdx.y * TBM;
    const int colBase = blockIdx.x * TBN;

    float acc[4][4][4];
#pragma unroll
    for (int i = 0; i < 4; i++)
#pragma unroll
        for (int j = 0; j < 4; j++)
#pragma unroll
            for (int k = 0; k < 4; k++) acc[i][j][k] = 0.f;

    GEMM_MAINLOOP(acc)

    const int tr = lane >> 2;
    const int tc = (lane & 3) * 2;
#pragma unroll
    for (int mt = 0; mt < 4; mt++) {
        const int r0 = rowBase + warp_m * 64 + mt * 16 + tr;
#pragma unroll
        for (int nt = 0; nt < 4; nt++) {
            const int c = colBase + warp_n * 32 + nt * 8 + tc;
            const float b0 = bias[c], b1 = bias[c + 1];
            float2 v0, v1;
            v0.x = acc[mt][nt][0] + b0; v0.y = acc[mt][nt][1] + b1;
            v1.x = acc[mt][nt][2] + b0; v1.y = acc[mt][nt][3] + b1;
            *(float2*)(C + (size_t)r0 * N + c) = v0;
            *(float2*)(C + (size_t)(r0 + 8) * N + c) = v1;
        }
    }
}

// ---------------------------------------------------------------------------
// Scores via mma: S[bh][q][k] = (Q.K^T)/8 masked -> fp32 logits
// ---------------------------------------------------------------------------
#define SROW     144u
#define S_TILE   (128u * SROW)       // 18432
#define SM_SCORES (4u * S_TILE)      // 73728

__global__ __launch_bounds__(256) void scores_mma_kernel(
    const __nv_bfloat16* __restrict__ qhi, const __nv_bfloat16* __restrict__ qlo,
    const __nv_bfloat16* __restrict__ khi, const __nv_bfloat16* __restrict__ klo,
    const int* __restrict__ mask, float* __restrict__ logits)
{
    extern __shared__ __align__(128) char smem[];
    const uint32_t sbase = smem_u32(smem);
    const int tid    = threadIdx.x;
    const int lane   = tid & 31;
    const int wid    = tid >> 5;
    const int warp_m = wid >> 2;
    const int warp_n = wid & 3;

    const int k0 = blockIdx.x * 128;
    const int q0 = blockIdx.y * 128;
    const int bh = blockIdx.z;
    const int b  = bh >> 4;

    for (int i = tid; i < 1024; i += 256) {
        const int row = i >> 3;
        const int seg = i & 7;
        const uint32_t d = (uint32_t)row * SROW + seg * 16;
        const size_t gq = ((size_t)bh * Tc + q0 + row) * 64 + seg * 8;
        const size_t gk = ((size_t)bh * Tc + k0 + row) * 64 + seg * 8;
        cpasync16(sbase + d,              qhi + gq);
        cpasync16(sbase + S_TILE + d,     qlo + gq);
        cpasync16(sbase + 2 * S_TILE + d, khi + gk);
        cpasync16(sbase + 3 * S_TILE + d, klo + gk);
    }
    asm volatile("cp.async.commit_group;" ::: "memory");
    asm volatile("cp.async.wait_group 0;" ::: "memory");
    __syncthreads();

    float acc[4][4][4];
#pragma unroll
    for (int i = 0; i < 4; i++)
#pragma unroll
        for (int j = 0; j < 4; j++)
#pragma unroll
            for (int k = 0; k < 4; k++) acc[i][j][k] = 0.f;

#pragma unroll
    for (int ks = 0; ks < 4; ks++) {
        uint32_t ahi[4][4], alo[4][4], bhi[4][2], blo[4][2];
#pragma unroll
        for (int mt = 0; mt < 4; mt++) {
            const uint32_t addr = sbase
                + (uint32_t)(warp_m * 64 + mt * 16 + (lane & 15)) * SROW
                + ks * 32 + (lane >> 4) * 16;
            ldm_x4(ahi[mt], addr);
            ldm_x4(alo[mt], addr + S_TILE);
        }
#pragma unroll
        for (int pr = 0; pr < 2; pr++) {
            uint32_t tmp[4];
            const uint32_t addr = sbase + 2 * S_TILE
                + (uint32_t)(warp_n * 32 + pr * 16 + (lane >> 4) * 8 + (lane & 7)) * SROW
                + ks * 32 + ((lane >> 3) & 1) * 16;
            ldm_x4(tmp, addr);
            bhi[pr * 2 + 0][0] = tmp[0]; bhi[pr * 2 + 0][1] = tmp[1];
            bhi[pr * 2 + 1][0] = tmp[2]; bhi[pr * 2 + 1][1] = tmp[3];
            ldm_x4(tmp, addr + S_TILE);
            blo[pr * 2 + 0][0] = tmp[0]; blo[pr * 2 + 0][1] = tmp[1];
            blo[pr * 2 + 1][0] = tmp[2]; blo[pr * 2 + 1][1] = tmp[3];
        }
#pragma unroll
        for (int mt = 0; mt < 4; mt++)
#pragma unroll
            for (int nt = 0; nt < 4; nt++) {
                mma_bf16(acc[mt][nt], ahi[mt], bhi[nt]);
                mma_bf16(acc[mt][nt], ahi[mt], blo[nt]);
                mma_bf16(acc[mt][nt], alo[mt], bhi[nt]);
            }
    }

    const float NEG_INF = __int_as_float(0xff800000);
    const int tr = lane >> 2;
    const int tc = (lane & 3) * 2;
#pragma unroll
    for (int mt = 0; mt < 4; mt++) {
        const int q = q0 + warp_m * 64 + mt * 16 + tr;
#pragma unroll
        for (int nt = 0; nt < 4; nt++) {
            const int c = k0 + warp_n * 32 + nt * 8 + tc;
            const int m0 = mask[b * Tc + c];
            const int m1 = mask[b * Tc + c + 1];
            float2 v0, v1;
            v0.x = m0 ? acc[mt][nt][0] * 0.125f : NEG_INF;
            v0.y = m1 ? acc[mt][nt][1] * 0.125f : NEG_INF;
            v1.x = m0 ? acc[mt][nt][2] * 0.125f : NEG_INF;
            v1.y = m1 ? acc[mt][nt][3] * 0.125f : NEG_INF;
            float* outp = logits + ((size_t)bh * Tc + q) * Tc + c;
            *(float2*)outp = v0;
            *(float2*)(outp + 8 * Tc) = v1;
        }
    }
}

// ---------------------------------------------------------------------------
// Softmax in place over last dim (1024). Writes ONLY mandatory fp32 weights.
// ---------------------------------------------------------------------------
__global__ __launch_bounds__(256) void softmax_kernel(float* __restrict__ w)
{
    __shared__ float red[256];
    float* p = w + (size_t)blockIdx.x * 1024;
    const int tid = threadIdx.x;

    float4 v = ((const float4*)p)[tid];
    float m = fmaxf(fmaxf(v.x, v.y), fmaxf(v.z, v.w));
    red[tid] = m;
    __syncthreads();
    for (int s = 128; s > 0; s >>= 1) {
        if (tid < s) red[tid] = fmaxf(red[tid], red[tid + s]);
        __syncthreads();
    }
    m = red[0];
    __syncthreads();

    float4 e;
    e.x = __expf(v.x - m);
    e.y = __expf(v.y - m);
    e.z = __expf(v.z - m);
    e.w = __expf(v.w - m);
    red[tid] = e.x + e.y + e.z + e.w;
    __syncthreads();
    for (int s = 128; s > 0; s >>= 1) {
        if (tid < s) red[tid] += red[tid + s];
        __syncthreads();
    }
    const float inv = 1.0f / red[0];

    e.x *= inv; e.y *= inv; e.z *= inv; e.w *= inv;
    ((float4*)p)[tid] = e;
}

// ---------------------------------------------------------------------------
// ctx via mma: ctx[bh][q][dk] = W[bh][q][:] @ V[bh][:][dk]
// W read as fp32 (the softmaxed output weights); A-fragments are built by
// LDS.64 from an fp32 smem tile + in-register bf16 hi/lo split.
// V = bf16 hi/lo splits via ldmatrix.trans. 3-term emulation.
// ---------------------------------------------------------------------------
#define CWF_STRIDE_F 72u                         // floats per smem row (64+8 pad)
#define CW_TILE_F  (128u * CWF_STRIDE_F * 4u)    // 36864 B
#define CV_TILE    (64u * SROW)                  // 9216 B
#define C_BUF      (CW_TILE_F + 2u * CV_TILE)    // 55296 B
#define SM_CTX     (2u * C_BUF)                  // 110592 B

__global__ __launch_bounds__(256) void ctx_mma_kernel(
    const float* __restrict__ w,                 // fp32 weights [bh][q][k]
    const __nv_bfloat16* __restrict__ vhi, const __nv_bfloat16* __restrict__ vlo,
    __nv_bfloat16* __restrict__ ctxhi, __nv_bfloat16* __restrict__ ctxlo)
{
    extern __shared__ __align__(128) char smem[];
    const uint32_t sbase = smem_u32(smem);
    const int tid  = threadIdx.x;
    const int lane = tid & 31;
    const int wid  = tid >> 5;            // warp tile: 16 q-rows x 64 dk

    const int q0 = blockIdx.x * 128;
    const int bh = blockIdx.y;
    const int b  = bh >> 4;
    const int h  = bh & 15;

    float acc[8][4];
#pragma unroll
    for (int i = 0; i < 8; i++)
#pragma unroll
        for (int j = 0; j < 4; j++) acc[i][j] = 0.f;

    auto stage = [&](uint32_t sb, int k0) {
        // W fp32 tile: 128 rows x 64 floats (16 x 16B segs/row)
        for (int i = tid; i < 2048; i += 256) {
            const int row = i >> 4;
            const int seg = i & 15;
            const uint32_t d = (uint32_t)row * (CWF_STRIDE_F * 4) + seg * 16;
            const size_t g = ((size_t)bh * Tc + q0 + row) * Tc + k0 + seg * 4;
            cpasync16(sb + d, w + g);
        }
        // V tiles: 64 rows x 64 bf16, hi & lo
        for (int i = tid; i < 512; i += 256) {
            const int row = i >> 3;
            const int seg = i & 7;
            const uint32_t d = (uint32_t)row * SROW + seg * 16;
            const size_t g = ((size_t)bh * Tc + k0 + row) * 64 + seg * 8;
            cpasync16(sb + CW_TILE_F + d,           vhi + g);
            cpasync16(sb + CW_TILE_F + CV_TILE + d, vlo + g);
        }
        asm volatile("cp.async.commit_group;" ::: "memory");
    };

    const int tr = lane >> 2;
    const int tc = (lane & 3) * 2;

    stage(sbase, 0);
    for (int ch = 0; ch < 16; ch++) {
        asm volatile("cp.async.wait_group 0;" ::: "memory");
        __syncthreads();
        if (ch + 1 < 16)
            stage(sbase + ((ch + 1) & 1) * C_BUF, (ch + 1) * 64);

        const uint32_t cb = sbase + (ch & 1) * C_BUF;
        const float* wsm = (const float*)(smem + (ch & 1) * C_BUF);
#pragma unroll
        for (int ks = 0; ks < 4; ks++) {
            uint32_t ahi[4], alo[4], bhi[8][2], blo[8][2];
            {
                // A fragment rows: wid*16 + tr (+8); cols: ks*16 + tc (+8)
                const uint32_t r0off = (uint32_t)(wid * 16 + tr) * CWF_STRIDE_F
                                       + ks * 16 + tc;
                float2 f00 = *(const float2*)(wsm + r0off);
                float2 f10 = *(const float2*)(wsm + r0off + 8 * CWF_STRIDE_F);
                float2 f01 = *(const float2*)(wsm + r0off + 8);
                float2 f11 = *(const float2*)(wsm + r0off + 8 * CWF_STRIDE_F + 8);
                split_pack2(f00.x, f00.y, ahi[0], alo[0]);
                split_pack2(f10.x, f10.y, ahi[1], alo[1]);
                split_pack2(f01.x, f01.y, ahi[2], alo[2]);
                split_pack2(f11.x, f11.y, ahi[3], alo[3]);
            }
#pragma unroll
            for (int nc = 0; nc < 4; nc++) {
                uint32_t tmp[4];
                const uint32_t addr = cb + CW_TILE_F
                    + (uint32_t)(ks * 16 + (lane & 7) + ((lane >> 3) & 1) * 8) * SROW
                    + nc * 32 + (lane >> 4) * 16;
                ldm_x4_trans(tmp, addr);
                bhi[nc * 2 + 0][0] = tmp[0]; bhi[nc * 2 + 0][1] = tmp[1];
                bhi[nc * 2 + 1][0] = tmp[2]; bhi[nc * 2 + 1][1] = tmp[3];
                ldm_x4_trans(tmp, addr + CV_TILE);
                blo[nc * 2 + 0][0] = tmp[0]; blo[nc * 2 + 0][1] = tmp[1];
                blo[nc * 2 + 1][0] = tmp[2]; blo[nc * 2 + 1][1] = tmp[3];
            }
#pragma unroll
            for (int nt = 0; nt < 8; nt++) {
                mma_bf16(acc[nt], ahi, bhi[nt]);
                mma_bf16(acc[nt], ahi, blo[nt]);
                mma_bf16(acc[nt], alo, bhi[nt]);
            }
        }
    }

    // epilogue: split-store ctx in [b*T+t][D] layout
    const int t0 = q0 + wid * 16 + tr;
#pragma unroll
    for (int nt = 0; nt < 8; nt++) {
        const int dk = nt * 8 + tc;
        const size_t i0 = ((size_t)(b * Tc + t0)) * Dc + h * 64 + dk;
        const size_t i1 = ((size_t)(b * Tc + t0 + 8)) * Dc + h * 64 + dk;
        split_store2(ctxhi, ctxlo, i0, acc[nt][0], acc[nt][1]);
        split_store2(ctxhi, ctxlo, i1, acc[nt][2], acc[nt][3]);
    }
}

// ---------------------------------------------------------------------------
extern "C" void kernel_launch(void* const* d_in, const int* in_sizes, int n_in,
                              void* d_out, int out_size)
{
    const float* x    = (const float*)d_in[0];
    const int*   mask = (const int*)d_in[1];      // jax bool -> int32
    const float* Wqkv = (const float*)d_in[2];
    const float* bqkv = (const float*)d_in[3];
    const float* Wo   = (const float*)d_in[4];
    const float* bo   = (const float*)d_in[5];

    float* out     = (float*)d_out;
    float* weights = out + (size_t)Bc * Tc * Dc;

    __nv_bfloat16 *xhi, *xlo, *wqhi, *wqlo, *wohi, *wolo;
    __nv_bfloat16 *qhi, *qlo, *khi, *klo, *vhi, *vlo, *ctxhi, *ctxlo;
    cudaGetSymbolAddress((void**)&xhi, g_xhi);
    cudaGetSymbolAddress((void**)&xlo, g_xlo);
    cudaGetSymbolAddress((void**)&wqhi, g_wqkvthi);
    cudaGetSymbolAddress((void**)&wqlo, g_wqkvtlo);
    cudaGetSymbolAddress((void**)&wohi, g_wothi);
    cudaGetSymbolAddress((void**)&wolo, g_wotlo);
    cudaGetSymbolAddress((void**)&qhi, g_qhi);
    cudaGetSymbolAddress((void**)&qlo, g_qlo);
    cudaGetSymbolAddress((void**)&khi, g_khi);
    cudaGetSymbolAddress((void**)&klo, g_klo);
    cudaGetSymbolAddress((void**)&vhi, g_vhi);
    cudaGetSymbolAddress((void**)&vlo, g_vlo);
    cudaGetSymbolAddress((void**)&ctxhi, g_ctxhi);
    cudaGetSymbolAddress((void**)&ctxlo, g_ctxlo);

    static int attr_set = 0;
    if (!attr_set) {
        cudaFuncSetAttribute(gemm_qkv_kernel,
                             cudaFuncAttributeMaxDynamicSharedMemorySize, GSMEM);
        cudaFuncSetAttribute(gemm_mma_split_kernel,
                             cudaFuncAttributeMaxDynamicSharedMemorySize, GSMEM);
        cudaFuncSetAttribute(scores_mma_kernel,
                             cudaFuncAttributeMaxDynamicSharedMemorySize, SM_SCORES);
        cudaFuncSetAttribute(ctx_mma_kernel,
                             cudaFuncAttributeMaxDynamicSharedMemorySize, SM_CTX);
        attr_set = 1;
    }

    const int nx4 = (Bc * Tc * Dc) / 4;

    // 0) input splits / weight transposes
    split_kernel<<<(nx4 + 255) / 256, 256>>>(x, xhi, xlo, nx4);
    transpose_split_kernel<<<dim3(D3c / 32, Dc / 32), 256>>>(Wqkv, wqhi, wqlo, Dc, D3c);
    transpose_split_kernel<<<dim3(Dc / 32, Dc / 32), 256>>>(Wo, wohi, wolo, Dc, Dc);

    // 1) QKV projection -> head-major bf16 splits
    gemm_qkv_kernel<<<dim3(D3c / TBN, (Bc * Tc) / TBM), 256, GSMEM>>>(
        xhi, xlo, wqhi, wqlo, bqkv, qhi, qlo, khi, klo, vhi, vlo, Dc);

    // 2) scores on tensor cores -> masked scaled fp32 logits
    scores_mma_kernel<<<dim3(Tc / 128, Tc / 128, Bc * NHc), 256, SM_SCORES>>>(
        qhi, qlo, khi, klo, mask, weights);

    // 3) softmax in place (fp32 weights only — the mandatory output)
    softmax_kernel<<<Bc * NHc * Tc, 256>>>(weights);

    // 4) ctx on tensor cores, consuming fp32 weights directly
    ctx_mma_kernel<<<dim3(Tc / 128, Bc * NHc), 256, SM_CTX>>>(
        weights, vhi, vlo, ctxhi, ctxlo);

    // 5) output projection
    gemm_mma_split_kernel<<<dim3(Dc / TBN, (Bc * Tc) / TBM), 256, GSMEM>>>(
        ctxhi, ctxlo, wohi, wolo, bo, out, Dc, Dc);
}

// round 12
// speedup vs baseline: 2.3844x; 1.0207x over previous
#include <cuda_runtime.h>
#include <cuda_bf16.h>
#include <cstdint>

// Problem constants
#define Bc   8
#define Tc   1024
#define Dc   1024
#define NHc  16
#define DKc  64
#define D3c  3072

// ---------------------------------------------------------------------------
// Scratch (device globals — allocation-free rule)
// ---------------------------------------------------------------------------
__device__ __nv_bfloat16 g_xhi[(size_t)Bc * Tc * Dc];
__device__ __nv_bfloat16 g_xlo[(size_t)Bc * Tc * Dc];
__device__ __nv_bfloat16 g_wqkvthi[(size_t)D3c * Dc];   // Wqkv^T [N=3072][K=1024]
__device__ __nv_bfloat16 g_wqkvtlo[(size_t)D3c * Dc];
__device__ __nv_bfloat16 g_wothi[(size_t)Dc * Dc];      // Wo^T [N=1024][K=1024]
__device__ __nv_bfloat16 g_wotlo[(size_t)Dc * Dc];
// head-major splits produced by QKV epilogue: [bh][t][64]
__device__ __nv_bfloat16 g_qhi[(size_t)128 * Tc * DKc];
__device__ __nv_bfloat16 g_qlo[(size_t)128 * Tc * DKc];
__device__ __nv_bfloat16 g_khi[(size_t)128 * Tc * DKc];
__device__ __nv_bfloat16 g_klo[(size_t)128 * Tc * DKc];
__device__ __nv_bfloat16 g_vhi[(size_t)128 * Tc * DKc];
__device__ __nv_bfloat16 g_vlo[(size_t)128 * Tc * DKc];
// ctx splits: [b*T+t][D]
__device__ __nv_bfloat16 g_ctxhi[(size_t)Bc * Tc * Dc];
__device__ __nv_bfloat16 g_ctxlo[(size_t)Bc * Tc * Dc];

// ---------------------------------------------------------------------------
// sm_80-era primitives (legal on plain sm_103 target)
// ---------------------------------------------------------------------------
__device__ __forceinline__ uint32_t smem_u32(const void* p) {
    uint32_t a;
    asm("{ .reg .u64 t; cvta.to.shared.u64 t, %1; cvt.u32.u64 %0, t; }"
        : "=r"(a) : "l"(p));
    return a;
}
__device__ __forceinline__ void cpasync16(uint32_t dst_smem, const void* src) {
    asm volatile("cp.async.cg.shared.global [%0], [%1], 16;"
                 :: "r"(dst_smem), "l"(src));
}
__device__ __forceinline__ void ldm_x4(uint32_t* r, uint32_t addr) {
    asm volatile("ldmatrix.sync.aligned.m8n8.x4.shared.b16 {%0,%1,%2,%3}, [%4];"
                 : "=r"(r[0]), "=r"(r[1]), "=r"(r[2]), "=r"(r[3]) : "r"(addr));
}
__device__ __forceinline__ void ldm_x4_trans(uint32_t* r, uint32_t addr) {
    asm volatile("ldmatrix.sync.aligned.m8n8.x4.trans.shared.b16 {%0,%1,%2,%3}, [%4];"
                 : "=r"(r[0]), "=r"(r[1]), "=r"(r[2]), "=r"(r[3]) : "r"(addr));
}
__device__ __forceinline__ void mma_bf16(float* d, const uint32_t* a, const uint32_t* b) {
    asm volatile(
        "mma.sync.aligned.m16n8k16.row.col.f32.bf16.bf16.f32 "
        "{%0,%1,%2,%3}, {%4,%5,%6,%7}, {%8,%9}, {%0,%1,%2,%3};"
        : "+f"(d[0]), "+f"(d[1]), "+f"(d[2]), "+f"(d[3])
        : "r"(a[0]), "r"(a[1]), "r"(a[2]), "r"(a[3]), "r"(b[0]), "r"(b[1]));
}

__device__ __forceinline__ void split_store2(
    __nv_bfloat16* hi, __nv_bfloat16* lo, size_t idx, float f0, float f1)
{
    __nv_bfloat16 h0 = __float2bfloat16(f0);
    __nv_bfloat16 h1 = __float2bfloat16(f1);
    __nv_bfloat16 l0 = __float2bfloat16(f0 - __bfloat162float(h0));
    __nv_bfloat16 l1 = __float2bfloat16(f1 - __bfloat162float(h1));
    ushort2 hp, lp;
    hp.x = *(unsigned short*)&h0; hp.y = *(unsigned short*)&h1;
    lp.x = *(unsigned short*)&l0; lp.y = *(unsigned short*)&l1;
    *(ushort2*)(hi + idx) = hp;
    *(ushort2*)(lo + idx) = lp;
}

// pack two floats -> bf16x2 hi reg + bf16x2 lo reg (split)
__device__ __forceinline__ void split_pack2(float f0, float f1,
                                            uint32_t& hi, uint32_t& lo)
{
    __nv_bfloat16 h0 = __float2bfloat16(f0);
    __nv_bfloat16 h1 = __float2bfloat16(f1);
    __nv_bfloat16 l0 = __float2bfloat16(f0 - __bfloat162float(h0));
    __nv_bfloat16 l1 = __float2bfloat16(f1 - __bfloat162float(h1));
    hi = (uint32_t)*(unsigned short*)&h0 | ((uint32_t)*(unsigned short*)&h1 << 16);
    lo = (uint32_t)*(unsigned short*)&l0 | ((uint32_t)*(unsigned short*)&l1 << 16);
}

// ---------------------------------------------------------------------------
// Conversion kernels
// ---------------------------------------------------------------------------
__global__ __launch_bounds__(256) void split_kernel(
    const float* __restrict__ in, __nv_bfloat16* __restrict__ hi,
    __nv_bfloat16* __restrict__ lo, int n4)
{
    int i = blockIdx.x * 256 + threadIdx.x;
    if (i >= n4) return;
    float4 v = ((const float4*)in)[i];
    __nv_bfloat16 h0 = __float2bfloat16(v.x);
    __nv_bfloat16 h1 = __float2bfloat16(v.y);
    __nv_bfloat16 h2 = __float2bfloat16(v.z);
    __nv_bfloat16 h3 = __float2bfloat16(v.w);
    __nv_bfloat16 l0 = __float2bfloat16(v.x - __bfloat162float(h0));
    __nv_bfloat16 l1 = __float2bfloat16(v.y - __bfloat162float(h1));
    __nv_bfloat16 l2 = __float2bfloat16(v.z - __bfloat162float(h2));
    __nv_bfloat16 l3 = __float2bfloat16(v.w - __bfloat162float(h3));
    ushort4 hp, lp;
    hp.x = *(unsigned short*)&h0; hp.y = *(unsigned short*)&h1;
    hp.z = *(unsigned short*)&h2; hp.w = *(unsigned short*)&h3;
    lp.x = *(unsigned short*)&l0; lp.y = *(unsigned short*)&l1;
    lp.z = *(unsigned short*)&l2; lp.w = *(unsigned short*)&l3;
    ((ushort4*)hi)[i] = hp;
    ((ushort4*)lo)[i] = lp;
}

__global__ __launch_bounds__(256) void transpose_split_kernel(
    const float* __restrict__ W, __nv_bfloat16* __restrict__ Thi,
    __nv_bfloat16* __restrict__ Tlo, int K, int N)
{
    __shared__ float t[32][33];
    const int n0 = blockIdx.x * 32;
    const int k0 = blockIdx.y * 32;
    const int tx = threadIdx.x & 31;
    const int ty = threadIdx.x >> 5;
    for (int j = ty; j < 32; j += 8)
        t[j][tx] = W[(size_t)(k0 + j) * N + n0 + tx];
    __syncthreads();
    for (int j = ty; j < 32; j += 8) {
        float v = t[tx][j];
        __nv_bfloat16 h = __float2bfloat16(v);
        __nv_bfloat16 l = __float2bfloat16(v - __bfloat162float(h));
        Thi[(size_t)(n0 + j) * K + k0 + tx] = h;
        Tlo[(size_t)(n0 + j) * K + k0 + tx] = l;
    }
}

// ---------------------------------------------------------------------------
// Shared GEMM mainloop config (128x128 block, 8 warps 64x32, K-chunk 32)
// Distance-2 cp.async prefetch: two buffers, wait_group 1.
// ---------------------------------------------------------------------------
#define TBM 128
#define TBN 128
#define TBK 32
#define ROW_B    80u
#define T_BYTES  10240u
#define BUF_BYTES (4u * T_BYTES)
#define GSMEM    (2 * BUF_BYTES)

__device__ __forceinline__ void stage_chunk(
    uint32_t sbase, const __nv_bfloat16* Ahi, const __nv_bfloat16* Alo,
    const __nv_bfloat16* Bhi, const __nv_bfloat16* Blo,
    int rowBase, int colBase, int K, int k0, int tid)
{
    const int quad = tid & 3;
    const int r0   = tid >> 2;
#pragma unroll
    for (int p = 0; p < 2; p++) {
        const int row = r0 + p * 64;
        const uint32_t d = (uint32_t)row * ROW_B + quad * 16;
        const size_t ga = (size_t)(rowBase + row) * K + k0 + quad * 8;
        const size_t gb = (size_t)(colBase + row) * K + k0 + quad * 8;
        cpasync16(sbase + d,               Ahi + ga);
        cpasync16(sbase + T_BYTES + d,     Alo + ga);
        cpasync16(sbase + 2 * T_BYTES + d, Bhi + gb);
        cpasync16(sbase + 3 * T_BYTES + d, Blo + gb);
    }
    asm volatile("cp.async.commit_group;" ::: "memory");
}

// Mainloop with prefetch distance 2
#define GEMM_MAINLOOP(ACC)                                                    \
    const int nchunks = K / TBK;                                              \
    stage_chunk(sbase, Ahi, Alo, Bhi, Blo, rowBase, colBase, K, 0, tid);      \
    if (nchunks > 1)                                                          \
        stage_chunk(sbase + BUF_BYTES, Ahi, Alo, Bhi, Blo, rowBase, colBase,  \
                    K, TBK, tid);                                             \
    for (int ch = 0; ch < nchunks; ch++) {                                    \
        if (ch + 1 < nchunks) {                                               \
            asm volatile("cp.async.wait_group 1;" ::: "memory");              \
        } else {                                                              \
            asm volatile("cp.async.wait_group 0;" ::: "memory");              \
        }                                                                     \
        __syncthreads();                                                      \
        const uint32_t cb = sbase + (ch & 1) * BUF_BYTES;                     \
        _Pragma("unroll")                                                     \
        for (int ks = 0; ks < 2; ks++) {                                      \
            uint32_t ahi[4][4], alo[4][4], bhi[4][2], blo[4][2];              \
            _Pragma("unroll")                                                 \
            for (int mt = 0; mt < 4; mt++) {                                  \
                const uint32_t addr = cb                                      \
                    + (uint32_t)(warp_m * 64 + mt * 16 + (lane & 15)) * ROW_B \
                    + ks * 32 + (lane >> 4) * 16;                             \
                ldm_x4(ahi[mt], addr);                                        \
                ldm_x4(alo[mt], addr + T_BYTES);                              \
            }                                                                 \
            _Pragma("unroll")                                                 \
            for (int pr = 0; pr < 2; pr++) {                                  \
                uint32_t tmp[4];                                              \
                const uint32_t addr = cb + 2 * T_BYTES                        \
                    + (uint32_t)(warp_n * 32 + pr * 16 + (lane >> 4) * 8      \
                                 + (lane & 7)) * ROW_B                        \
                    + ks * 32 + ((lane >> 3) & 1) * 16;                       \
                ldm_x4(tmp, addr);                                            \
                bhi[pr * 2 + 0][0] = tmp[0]; bhi[pr * 2 + 0][1] = tmp[1];     \
                bhi[pr * 2 + 1][0] = tmp[2]; bhi[pr * 2 + 1][1] = tmp[3];     \
                ldm_x4(tmp, addr + T_BYTES);                                  \
                blo[pr * 2 + 0][0] = tmp[0]; blo[pr * 2 + 0][1] = tmp[1];     \
                blo[pr * 2 + 1][0] = tmp[2]; blo[pr * 2 + 1][1] = tmp[3];     \
            }                                                                 \
            _Pragma("unroll")                                                 \
            for (int mt = 0; mt < 4; mt++)                                    \
                _Pragma("unroll")                                             \
                for (int nt = 0; nt < 4; nt++) {                              \
                    mma_bf16(ACC[mt][nt], ahi[mt], bhi[nt]);                  \
                    mma_bf16(ACC[mt][nt], ahi[mt], blo[nt]);                  \
                    mma_bf16(ACC[mt][nt], alo[mt], bhi[nt]);                  \
                }                                                             \
        }                                                                     \
        if (ch + 2 < nchunks) {                                               \
            __syncthreads();                                                  \
            stage_chunk(sbase + (ch & 1) * BUF_BYTES, Ahi, Alo, Bhi, Blo,     \
                        rowBase, colBase, K, (ch + 2) * TBK, tid);            \
        }                                                                     \
    }

// ---------------------------------------------------------------------------
// QKV GEMM -> head-major bf16 hi/lo splits
// ---------------------------------------------------------------------------
__global__ __launch_bounds__(256, 2) void gemm_qkv_kernel(
    const __nv_bfloat16* __restrict__ Ahi, const __nv_bfloat16* __restrict__ Alo,
    const __nv_bfloat16* __restrict__ Bhi, const __nv_bfloat16* __restrict__ Blo,
    const float* __restrict__ bias,
    __nv_bfloat16* __restrict__ qhi, __nv_bfloat16* __restrict__ qlo,
    __nv_bfloat16* __restrict__ khi, __nv_bfloat16* __restrict__ klo,
    __nv_bfloat16* __restrict__ vhi, __nv_bfloat16* __restrict__ vlo,
    int K)
{
    extern __shared__ __align__(128) char smem[];
    const uint32_t sbase = smem_u32(smem);
    const int tid    = threadIdx.x;
    const int lane   = tid & 31;
    const int wid    = tid >> 5;
    const int warp_m = wid >> 2;
    const int warp_n = wid & 3;
    const int rowBase = blockIdx.y * TBM;
    const int colBase = blockIdx.x * TBN;

    float acc[4][4][4];
#pragma unroll
    for (int i = 0; i < 4; i++)
#pragma unroll
        for (int j = 0; j < 4; j++)
#pragma unroll
            for (int k = 0; k < 4; k++) acc[i][j][k] = 0.f;

    GEMM_MAINLOOP(acc)

    // epilogue: split + scatter to head-major layout
    const int region = colBase >> 10;          // 0=q,1=k,2=v
    __nv_bfloat16* dsthi = (region == 0) ? qhi : ((region == 1) ? khi : vhi);
    __nv_bfloat16* dstlo = (region == 0) ? qlo : ((region == 1) ? klo : vlo);
    const int b  = rowBase >> 10;
    const int tr = lane >> 2;
    const int tc = (lane & 3) * 2;
#pragma unroll
    for (int mt = 0; mt < 4; mt++) {
        const int t0 = (rowBase & 1023) + warp_m * 64 + mt * 16 + tr;
#pragma unroll
        for (int nt = 0; nt < 4; nt++) {
            const int c = colBase + warp_n * 32 + nt * 8 + tc;
            const int head = (c & 1023) >> 6;
            const int dk   = c & 63;
            const float b0 = bias[c], b1 = bias[c + 1];
            const size_t rowb = (size_t)(b * 16 + head) * Tc;
            split_store2(dsthi, dstlo, (rowb + t0) * 64 + dk,
                         acc[mt][nt][0] + b0, acc[mt][nt][1] + b1);
            split_store2(dsthi, dstlo, (rowb + t0 + 8) * 64 + dk,
                         acc[mt][nt][2] + b0, acc[mt][nt][3] + b1);
        }
    }
}

// ---------------------------------------------------------------------------
// Output projection GEMM (fp32 out + bias)
// ---------------------------------------------------------------------------
__global__ __launch_bounds__(256, 2) void gemm_mma_split_kernel(
    const __nv_bfloat16* __restrict__ Ahi, const __nv_bfloat16* __restrict__ Alo,
    const __nv_bfloat16* __restrict__ Bhi, const __nv_bfloat16* __restrict__ Blo,
    const float* __restrict__ bias, float* __restrict__ C, int N, int K)
{
    extern __shared__ __align__(128) char smem[];
    const uint32_t sbase = smem_u32(smem);
    const int tid    = threadIdx.x;
    const int lane   = tid & 31;
    const int wid    = tid >> 5;
    const int warp_m = wid >> 2;
    const int warp_n = wid & 3;
    const int rowBase = blockIdx.y * TBM;
    const int colBase = blockIdx.x * TBN;

    float acc[4][4][4];
#pragma unroll
    for (int i = 0; i < 4; i++)
#pragma unroll
        for (int j = 0; j < 4; j++)
#pragma unroll
            for (int k = 0; k < 4; k++) acc[i][j][k] = 0.f;

    GEMM_MAINLOOP(acc)

    const int tr = lane >> 2;
    const int tc = (lane & 3) * 2;
#pragma unroll
    for (int mt = 0; mt < 4; mt++) {
        const int r0 = rowBase + warp_m * 64 + mt * 16 + tr;
#pragma unroll
        for (int nt = 0; nt < 4; nt++) {
            const int c = colBase + warp_n * 32 + nt * 8 + tc;
            const float b0 = bias[c], b1 = bias[c + 1];
            float2 v0, v1;
            v0.x = acc[mt][nt][0] + b0; v0.y = acc[mt][nt][1] + b1;
            v1.x = acc[mt][nt][2] + b0; v1.y = acc[mt][nt][3] + b1;
            *(float2*)(C + (size_t)r0 * N + c) = v0;
            *(float2*)(C + (size_t)(r0 + 8) * N + c) = v1;
        }
    }
}

// ---------------------------------------------------------------------------
// Scores via mma: S[bh][q][k] = (Q.K^T)/8 masked -> fp32 logits
// ---------------------------------------------------------------------------
#define SROW     144u
#define S_TILE   (128u * SROW)       // 18432
#define SM_SCORES (4u * S_TILE)      // 73728

__global__ __launch_bounds__(256) void scores_mma_kernel(
    const __nv_bfloat16* __restrict__ qhi, const __nv_bfloat16* __restrict__ qlo,
    const __nv_bfloat16* __restrict__ khi, const __nv_bfloat16* __restrict__ klo,
    const int* __restrict__ mask, float* __restrict__ logits)
{
    extern __shared__ __align__(128) char smem[];
    const uint32_t sbase = smem_u32(smem);
    const int tid    = threadIdx.x;
    const int lane   = tid & 31;
    const int wid    = tid >> 5;
    const int warp_m = wid >> 2;
    const int warp_n = wid & 3;

    const int k0 = blockIdx.x * 128;
    const int q0 = blockIdx.y * 128;
    const int bh = blockIdx.z;
    const int b  = bh >> 4;

    for (int i = tid; i < 1024; i += 256) {
        const int row = i >> 3;
        const int seg = i & 7;
        const uint32_t d = (uint32_t)row * SROW + seg * 16;
        const size_t gq = ((size_t)bh * Tc + q0 + row) * 64 + seg * 8;
        const size_t gk = ((size_t)bh * Tc + k0 + row) * 64 + seg * 8;
        cpasync16(sbase + d,              qhi + gq);
        cpasync16(sbase + S_TILE + d,     qlo + gq);
        cpasync16(sbase + 2 * S_TILE + d, khi + gk);
        cpasync16(sbase + 3 * S_TILE + d, klo + gk);
    }
    asm volatile("cp.async.commit_group;" ::: "memory");
    asm volatile("cp.async.wait_group 0;" ::: "memory");
    __syncthreads();

    float acc[4][4][4];
#pragma unroll
    for (int i = 0; i < 4; i++)
#pragma unroll
        for (int j = 0; j < 4; j++)
#pragma unroll
            for (int k = 0; k < 4; k++) acc[i][j][k] = 0.f;

#pragma unroll
    for (int ks = 0; ks < 4; ks++) {
        uint32_t ahi[4][4], alo[4][4], bhi[4][2], blo[4][2];
#pragma unroll
        for (int mt = 0; mt < 4; mt++) {
            const uint32_t addr = sbase
                + (uint32_t)(warp_m * 64 + mt * 16 + (lane & 15)) * SROW
                + ks * 32 + (lane >> 4) * 16;
            ldm_x4(ahi[mt], addr);
            ldm_x4(alo[mt], addr + S_TILE);
        }
#pragma unroll
        for (int pr = 0; pr < 2; pr++) {
            uint32_t tmp[4];
            const uint32_t addr = sbase + 2 * S_TILE
                + (uint32_t)(warp_n * 32 + pr * 16 + (lane >> 4) * 8 + (lane & 7)) * SROW
                + ks * 32 + ((lane >> 3) & 1) * 16;
            ldm_x4(tmp, addr);
            bhi[pr * 2 + 0][0] = tmp[0]; bhi[pr * 2 + 0][1] = tmp[1];
            bhi[pr * 2 + 1][0] = tmp[2]; bhi[pr * 2 + 1][1] = tmp[3];
            ldm_x4(tmp, addr + S_TILE);
            blo[pr * 2 + 0][0] = tmp[0]; blo[pr * 2 + 0][1] = tmp[1];
            blo[pr * 2 + 1][0] = tmp[2]; blo[pr * 2 + 1][1] = tmp[3];
        }
#pragma unroll
        for (int mt = 0; mt < 4; mt++)
#pragma unroll
            for (int nt = 0; nt < 4; nt++) {
                mma_bf16(acc[mt][nt], ahi[mt], bhi[nt]);
                mma_bf16(acc[mt][nt], ahi[mt], blo[nt]);
                mma_bf16(acc[mt][nt], alo[mt], bhi[nt]);
            }
    }

    const float NEG_INF = __int_as_float(0xff800000);
    const int tr = lane >> 2;
    const int tc = (lane & 3) * 2;
#pragma unroll
    for (int mt = 0; mt < 4; mt++) {
        const int q = q0 + warp_m * 64 + mt * 16 + tr;
#pragma unroll
        for (int nt = 0; nt < 4; nt++) {
            const int c = k0 + warp_n * 32 + nt * 8 + tc;
            const int m0 = mask[b * Tc + c];
            const int m1 = mask[b * Tc + c + 1];
            float2 v0, v1;
            v0.x = m0 ? acc[mt][nt][0] * 0.125f : NEG_INF;
            v0.y = m1 ? acc[mt][nt][1] * 0.125f : NEG_INF;
            v1.x = m0 ? acc[mt][nt][2] * 0.125f : NEG_INF;
            v1.y = m1 ? acc[mt][nt][3] * 0.125f : NEG_INF;
            float* outp = logits + ((size_t)bh * Tc + q) * Tc + c;
            *(float2*)outp = v0;
            *(float2*)(outp + 8 * Tc) = v1;
        }
    }
}

// ---------------------------------------------------------------------------
// Softmax in place over last dim (1024). Shuffle reductions, 4 barriers.
// ---------------------------------------------------------------------------
__global__ __launch_bounds__(256) void softmax_kernel(float* __restrict__ w)
{
    __shared__ float warpred[8];
    __shared__ float bc;
    float* p = w + (size_t)blockIdx.x * 1024;
    const int tid  = threadIdx.x;
    const int lane = tid & 31;
    const int wid  = tid >> 5;

    float4 v = ((const float4*)p)[tid];
    float m = fmaxf(fmaxf(v.x, v.y), fmaxf(v.z, v.w));
#pragma unroll
    for (int o = 16; o > 0; o >>= 1)
        m = fmaxf(m, __shfl_xor_sync(0xffffffffu, m, o));
    if (lane == 0) warpred[wid] = m;
    __syncthreads();
    if (wid == 0) {
        float t = (lane < 8) ? warpred[lane] : -3.4e38f;
#pragma unroll
        for (int o = 4; o > 0; o >>= 1)
            t = fmaxf(t, __shfl_xor_sync(0xffffffffu, t, o));
        if (lane == 0) bc = t;
    }
    __syncthreads();
    m = bc;

    float4 e;
    e.x = __expf(v.x - m);
    e.y = __expf(v.y - m);
    e.z = __expf(v.z - m);
    e.w = __expf(v.w - m);
    float s = e.x + e.y + e.z + e.w;
#pragma unroll
    for (int o = 16; o > 0; o >>= 1)
        s += __shfl_xor_sync(0xffffffffu, s, o);
    if (lane == 0) warpred[wid] = s;
    __syncthreads();
    if (wid == 0) {
        float t = (lane < 8) ? warpred[lane] : 0.f;
#pragma unroll
        for (int o = 4; o > 0; o >>= 1)
            t += __shfl_xor_sync(0xffffffffu, t, o);
        if (lane == 0) bc = 1.0f / t;
    }
    __syncthreads();
    const float inv = bc;

    e.x *= inv; e.y *= inv; e.z *= inv; e.w *= inv;
    ((float4*)p)[tid] = e;
}

// ---------------------------------------------------------------------------
// ctx via mma: ctx[bh][q][dk] = W[bh][q][:] @ V[bh][:][dk]
// W read fp32 (softmax output), in-register split; V bf16 splits via
// ldmatrix.trans. Distance-2 prefetch.
// ---------------------------------------------------------------------------
#define CWF_STRIDE_F 72u                         // floats per smem row (64+8 pad)
#define CW_TILE_F  (128u * CWF_STRIDE_F * 4u)    // 36864 B
#define CV_TILE    (64u * SROW)                  // 9216 B
#define C_BUF      (CW_TILE_F + 2u * CV_TILE)    // 55296 B
#define SM_CTX     (2u * C_BUF)                  // 110592 B

__global__ __launch_bounds__(256) void ctx_mma_kernel(
    const float* __restrict__ w,                 // fp32 weights [bh][q][k]
    const __nv_bfloat16* __restrict__ vhi, const __nv_bfloat16* __restrict__ vlo,
    __nv_bfloat16* __restrict__ ctxhi, __nv_bfloat16* __restrict__ ctxlo)
{
    extern __shared__ __align__(128) char smem[];
    const uint32_t sbase = smem_u32(smem);
    const int tid  = threadIdx.x;
    const int lane = tid & 31;
    const int wid  = tid >> 5;            // warp tile: 16 q-rows x 64 dk

    const int q0 = blockIdx.x * 128;
    const int bh = blockIdx.y;
    const int b  = bh >> 4;
    const int h  = bh & 15;

    float acc[8][4];
#pragma unroll
    for (int i = 0; i < 8; i++)
#pragma unroll
        for (int j = 0; j < 4; j++) acc[i][j] = 0.f;

    auto stage = [&](uint32_t sb, int k0) {
        for (int i = tid; i < 2048; i += 256) {
            const int row = i >> 4;
            const int seg = i & 15;
            const uint32_t d = (uint32_t)row * (CWF_STRIDE_F * 4) + seg * 16;
            const size_t g = ((size_t)bh * Tc + q0 + row) * Tc + k0 + seg * 4;
            cpasync16(sb + d, w + g);
        }
        for (int i = tid; i < 512; i += 256) {
            const int row = i >> 3;
            const int seg = i & 7;
            const uint32_t d = (uint32_t)row * SROW + seg * 16;
            const size_t g = ((size_t)bh * Tc + k0 + row) * 64 + seg * 8;
            cpasync16(sb + CW_TILE_F + d,           vhi + g);
            cpasync16(sb + CW_TILE_F + CV_TILE + d, vlo + g);
        }
        asm volatile("cp.async.commit_group;" ::: "memory");
    };

    const int tr = lane >> 2;
    const int tc = (lane & 3) * 2;

    stage(sbase, 0);
    stage(sbase + C_BUF, 64);
    for (int ch = 0; ch < 16; ch++) {
        if (ch + 1 < 16) {
            asm volatile("cp.async.wait_group 1;" ::: "memory");
        } else {
            asm volatile("cp.async.wait_group 0;" ::: "memory");
        }
        __syncthreads();

        const uint32_t cb = sbase + (ch & 1) * C_BUF;
        const float* wsm = (const float*)(smem + (ch & 1) * C_BUF);
#pragma unroll
        for (int ks = 0; ks < 4; ks++) {
            uint32_t ahi[4], alo[4], bhi[8][2], blo[8][2];
            {
                const uint32_t r0off = (uint32_t)(wid * 16 + tr) * CWF_STRIDE_F
                                       + ks * 16 + tc;
                float2 f00 = *(const float2*)(wsm + r0off);
                float2 f10 = *(const float2*)(wsm + r0off + 8 * CWF_STRIDE_F);
                float2 f01 = *(const float2*)(wsm + r0off + 8);
                float2 f11 = *(const float2*)(wsm + r0off + 8 * CWF_STRIDE_F + 8);
                split_pack2(f00.x, f00.y, ahi[0], alo[0]);
                split_pack2(f10.x, f10.y, ahi[1], alo[1]);
                split_pack2(f01.x, f01.y, ahi[2], alo[2]);
                split_pack2(f11.x, f11.y, ahi[3], alo[3]);
            }
#pragma unroll
            for (int nc = 0; nc < 4; nc++) {
                uint32_t tmp[4];
                const uint32_t addr = cb + CW_TILE_F
                    + (uint32_t)(ks * 16 + (lane & 7) + ((lane >> 3) & 1) * 8) * SROW
                    + nc * 32 + (lane >> 4) * 16;
                ldm_x4_trans(tmp, addr);
                bhi[nc * 2 + 0][0] = tmp[0]; bhi[nc * 2 + 0][1] = tmp[1];
                bhi[nc * 2 + 1][0] = tmp[2]; bhi[nc * 2 + 1][1] = tmp[3];
                ldm_x4_trans(tmp, addr + CV_TILE);
                blo[nc * 2 + 0][0] = tmp[0]; blo[nc * 2 + 0][1] = tmp[1];
                blo[nc * 2 + 1][0] = tmp[2]; blo[nc * 2 + 1][1] = tmp[3];
            }
#pragma unroll
            for (int nt = 0; nt < 8; nt++) {
                mma_bf16(acc[nt], ahi, bhi[nt]);
                mma_bf16(acc[nt], ahi, blo[nt]);
                mma_bf16(acc[nt], alo, bhi[nt]);
            }
        }

        if (ch + 2 < 16) {
            __syncthreads();
            stage(sbase + (ch & 1) * C_BUF, (ch + 2) * 64);
        }
    }

    // epilogue: split-store ctx in [b*T+t][D] layout
    const int t0 = q0 + wid * 16 + tr;
#pragma unroll
    for (int nt = 0; nt < 8; nt++) {
        const int dk = nt * 8 + tc;
        const size_t i0 = ((size_t)(b * Tc + t0)) * Dc + h * 64 + dk;
        const size_t i1 = ((size_t)(b * Tc + t0 + 8)) * Dc + h * 64 + dk;
        split_store2(ctxhi, ctxlo, i0, acc[nt][0], acc[nt][1]);
        split_store2(ctxhi, ctxlo, i1, acc[nt][2], acc[nt][3]);
    }
}

// ---------------------------------------------------------------------------
extern "C" void kernel_launch(void* const* d_in, const int* in_sizes, int n_in,
                              void* d_out, int out_size)
{
    const float* x    = (const float*)d_in[0];
    const int*   mask = (const int*)d_in[1];      // jax bool -> int32
    const float* Wqkv = (const float*)d_in[2];
    const float* bqkv = (const float*)d_in[3];
    const float* Wo   = (const float*)d_in[4];
    const float* bo   = (const float*)d_in[5];

    float* out     = (float*)d_out;
    float* weights = out + (size_t)Bc * Tc * Dc;

    __nv_bfloat16 *xhi, *xlo, *wqhi, *wqlo, *wohi, *wolo;
    __nv_bfloat16 *qhi, *qlo, *khi, *klo, *vhi, *vlo, *ctxhi, *ctxlo;
    cudaGetSymbolAddress((void**)&xhi, g_xhi);
    cudaGetSymbolAddress((void**)&xlo, g_xlo);
    cudaGetSymbolAddress((void**)&wqhi, g_wqkvthi);
    cudaGetSymbolAddress((void**)&wqlo, g_wqkvtlo);
    cudaGetSymbolAddress((void**)&wohi, g_wothi);
    cudaGetSymbolAddress((void**)&wolo, g_wotlo);
    cudaGetSymbolAddress((void**)&qhi, g_qhi);
    cudaGetSymbolAddress((void**)&qlo, g_qlo);
    cudaGetSymbolAddress((void**)&khi, g_khi);
    cudaGetSymbolAddress((void**)&klo, g_klo);
    cudaGetSymbolAddress((void**)&vhi, g_vhi);
    cudaGetSymbolAddress((void**)&vlo, g_vlo);
    cudaGetSymbolAddress((void**)&ctxhi, g_ctxhi);
    cudaGetSymbolAddress((void**)&ctxlo, g_ctxlo);

    static int attr_set = 0;
    if (!attr_set) {
        cudaFuncSetAttribute(gemm_qkv_kernel,
                             cudaFuncAttributeMaxDynamicSharedMemorySize, GSMEM);
        cudaFuncSetAttribute(gemm_mma_split_kernel,
                             cudaFuncAttributeMaxDynamicSharedMemorySize, GSMEM);
        cudaFuncSetAttribute(scores_mma_kernel,
                             cudaFuncAttributeMaxDynamicSharedMemorySize, SM_SCORES);
        cudaFuncSetAttribute(ctx_mma_kernel,
                             cudaFuncAttributeMaxDynamicSharedMemorySize, SM_CTX);
        attr_set = 1;
    }

    const int nx4 = (Bc * Tc * Dc) / 4;

    // 0) input splits / weight transposes
    split_kernel<<<(nx4 + 255) / 256, 256>>>(x, xhi, xlo, nx4);
    transpose_split_kernel<<<dim3(D3c / 32, Dc / 32), 256>>>(Wqkv, wqhi, wqlo, Dc, D3c);
    transpose_split_kernel<<<dim3(Dc / 32, Dc / 32), 256>>>(Wo, wohi, wolo, Dc, Dc);

    // 1) QKV projection -> head-major bf16 splits
    gemm_qkv_kernel<<<dim3(D3c / TBN, (Bc * Tc) / TBM), 256, GSMEM>>>(
        xhi, xlo, wqhi, wqlo, bqkv, qhi, qlo, khi, klo, vhi, vlo, Dc);

    // 2) scores on tensor cores -> masked scaled fp32 logits
    scores_mma_kernel<<<dim3(Tc / 128, Tc / 128, Bc * NHc), 256, SM_SCORES>>>(
        qhi, qlo, khi, klo, mask, weights);

    // 3) softmax in place (fp32 weights only — the mandatory output)
    softmax_kernel<<<Bc * NHc * Tc, 256>>>(weights);

    // 4) ctx on tensor cores, consuming fp32 weights directly
    ctx_mma_kernel<<<dim3(Tc / 128, Bc * NHc), 256, SM_CTX>>>(
        weights, vhi, vlo, ctxhi, ctxlo);

    // 5) output projection
    gemm_mma_split_kernel<<<dim3(Dc / TBN, (Bc * Tc) / TBM), 256, GSMEM>>>(
        ctxhi, ctxlo, wohi, wolo, bo, out, Dc, Dc);
}

// round 14
// speedup vs baseline: 2.6568x; 1.1142x over previous
#include <cuda_runtime.h>
#include <cuda_bf16.h>
#include <cstdint>

// Problem constants
#define Bc   8
#define Tc   1024
#define Dc   1024
#define NHc  16
#define DKc  64
#define D3c  3072

// ---------------------------------------------------------------------------
// Scratch (device globals — allocation-free rule)
// ---------------------------------------------------------------------------
__device__ __nv_bfloat16 g_xhi[(size_t)Bc * Tc * Dc];
__device__ __nv_bfloat16 g_xlo[(size_t)Bc * Tc * Dc];
__device__ __nv_bfloat16 g_wqkvthi[(size_t)D3c * Dc];   // Wqkv^T [N=3072][K=1024]
__device__ __nv_bfloat16 g_wqkvtlo[(size_t)D3c * Dc];
__device__ __nv_bfloat16 g_wothi[(size_t)Dc * Dc];      // Wo^T [N=1024][K=1024]
__device__ __nv_bfloat16 g_wotlo[(size_t)Dc * Dc];
// head-major splits produced by QKV epilogue: [bh][t][64]
__device__ __nv_bfloat16 g_qhi[(size_t)128 * Tc * DKc];
__device__ __nv_bfloat16 g_qlo[(size_t)128 * Tc * DKc];
__device__ __nv_bfloat16 g_khi[(size_t)128 * Tc * DKc];
__device__ __nv_bfloat16 g_klo[(size_t)128 * Tc * DKc];
__device__ __nv_bfloat16 g_vhi[(size_t)128 * Tc * DKc];
__device__ __nv_bfloat16 g_vlo[(size_t)128 * Tc * DKc];
// ctx splits: [b*T+t][D]
__device__ __nv_bfloat16 g_ctxhi[(size_t)Bc * Tc * Dc];
__device__ __nv_bfloat16 g_ctxlo[(size_t)Bc * Tc * Dc];
// softmax stats: partial per k-tile (m, sumexp); reduced (m, 1/sum)
__device__ float2 g_stats1[(size_t)128 * 8 * Tc];   // [bh][ktile][q]
__device__ float2 g_stats2[(size_t)128 * Tc];       // [bh][q]

// ---------------------------------------------------------------------------
// sm_80-era primitives (legal on plain sm_103 target)
// ---------------------------------------------------------------------------
__device__ __forceinline__ uint32_t smem_u32(const void* p) {
    uint32_t a;
    asm("{ .reg .u64 t; cvta.to.shared.u64 t, %1; cvt.u32.u64 %0, t; }"
        : "=r"(a) : "l"(p));
    return a;
}
__device__ __forceinline__ void cpasync16(uint32_t dst_smem, const void* src) {
    asm volatile("cp.async.cg.shared.global [%0], [%1], 16;"
                 :: "r"(dst_smem), "l"(src));
}
__device__ __forceinline__ void ldm_x4(uint32_t* r, uint32_t addr) {
    asm volatile("ldmatrix.sync.aligned.m8n8.x4.shared.b16 {%0,%1,%2,%3}, [%4];"
                 : "=r"(r[0]), "=r"(r[1]), "=r"(r[2]), "=r"(r[3]) : "r"(addr));
}
__device__ __forceinline__ void ldm_x4_trans(uint32_t* r, uint32_t addr) {
    asm volatile("ldmatrix.sync.aligned.m8n8.x4.trans.shared.b16 {%0,%1,%2,%3}, [%4];"
                 : "=r"(r[0]), "=r"(r[1]), "=r"(r[2]), "=r"(r[3]) : "r"(addr));
}
__device__ __forceinline__ void mma_bf16(float* d, const uint32_t* a, const uint32_t* b) {
    asm volatile(
        "mma.sync.aligned.m16n8k16.row.col.f32.bf16.bf16.f32 "
        "{%0,%1,%2,%3}, {%4,%5,%6,%7}, {%8,%9}, {%0,%1,%2,%3};"
        : "+f"(d[0]), "+f"(d[1]), "+f"(d[2]), "+f"(d[3])
        : "r"(a[0]), "r"(a[1]), "r"(a[2]), "r"(a[3]), "r"(b[0]), "r"(b[1]));
}

__device__ __forceinline__ void split_store2(
    __nv_bfloat16* hi, __nv_bfloat16* lo, size_t idx, float f0, float f1)
{
    __nv_bfloat16 h0 = __float2bfloat16(f0);
    __nv_bfloat16 h1 = __float2bfloat16(f1);
    __nv_bfloat16 l0 = __float2bfloat16(f0 - __bfloat162float(h0));
    __nv_bfloat16 l1 = __float2bfloat16(f1 - __bfloat162float(h1));
    ushort2 hp, lp;
    hp.x = *(unsigned short*)&h0; hp.y = *(unsigned short*)&h1;
    lp.x = *(unsigned short*)&l0; lp.y = *(unsigned short*)&l1;
    *(ushort2*)(hi + idx) = hp;
    *(ushort2*)(lo + idx) = lp;
}

// pack two floats -> bf16x2 hi reg + bf16x2 lo reg (split)
__device__ __forceinline__ void split_pack2(float f0, float f1,
                                            uint32_t& hi, uint32_t& lo)
{
    __nv_bfloat16 h0 = __float2bfloat16(f0);
    __nv_bfloat16 h1 = __float2bfloat16(f1);
    __nv_bfloat16 l0 = __float2bfloat16(f0 - __bfloat162float(h0));
    __nv_bfloat16 l1 = __float2bfloat16(f1 - __bfloat162float(h1));
    hi = (uint32_t)*(unsigned short*)&h0 | ((uint32_t)*(unsigned short*)&h1 << 16);
    lo = (uint32_t)*(unsigned short*)&l0 | ((uint32_t)*(unsigned short*)&l1 << 16);
}

// ---------------------------------------------------------------------------
// Conversion kernels
// ---------------------------------------------------------------------------
__global__ __launch_bounds__(256) void split_kernel(
    const float* __restrict__ in, __nv_bfloat16* __restrict__ hi,
    __nv_bfloat16* __restrict__ lo, int n4)
{
    int i = blockIdx.x * 256 + threadIdx.x;
    if (i >= n4) return;
    float4 v = ((const float4*)in)[i];
    __nv_bfloat16 h0 = __float2bfloat16(v.x);
    __nv_bfloat16 h1 = __float2bfloat16(v.y);
    __nv_bfloat16 h2 = __float2bfloat16(v.z);
    __nv_bfloat16 h3 = __float2bfloat16(v.w);
    __nv_bfloat16 l0 = __float2bfloat16(v.x - __bfloat162float(h0));
    __nv_bfloat16 l1 = __float2bfloat16(v.y - __bfloat162float(h1));
    __nv_bfloat16 l2 = __float2bfloat16(v.z - __bfloat162float(h2));
    __nv_bfloat16 l3 = __float2bfloat16(v.w - __bfloat162float(h3));
    ushort4 hp, lp;
    hp.x = *(unsigned short*)&h0; hp.y = *(unsigned short*)&h1;
    hp.z = *(unsigned short*)&h2; hp.w = *(unsigned short*)&h3;
    lp.x = *(unsigned short*)&l0; lp.y = *(unsigned short*)&l1;
    lp.z = *(unsigned short*)&l2; lp.w = *(unsigned short*)&l3;
    ((ushort4*)hi)[i] = hp;
    ((ushort4*)lo)[i] = lp;
}

__global__ __launch_bounds__(256) void transpose_split_kernel(
    const float* __restrict__ W, __nv_bfloat16* __restrict__ Thi,
    __nv_bfloat16* __restrict__ Tlo, int K, int N)
{
    __shared__ float t[32][33];
    const int n0 = blockIdx.x * 32;
    const int k0 = blockIdx.y * 32;
    const int tx = threadIdx.x & 31;
    const int ty = threadIdx.x >> 5;
    for (int j = ty; j < 32; j += 8)
        t[j][tx] = W[(size_t)(k0 + j) * N + n0 + tx];
    __syncthreads();
    for (int j = ty; j < 32; j += 8) {
        float v = t[tx][j];
        __nv_bfloat16 h = __float2bfloat16(v);
        __nv_bfloat16 l = __float2bfloat16(v - __bfloat162float(h));
        Thi[(size_t)(n0 + j) * K + k0 + tx] = h;
        Tlo[(size_t)(n0 + j) * K + k0 + tx] = l;
    }
}

// ---------------------------------------------------------------------------
// Shared GEMM mainloop config (128x128 block, 8 warps 64x32, K-chunk 32)
// Round-11 schedule (measured fastest): stage next chunk right after wait.
// ---------------------------------------------------------------------------
#define TBM 128
#define TBN 128
#define TBK 32
#define ROW_B    80u
#define T_BYTES  10240u
#define BUF_BYTES (4u * T_BYTES)
#define GSMEM    (2 * BUF_BYTES)

__device__ __forceinline__ void stage_chunk(
    uint32_t sbase, const __nv_bfloat16* Ahi, const __nv_bfloat16* Alo,
    const __nv_bfloat16* Bhi, const __nv_bfloat16* Blo,
    int rowBase, int colBase, int K, int k0, int tid)
{
    const int quad = tid & 3;
    const int r0   = tid >> 2;
#pragma unroll
    for (int p = 0; p < 2; p++) {
        const int row = r0 + p * 64;
        const uint32_t d = (uint32_t)row * ROW_B + quad * 16;
        const size_t ga = (size_t)(rowBase + row) * K + k0 + quad * 8;
        const size_t gb = (size_t)(colBase + row) * K + k0 + quad * 8;
        cpasync16(sbase + d,               Ahi + ga);
        cpasync16(sbase + T_BYTES + d,     Alo + ga);
        cpasync16(sbase + 2 * T_BYTES + d, Bhi + gb);
        cpasync16(sbase + 3 * T_BYTES + d, Blo + gb);
    }
    asm volatile("cp.async.commit_group;" ::: "memory");
}

#define GEMM_MAINLOOP(ACC)                                                    \
    const int nchunks = K / TBK;                                              \
    stage_chunk(sbase, Ahi, Alo, Bhi, Blo, rowBase, colBase, K, 0, tid);      \
    for (int ch = 0; ch < nchunks; ch++) {                                    \
        asm volatile("cp.async.wait_group 0;" ::: "memory");                  \
        __syncthreads();                                                      \
        if (ch + 1 < nchunks)                                                 \
            stage_chunk(sbase + ((ch + 1) & 1) * BUF_BYTES, Ahi, Alo, Bhi,    \
                        Blo, rowBase, colBase, K, (ch + 1) * TBK, tid);       \
        const uint32_t cb = sbase + (ch & 1) * BUF_BYTES;                     \
        _Pragma("unroll")                                                     \
        for (int ks = 0; ks < 2; ks++) {                                      \
            uint32_t ahi[4][4], alo[4][4], bhi[4][2], blo[4][2];              \
            _Pragma("unroll")                                                 \
            for (int mt = 0; mt < 4; mt++) {                                  \
                const uint32_t addr = cb                                      \
                    + (uint32_t)(warp_m * 64 + mt * 16 + (lane & 15)) * ROW_B \
                    + ks * 32 + (lane >> 4) * 16;                             \
                ldm_x4(ahi[mt], addr);                                        \
                ldm_x4(alo[mt], addr + T_BYTES);                              \
            }                                                                 \
            _Pragma("unroll")                                                 \
            for (int pr = 0; pr < 2; pr++) {                                  \
                uint32_t tmp[4];                                              \
                const uint32_t addr = cb + 2 * T_BYTES                        \
                    + (uint32_t)(warp_n * 32 + pr * 16 + (lane >> 4) * 8      \
                                 + (lane & 7)) * ROW_B                        \
                    + ks * 32 + ((lane >> 3) & 1) * 16;                       \
                ldm_x4(tmp, addr);                                            \
                bhi[pr * 2 + 0][0] = tmp[0]; bhi[pr * 2 + 0][1] = tmp[1];     \
                bhi[pr * 2 + 1][0] = tmp[2]; bhi[pr * 2 + 1][1] = tmp[3];     \
                ldm_x4(tmp, addr + T_BYTES);                                  \
                blo[pr * 2 + 0][0] = tmp[0]; blo[pr * 2 + 0][1] = tmp[1];     \
                blo[pr * 2 + 1][0] = tmp[2]; blo[pr * 2 + 1][1] = tmp[3];     \
            }                                                                 \
            _Pragma("unroll")                                                 \
            for (int mt = 0; mt < 4; mt++)                                    \
                _Pragma("unroll")                                             \
                for (int nt = 0; nt < 4; nt++) {                              \
                    mma_bf16(ACC[mt][nt], ahi[mt], bhi[nt]);                  \
                    mma_bf16(ACC[mt][nt], ahi[mt], blo[nt]);                  \
                    mma_bf16(ACC[mt][nt], alo[mt], bhi[nt]);                  \
                }                                                             \
        }                                                                     \
    }

// ---------------------------------------------------------------------------
// QKV GEMM -> head-major bf16 hi/lo splits
// ---------------------------------------------------------------------------
__global__ __launch_bounds__(256, 2) void gemm_qkv_kernel(
    const __nv_bfloat16* __restrict__ Ahi, const __nv_bfloat16* __restrict__ Alo,
    const __nv_bfloat16* __restrict__ Bhi, const __nv_bfloat16* __restrict__ Blo,
    const float* __restrict__ bias,
    __nv_bfloat16* __restrict__ qhi, __nv_bfloat16* __restrict__ qlo,
    __nv_bfloat16* __restrict__ khi, __nv_bfloat16* __restrict__ klo,
    __nv_bfloat16* __restrict__ vhi, __nv_bfloat16* __restrict__ vlo,
    int K)
{
    extern __shared__ __align__(128) char smem[];
    const uint32_t sbase = smem_u32(smem);
    const int tid    = threadIdx.x;
    const int lane   = tid & 31;
    const int wid    = tid >> 5;
    const int warp_m = wid >> 2;
    const int warp_n = wid & 3;
    const int rowBase = blockIdx.y * TBM;
    const int colBase = blockIdx.x * TBN;

    float acc[4][4][4];
#pragma unroll
    for (int i = 0; i < 4; i++)
#pragma unroll
        for (int j = 0; j < 4; j++)
#pragma unroll
            for (int k = 0; k < 4; k++) acc[i][j][k] = 0.f;

    GEMM_MAINLOOP(acc)

    // epilogue: split + scatter to head-major layout
    const int region = colBase >> 10;          // 0=q,1=k,2=v
    __nv_bfloat16* dsthi = (region == 0) ? qhi : ((region == 1) ? khi : vhi);
    __nv_bfloat16* dstlo = (region == 0) ? qlo : ((region == 1) ? klo : vlo);
    const int b  = rowBase >> 10;
    const int tr = lane >> 2;
    const int tc = (lane & 3) * 2;
#pragma unroll
    for (int mt = 0; mt < 4; mt++) {
        const int t0 = (rowBase & 1023) + warp_m * 64 + mt * 16 + tr;
#pragma unroll
        for (int nt = 0; nt < 4; nt++) {
            const int c = colBase + warp_n * 32 + nt * 8 + tc;
            const int head = (c & 1023) >> 6;
            const int dk   = c & 63;
            const float b0 = bias[c], b1 = bias[c + 1];
            const size_t rowb = (size_t)(b * 16 + head) * Tc;
            split_store2(dsthi, dstlo, (rowb + t0) * 64 + dk,
                         acc[mt][nt][0] + b0, acc[mt][nt][1] + b1);
            split_store2(dsthi, dstlo, (rowb + t0 + 8) * 64 + dk,
                         acc[mt][nt][2] + b0, acc[mt][nt][3] + b1);
        }
    }
}

// ---------------------------------------------------------------------------
// Output projection GEMM (fp32 out + bias)
// ---------------------------------------------------------------------------
__global__ __launch_bounds__(256, 2) void gemm_mma_split_kernel(
    const __nv_bfloat16* __restrict__ Ahi, const __nv_bfloat16* __restrict__ Alo,
    const __nv_bfloat16* __restrict__ Bhi, const __nv_bfloat16* __restrict__ Blo,
    const float* __restrict__ bias, float* __restrict__ C, int N, int K)
{
    extern __shared__ __align__(128) char smem[];
    const uint32_t sbase = smem_u32(smem);
    const int tid    = threadIdx.x;
    const int lane   = tid & 31;
    const int wid    = tid >> 5;
    const int warp_m = wid >> 2;
    const int warp_n = wid & 3;
    const int rowBase = blockIdx.y * TBM;
    const int colBase = blockIdx.x * TBN;

    float acc[4][4][4];
#pragma unroll
    for (int i = 0; i < 4; i++)
#pragma unroll
        for (int j = 0; j < 4; j++)
#pragma unroll
            for (int k = 0; k < 4; k++) acc[i][j][k] = 0.f;

    GEMM_MAINLOOP(acc)

    const int tr = lane >> 2;
    const int tc = (lane & 3) * 2;
#pragma unroll
    for (int mt = 0; mt < 4; mt++) {
        const int r0 = rowBase + warp_m * 64 + mt * 16 + tr;
#pragma unroll
        for (int nt = 0; nt < 4; nt++) {
            const int c = colBase + warp_n * 32 + nt * 8 + tc;
            const float b0 = bias[c], b1 = bias[c + 1];
            float2 v0, v1;
            v0.x = acc[mt][nt][0] + b0; v0.y = acc[mt][nt][1] + b1;
            v1.x = acc[mt][nt][2] + b0; v1.y = acc[mt][nt][3] + b1;
            *(float2*)(C + (size_t)r0 * N + c) = v0;
            *(float2*)(C + (size_t)(r0 + 8) * N + c) = v1;
        }
    }
}

// ---------------------------------------------------------------------------
// Scores via mma: raw masked scaled logits -> gmem, plus per-(row, ktile)
// partial softmax stats (max, sumexp) -> g_stats1.
// ---------------------------------------------------------------------------
#define SROW     144u
#define S_TILE   (128u * SROW)       // 18432
#define SM_SCORES (4u * S_TILE)      // 73728

__global__ __launch_bounds__(256) void scores_mma_kernel(
    const __nv_bfloat16* __restrict__ qhi, const __nv_bfloat16* __restrict__ qlo,
    const __nv_bfloat16* __restrict__ khi, const __nv_bfloat16* __restrict__ klo,
    const int* __restrict__ mask, float* __restrict__ logits,
    float2* __restrict__ stats1)
{
    extern __shared__ __align__(128) char smem[];
    const uint32_t sbase = smem_u32(smem);
    const int tid    = threadIdx.x;
    const int lane   = tid & 31;
    const int wid    = tid >> 5;
    const int warp_m = wid >> 2;
    const int warp_n = wid & 3;

    const int k0 = blockIdx.x * 128;
    const int q0 = blockIdx.y * 128;
    const int bh = blockIdx.z;
    const int b  = bh >> 4;

    for (int i = tid; i < 1024; i += 256) {
        const int row = i >> 3;
        const int seg = i & 7;
        const uint32_t d = (uint32_t)row * SROW + seg * 16;
        const size_t gq = ((size_t)bh * Tc + q0 + row) * 64 + seg * 8;
        const size_t gk = ((size_t)bh * Tc + k0 + row) * 64 + seg * 8;
        cpasync16(sbase + d,              qhi + gq);
        cpasync16(sbase + S_TILE + d,     qlo + gq);
        cpasync16(sbase + 2 * S_TILE + d, khi + gk);
        cpasync16(sbase + 3 * S_TILE + d, klo + gk);
    }
    asm volatile("cp.async.commit_group;" ::: "memory");
    asm volatile("cp.async.wait_group 0;" ::: "memory");
    __syncthreads();

    float acc[4][4][4];
#pragma unroll
    for (int i = 0; i < 4; i++)
#pragma unroll
        for (int j = 0; j < 4; j++)
#pragma unroll
            for (int k = 0; k < 4; k++) acc[i][j][k] = 0.f;

#pragma unroll
    for (int ks = 0; ks < 4; ks++) {
        uint32_t ahi[4][4], alo[4][4], bhi[4][2], blo[4][2];
#pragma unroll
        for (int mt = 0; mt < 4; mt++) {
            const uint32_t addr = sbase
                + (uint32_t)(warp_m * 64 + mt * 16 + (lane & 15)) * SROW
                + ks * 32 + (lane >> 4) * 16;
            ldm_x4(ahi[mt], addr);
            ldm_x4(alo[mt], addr + S_TILE);
        }
#pragma unroll
        for (int pr = 0; pr < 2; pr++) {
            uint32_t tmp[4];
            const uint32_t addr = sbase + 2 * S_TILE
                + (uint32_t)(warp_n * 32 + pr * 16 + (lane >> 4) * 8 + (lane & 7)) * SROW
                + ks * 32 + ((lane >> 3) & 1) * 16;
            ldm_x4(tmp, addr);
            bhi[pr * 2 + 0][0] = tmp[0]; bhi[pr * 2 + 0][1] = tmp[1];
            bhi[pr * 2 + 1][0] = tmp[2]; bhi[pr * 2 + 1][1] = tmp[3];
            ldm_x4(tmp, addr + S_TILE);
            blo[pr * 2 + 0][0] = tmp[0]; blo[pr * 2 + 0][1] = tmp[1];
            blo[pr * 2 + 1][0] = tmp[2]; blo[pr * 2 + 1][1] = tmp[3];
        }
#pragma unroll
        for (int mt = 0; mt < 4; mt++)
#pragma unroll
            for (int nt = 0; nt < 4; nt++) {
                mma_bf16(acc[mt][nt], ahi[mt], bhi[nt]);
                mma_bf16(acc[mt][nt], ahi[mt], blo[nt]);
                mma_bf16(acc[mt][nt], alo[mt], bhi[nt]);
            }
    }

    const float NEG_INF = __int_as_float(0xff800000);
    const int tr = lane >> 2;
    const int tc = (lane & 3) * 2;

    // mask + scale in place
    int mk[4][2];
#pragma unroll
    for (int nt = 0; nt < 4; nt++) {
        const int c = k0 + warp_n * 32 + nt * 8 + tc;
        mk[nt][0] = mask[b * Tc + c];
        mk[nt][1] = mask[b * Tc + c + 1];
    }
#pragma unroll
    for (int mt = 0; mt < 4; mt++)
#pragma unroll
        for (int nt = 0; nt < 4; nt++) {
            acc[mt][nt][0] = mk[nt][0] ? acc[mt][nt][0] * 0.125f : NEG_INF;
            acc[mt][nt][1] = mk[nt][1] ? acc[mt][nt][1] * 0.125f : NEG_INF;
            acc[mt][nt][2] = mk[nt][0] ? acc[mt][nt][2] * 0.125f : NEG_INF;
            acc[mt][nt][3] = mk[nt][1] ? acc[mt][nt][3] * 0.125f : NEG_INF;
        }

    // store raw logits
#pragma unroll
    for (int mt = 0; mt < 4; mt++) {
        const int q = q0 + warp_m * 64 + mt * 16 + tr;
#pragma unroll
        for (int nt = 0; nt < 4; nt++) {
            const int c = k0 + warp_n * 32 + nt * 8 + tc;
            float* outp = logits + ((size_t)bh * Tc + q) * Tc + c;
            *(float2*)outp = make_float2(acc[mt][nt][0], acc[mt][nt][1]);
            *(float2*)(outp + 8 * Tc) = make_float2(acc[mt][nt][2], acc[mt][nt][3]);
        }
    }

    // per-row partial max over this 128-col tile
    float rmax[4][2];
#pragma unroll
    for (int mt = 0; mt < 4; mt++) {
        float m0 = NEG_INF, m1 = NEG_INF;
#pragma unroll
        for (int nt = 0; nt < 4; nt++) {
            m0 = fmaxf(m0, fmaxf(acc[mt][nt][0], acc[mt][nt][1]));
            m1 = fmaxf(m1, fmaxf(acc[mt][nt][2], acc[mt][nt][3]));
        }
        rmax[mt][0] = m0; rmax[mt][1] = m1;
    }
#pragma unroll
    for (int o = 1; o <= 2; o <<= 1)
#pragma unroll
        for (int mt = 0; mt < 4; mt++) {
            rmax[mt][0] = fmaxf(rmax[mt][0], __shfl_xor_sync(0xffffffffu, rmax[mt][0], o));
            rmax[mt][1] = fmaxf(rmax[mt][1], __shfl_xor_sync(0xffffffffu, rmax[mt][1], o));
        }

    __syncthreads();                    // tiles no longer needed; reuse smem
    float* redm = (float*)smem;         // [128][4]
    float* rowm = (float*)smem + 512;   // [128]
    float* reds = (float*)smem + 1024;  // [128][4]
    if ((lane & 3) == 0) {
#pragma unroll
        for (int mt = 0; mt < 4; mt++) {
            redm[(warp_m * 64 + mt * 16 + tr) * 4 + warp_n]     = rmax[mt][0];
            redm[(warp_m * 64 + mt * 16 + tr + 8) * 4 + warp_n] = rmax[mt][1];
        }
    }
    __syncthreads();
    if (tid < 128) {
        rowm[tid] = fmaxf(fmaxf(redm[tid * 4], redm[tid * 4 + 1]),
                          fmaxf(redm[tid * 4 + 2], redm[tid * 4 + 3]));
    }
    __syncthreads();

    // per-row partial sumexp
    float rsum[4][2];
#pragma unroll
    for (int mt = 0; mt < 4; mt++) {
        const int r0l = warp_m * 64 + mt * 16 + tr;
        float mr0 = rowm[r0l], mr1 = rowm[r0l + 8];
        const float mm0 = (mr0 == NEG_INF) ? 0.f : mr0;
        const float mm1 = (mr1 == NEG_INF) ? 0.f : mr1;
        float s0 = 0.f, s1 = 0.f;
#pragma unroll
        for (int nt = 0; nt < 4; nt++) {
            s0 += __expf(acc[mt][nt][0] - mm0) + __expf(acc[mt][nt][1] - mm0);
            s1 += __expf(acc[mt][nt][2] - mm1) + __expf(acc[mt][nt][3] - mm1);
        }
        rsum[mt][0] = s0; rsum[mt][1] = s1;
    }
#pragma unroll
    for (int o = 1; o <= 2; o <<= 1)
#pragma unroll
        for (int mt = 0; mt < 4; mt++) {
            rsum[mt][0] += __shfl_xor_sync(0xffffffffu, rsum[mt][0], o);
            rsum[mt][1] += __shfl_xor_sync(0xffffffffu, rsum[mt][1], o);
        }
    if ((lane & 3) == 0) {
#pragma unroll
        for (int mt = 0; mt < 4; mt++) {
            reds[(warp_m * 64 + mt * 16 + tr) * 4 + warp_n]     = rsum[mt][0];
            reds[(warp_m * 64 + mt * 16 + tr + 8) * 4 + warp_n] = rsum[mt][1];
        }
    }
    __syncthreads();
    if (tid < 128) {
        const float s = reds[tid * 4] + reds[tid * 4 + 1]
                      + reds[tid * 4 + 2] + reds[tid * 4 + 3];
        stats1[((size_t)bh * 8 + blockIdx.x) * Tc + q0 + tid] =
            make_float2(rowm[tid], s);
    }
}

// ---------------------------------------------------------------------------
// Fold per-ktile stats -> per-row (max, 1/sum)
// ---------------------------------------------------------------------------
__global__ __launch_bounds__(256) void stats_reduce_kernel(
    const float2* __restrict__ s1, float2* __restrict__ s2)
{
    const int i  = blockIdx.x * 256 + threadIdx.x;   // 0 .. 128*1024-1
    const int bh = i >> 10;
    const int q  = i & 1023;
    float2 v[8];
    float m = -3.4e38f;
#pragma unroll
    for (int t = 0; t < 8; t++) {
        v[t] = s1[((size_t)bh * 8 + t) * Tc + q];
        m = fmaxf(m, v[t].x);
    }
    float s = 0.f;
#pragma unroll
    for (int t = 0; t < 8; t++)
        if (v[t].y != 0.f) s += v[t].y * __expf(v[t].x - m);
    s2[i] = make_float2(m, 1.0f / s);
}

// ---------------------------------------------------------------------------
// ctx via mma, fused softmax-apply:
//   reads raw logits, applies e = exp(v-m)*inv in-register,
//   writes e to the mandatory weights output, and uses e as mma A operand.
// ---------------------------------------------------------------------------
#define CWF_STRIDE_F 72u
#define CW_TILE_F  (128u * CWF_STRIDE_F * 4u)    // 36864 B
#define CV_TILE    (64u * SROW)                  // 9216 B
#define C_BUF      (CW_TILE_F + 2u * CV_TILE)    // 55296 B
#define SM_CTX     (2u * C_BUF)                  // 110592 B

__global__ __launch_bounds__(256) void ctx_mma_kernel(
    float* __restrict__ w,                       // raw logits in, weights out
    const float2* __restrict__ stats,            // per-row (m, 1/sum)
    const __nv_bfloat16* __restrict__ vhi, const __nv_bfloat16* __restrict__ vlo,
    __nv_bfloat16* __restrict__ ctxhi, __nv_bfloat16* __restrict__ ctxlo)
{
    extern __shared__ __align__(128) char smem[];
    const uint32_t sbase = smem_u32(smem);
    const int tid  = threadIdx.x;
    const int lane = tid & 31;
    const int wid  = tid >> 5;            // warp tile: 16 q-rows x 64 dk

    const int q0 = blockIdx.x * 128;
    const int bh = blockIdx.y;
    const int b  = bh >> 4;
    const int h  = bh & 15;

    const int tr = lane >> 2;
    const int tc = (lane & 3) * 2;

    // softmax stats for this thread's two rows
    const float2 st0 = stats[bh * Tc + q0 + wid * 16 + tr];
    const float2 st1 = stats[bh * Tc + q0 + wid * 16 + tr + 8];
    const float m0 = st0.x, i0 = st0.y;
    const float m1 = st1.x, i1 = st1.y;

    float acc[8][4];
#pragma unroll
    for (int i = 0; i < 8; i++)
#pragma unroll
        for (int j = 0; j < 4; j++) acc[i][j] = 0.f;

    auto stage = [&](uint32_t sb, int k0) {
        for (int i = tid; i < 2048; i += 256) {
            const int row = i >> 4;
            const int seg = i & 15;
            const uint32_t d = (uint32_t)row * (CWF_STRIDE_F * 4) + seg * 16;
            const size_t g = ((size_t)bh * Tc + q0 + row) * Tc + k0 + seg * 4;
            cpasync16(sb + d, w + g);
        }
        for (int i = tid; i < 512; i += 256) {
            const int row = i >> 3;
            const int seg = i & 7;
            const uint32_t d = (uint32_t)row * SROW + seg * 16;
            const size_t g = ((size_t)bh * Tc + k0 + row) * 64 + seg * 8;
            cpasync16(sb + CW_TILE_F + d,           vhi + g);
            cpasync16(sb + CW_TILE_F + CV_TILE + d, vlo + g);
        }
        asm volatile("cp.async.commit_group;" ::: "memory");
    };

    stage(sbase, 0);
    stage(sbase + C_BUF, 64);
    for (int ch = 0; ch < 16; ch++) {
        if (ch + 1 < 16) {
            asm volatile("cp.async.wait_group 1;" ::: "memory");
        } else {
            asm volatile("cp.async.wait_group 0;" ::: "memory");
        }
        __syncthreads();

        const uint32_t cb = sbase + (ch & 1) * C_BUF;
        const float* wsm = (const float*)(smem + (ch & 1) * C_BUF);
        float* wout0 = w + ((size_t)bh * Tc + q0 + wid * 16 + tr) * Tc + ch * 64;
        float* wout1 = wout0 + 8 * Tc;
#pragma unroll
        for (int ks = 0; ks < 4; ks++) {
            uint32_t ahi[4], alo[4], bhi[8][2], blo[8][2];
            {
                const uint32_t r0off = (uint32_t)(wid * 16 + tr) * CWF_STRIDE_F
                                       + ks * 16 + tc;
                float2 f00 = *(const float2*)(wsm + r0off);
                float2 f10 = *(const float2*)(wsm + r0off + 8 * CWF_STRIDE_F);
                float2 f01 = *(const float2*)(wsm + r0off + 8);
                float2 f11 = *(const float2*)(wsm + r0off + 8 * CWF_STRIDE_F + 8);
                // softmax apply: e = exp(v - m) * inv
                const float L2E = 1.4426950408889634f;
                f00.x = exp2f((f00.x - m0) * L2E) * i0;
                f00.y = exp2f((f00.y - m0) * L2E) * i0;
                f01.x = exp2f((f01.x - m0) * L2E) * i0;
                f01.y = exp2f((f01.y - m0) * L2E) * i0;
                f10.x = exp2f((f10.x - m1) * L2E) * i1;
                f10.y = exp2f((f10.y - m1) * L2E) * i1;
                f11.x = exp2f((f11.x - m1) * L2E) * i1;
                f11.y = exp2f((f11.y - m1) * L2E) * i1;
                // write softmaxed weights (mandatory output)
                *(float2*)(wout0 + ks * 16 + tc)     = f00;
                *(float2*)(wout0 + ks * 16 + tc + 8) = f01;
                *(float2*)(wout1 + ks * 16 + tc)     = f10;
                *(float2*)(wout1 + ks * 16 + tc + 8) = f11;
                split_pack2(f00.x, f00.y, ahi[0], alo[0]);
                split_pack2(f10.x, f10.y, ahi[1], alo[1]);
                split_pack2(f01.x, f01.y, ahi[2], alo[2]);
                split_pack2(f11.x, f11.y, ahi[3], alo[3]);
            }
#pragma unroll
            for (int nc = 0; nc < 4; nc++) {
                uint32_t tmp[4];
                const uint32_t addr = cb + CW_TILE_F
                    + (uint32_t)(ks * 16 + (lane & 7) + ((lane >> 3) & 1) * 8) * SROW
                    + nc * 32 + (lane >> 4) * 16;
                ldm_x4_trans(tmp, addr);
                bhi[nc * 2 + 0][0] = tmp[0]; bhi[nc * 2 + 0][1] = tmp[1];
                bhi[nc * 2 + 1][0] = tmp[2]; bhi[nc * 2 + 1][1] = tmp[3];
                ldm_x4_trans(tmp, addr + CV_TILE);
                blo[nc * 2 + 0][0] = tmp[0]; blo[nc * 2 + 0][1] = tmp[1];
                blo[nc * 2 + 1][0] = tmp[2]; blo[nc * 2 + 1][1] = tmp[3];
            }
#pragma unroll
            for (int nt = 0; nt < 8; nt++) {
                mma_bf16(acc[nt], ahi, bhi[nt]);
                mma_bf16(acc[nt], ahi, blo[nt]);
                mma_bf16(acc[nt], alo, bhi[nt]);
            }
        }

        if (ch + 2 < 16) {
            __syncthreads();
            stage(sbase + (ch & 1) * C_BUF, (ch + 2) * 64);
        }
    }

    // epilogue: split-store ctx in [b*T+t][D] layout
    const int t0 = q0 + wid * 16 + tr;
#pragma unroll
    for (int nt = 0; nt < 8; nt++) {
        const int dk = nt * 8 + tc;
        const size_t idx0 = ((size_t)(b * Tc + t0)) * Dc + h * 64 + dk;
        const size_t idx1 = ((size_t)(b * Tc + t0 + 8)) * Dc + h * 64 + dk;
        split_store2(ctxhi, ctxlo, idx0, acc[nt][0], acc[nt][1]);
        split_store2(ctxhi, ctxlo, idx1, acc[nt][2], acc[nt][3]);
    }
}

// ---------------------------------------------------------------------------
extern "C" void kernel_launch(void* const* d_in, const int* in_sizes, int n_in,
                              void* d_out, int out_size)
{
    const float* x    = (const float*)d_in[0];
    const int*   mask = (const int*)d_in[1];      // jax bool -> int32
    const float* Wqkv = (const float*)d_in[2];
    const float* bqkv = (const float*)d_in[3];
    const float* Wo   = (const float*)d_in[4];
    const float* bo   = (const float*)d_in[5];

    float* out     = (float*)d_out;
    float* weights = out + (size_t)Bc * Tc * Dc;

    __nv_bfloat16 *xhi, *xlo, *wqhi, *wqlo, *wohi, *wolo;
    __nv_bfloat16 *qhi, *qlo, *khi, *klo, *vhi, *vlo, *ctxhi, *ctxlo;
    float2 *stats1, *stats2;
    cudaGetSymbolAddress((void**)&xhi, g_xhi);
    cudaGetSymbolAddress((void**)&xlo, g_xlo);
    cudaGetSymbolAddress((void**)&wqhi, g_wqkvthi);
    cudaGetSymbolAddress((void**)&wqlo, g_wqkvtlo);
    cudaGetSymbolAddress((void**)&wohi, g_wothi);
    cudaGetSymbolAddress((void**)&wolo, g_wotlo);
    cudaGetSymbolAddress((void**)&qhi, g_qhi);
    cudaGetSymbolAddress((void**)&qlo, g_qlo);
    cudaGetSymbolAddress((void**)&khi, g_khi);
    cudaGetSymbolAddress((void**)&klo, g_klo);
    cudaGetSymbolAddress((void**)&vhi, g_vhi);
    cudaGetSymbolAddress((void**)&vlo, g_vlo);
    cudaGetSymbolAddress((void**)&ctxhi, g_ctxhi);
    cudaGetSymbolAddress((void**)&ctxlo, g_ctxlo);
    cudaGetSymbolAddress((void**)&stats1, g_stats1);
    cudaGetSymbolAddress((void**)&stats2, g_stats2);

    static int attr_set = 0;
    if (!attr_set) {
        cudaFuncSetAttribute(gemm_qkv_kernel,
                             cudaFuncAttributeMaxDynamicSharedMemorySize, GSMEM);
        cudaFuncSetAttribute(gemm_mma_split_kernel,
                             cudaFuncAttributeMaxDynamicSharedMemorySize, GSMEM);
        cudaFuncSetAttribute(scores_mma_kernel,
                             cudaFuncAttributeMaxDynamicSharedMemorySize, SM_SCORES);
        cudaFuncSetAttribute(ctx_mma_kernel,
                             cudaFuncAttributeMaxDynamicSharedMemorySize, SM_CTX);
        attr_set = 1;
    }

    const int nx4 = (Bc * Tc * Dc) / 4;

    // 0) input splits / weight transposes
    split_kernel<<<(nx4 + 255) / 256, 256>>>(x, xhi, xlo, nx4);
    transpose_split_kernel<<<dim3(D3c / 32, Dc / 32), 256>>>(Wqkv, wqhi, wqlo, Dc, D3c);
    transpose_split_kernel<<<dim3(Dc / 32, Dc / 32), 256>>>(Wo, wohi, wolo, Dc, Dc);

    // 1) QKV projection -> head-major bf16 splits
    gemm_qkv_kernel<<<dim3(D3c / TBN, (Bc * Tc) / TBM), 256, GSMEM>>>(
        xhi, xlo, wqhi, wqlo, bqkv, qhi, qlo, khi, klo, vhi, vlo, Dc);

    // 2) scores -> raw masked scaled logits + partial softmax stats
    scores_mma_kernel<<<dim3(Tc / 128, Tc / 128, Bc * NHc), 256, SM_SCORES>>>(
        qhi, qlo, khi, klo, mask, weights, stats1);

    // 3) fold stats -> per-row (m, 1/sum)
    stats_reduce_kernel<<<(128 * Tc) / 256, 256>>>(stats1, stats2);

    // 4) ctx with fused softmax-apply (writes final weights + ctx splits)
    ctx_mma_kernel<<<dim3(Tc / 128, Bc * NHc), 256, SM_CTX>>>(
        weights, stats2, vhi, vlo, ctxhi, ctxlo);

    // 5) output projection
    gemm_mma_split_kernel<<<dim3(Dc / TBN, (Bc * Tc) / TBM), 256, GSMEM>>>(
        ctxhi, ctxlo, wohi, wolo, bo, out, Dc, Dc);
}

// round 17
// speedup vs baseline: 2.8683x; 1.0796x over previous
#include <cuda_runtime.h>
#include <cuda_bf16.h>
#include <cstdint>

// Problem constants
#define Bc   8
#define Tc   1024
#define Dc   1024
#define NHc  16
#define DKc  64
#define D3c  3072

// ---------------------------------------------------------------------------
// Scratch (device globals — allocation-free rule)
// ---------------------------------------------------------------------------
__device__ __nv_bfloat16 g_xhi[(size_t)Bc * Tc * Dc];
__device__ __nv_bfloat16 g_xlo[(size_t)Bc * Tc * Dc];
__device__ __nv_bfloat16 g_wqkvthi[(size_t)D3c * Dc];   // Wqkv^T [N=3072][K=1024]
__device__ __nv_bfloat16 g_wqkvtlo[(size_t)D3c * Dc];
__device__ __nv_bfloat16 g_wothi[(size_t)Dc * Dc];      // Wo^T [N=1024][K=1024]
__device__ __nv_bfloat16 g_wotlo[(size_t)Dc * Dc];
// head-major splits produced by QKV epilogue: [bh][t][64]
__device__ __nv_bfloat16 g_qhi[(size_t)128 * Tc * DKc];
__device__ __nv_bfloat16 g_qlo[(size_t)128 * Tc * DKc];
__device__ __nv_bfloat16 g_khi[(size_t)128 * Tc * DKc];
__device__ __nv_bfloat16 g_klo[(size_t)128 * Tc * DKc];
__device__ __nv_bfloat16 g_vhi[(size_t)128 * Tc * DKc];
__device__ __nv_bfloat16 g_vlo[(size_t)128 * Tc * DKc];
// ctx splits: [b*T+t][D]
__device__ __nv_bfloat16 g_ctxhi[(size_t)Bc * Tc * Dc];
__device__ __nv_bfloat16 g_ctxlo[(size_t)Bc * Tc * Dc];
// softmax stats: partial per k-tile (m, sumexp); reduced (m, 1/sum)
__device__ float2 g_stats1[(size_t)128 * 8 * Tc];   // [bh][ktile][q]
__device__ float2 g_stats2[(size_t)128 * Tc];       // [bh][q]

// ---------------------------------------------------------------------------
// sm_80-era primitives (legal on plain sm_103 target)
// ---------------------------------------------------------------------------
__device__ __forceinline__ uint32_t smem_u32(const void* p) {
    uint32_t a;
    asm("{ .reg .u64 t; cvta.to.shared.u64 t, %1; cvt.u32.u64 %0, t; }"
        : "=r"(a) : "l"(p));
    return a;
}
__device__ __forceinline__ void cpasync16(uint32_t dst_smem, const void* src) {
    asm volatile("cp.async.cg.shared.global [%0], [%1], 16;"
                 :: "r"(dst_smem), "l"(src));
}
__device__ __forceinline__ void ldm_x4(uint32_t* r, uint32_t addr) {
    asm volatile("ldmatrix.sync.aligned.m8n8.x4.shared.b16 {%0,%1,%2,%3}, [%4];"
                 : "=r"(r[0]), "=r"(r[1]), "=r"(r[2]), "=r"(r[3]) : "r"(addr));
}
__device__ __forceinline__ void ldm_x4_trans(uint32_t* r, uint32_t addr) {
    asm volatile("ldmatrix.sync.aligned.m8n8.x4.trans.shared.b16 {%0,%1,%2,%3}, [%4];"
                 : "=r"(r[0]), "=r"(r[1]), "=r"(r[2]), "=r"(r[3]) : "r"(addr));
}
__device__ __forceinline__ void mma_bf16(float* d, const uint32_t* a, const uint32_t* b) {
    asm volatile(
        "mma.sync.aligned.m16n8k16.row.col.f32.bf16.bf16.f32 "
        "{%0,%1,%2,%3}, {%4,%5,%6,%7}, {%8,%9}, {%0,%1,%2,%3};"
        : "+f"(d[0]), "+f"(d[1]), "+f"(d[2]), "+f"(d[3])
        : "r"(a[0]), "r"(a[1]), "r"(a[2]), "r"(a[3]), "r"(b[0]), "r"(b[1]));
}

__device__ __forceinline__ void split_store2(
    __nv_bfloat16* hi, __nv_bfloat16* lo, size_t idx, float f0, float f1)
{
    __nv_bfloat16 h0 = __float2bfloat16(f0);
    __nv_bfloat16 h1 = __float2bfloat16(f1);
    __nv_bfloat16 l0 = __float2bfloat16(f0 - __bfloat162float(h0));
    __nv_bfloat16 l1 = __float2bfloat16(f1 - __bfloat162float(h1));
    ushort2 hp, lp;
    hp.x = *(unsigned short*)&h0; hp.y = *(unsigned short*)&h1;
    lp.x = *(unsigned short*)&l0; lp.y = *(unsigned short*)&l1;
    *(ushort2*)(hi + idx) = hp;
    *(ushort2*)(lo + idx) = lp;
}

// pack two floats -> bf16x2 hi reg + bf16x2 lo reg (split)
__device__ __forceinline__ void split_pack2(float f0, float f1,
                                            uint32_t& hi, uint32_t& lo)
{
    __nv_bfloat16 h0 = __float2bfloat16(f0);
    __nv_bfloat16 h1 = __float2bfloat16(f1);
    __nv_bfloat16 l0 = __float2bfloat16(f0 - __bfloat162float(h0));
    __nv_bfloat16 l1 = __float2bfloat16(f1 - __bfloat162float(h1));
    hi = (uint32_t)*(unsigned short*)&h0 | ((uint32_t)*(unsigned short*)&h1 << 16);
    lo = (uint32_t)*(unsigned short*)&l0 | ((uint32_t)*(unsigned short*)&l1 << 16);
}

// ---------------------------------------------------------------------------
// Conversion kernels
// ---------------------------------------------------------------------------
__global__ __launch_bounds__(256) void split_kernel(
    const float* __restrict__ in, __nv_bfloat16* __restrict__ hi,
    __nv_bfloat16* __restrict__ lo, int n4)
{
    int i = blockIdx.x * 256 + threadIdx.x;
    if (i >= n4) return;
    float4 v = ((const float4*)in)[i];
    __nv_bfloat16 h0 = __float2bfloat16(v.x);
    __nv_bfloat16 h1 = __float2bfloat16(v.y);
    __nv_bfloat16 h2 = __float2bfloat16(v.z);
    __nv_bfloat16 h3 = __float2bfloat16(v.w);
    __nv_bfloat16 l0 = __float2bfloat16(v.x - __bfloat162float(h0));
    __nv_bfloat16 l1 = __float2bfloat16(v.y - __bfloat162float(h1));
    __nv_bfloat16 l2 = __float2bfloat16(v.z - __bfloat162float(h2));
    __nv_bfloat16 l3 = __float2bfloat16(v.w - __bfloat162float(h3));
    ushort4 hp, lp;
    hp.x = *(unsigned short*)&h0; hp.y = *(unsigned short*)&h1;
    hp.z = *(unsigned short*)&h2; hp.w = *(unsigned short*)&h3;
    lp.x = *(unsigned short*)&l0; lp.y = *(unsigned short*)&l1;
    lp.z = *(unsigned short*)&l2; lp.w = *(unsigned short*)&l3;
    ((ushort4*)hi)[i] = hp;
    ((ushort4*)lo)[i] = lp;
}

__global__ __launch_bounds__(256) void transpose_split_kernel(
    const float* __restrict__ W, __nv_bfloat16* __restrict__ Thi,
    __nv_bfloat16* __restrict__ Tlo, int K, int N)
{
    __shared__ float t[32][33];
    const int n0 = blockIdx.x * 32;
    const int k0 = blockIdx.y * 32;
    const int tx = threadIdx.x & 31;
    const int ty = threadIdx.x >> 5;
    for (int j = ty; j < 32; j += 8)
        t[j][tx] = W[(size_t)(k0 + j) * N + n0 + tx];
    __syncthreads();
    for (int j = ty; j < 32; j += 8) {
        float v = t[tx][j];
        __nv_bfloat16 h = __float2bfloat16(v);
        __nv_bfloat16 l = __float2bfloat16(v - __bfloat162float(h));
        Thi[(size_t)(n0 + j) * K + k0 + tx] = h;
        Tlo[(size_t)(n0 + j) * K + k0 + tx] = l;
    }
}

// ---------------------------------------------------------------------------
// Projection GEMM mainloop (128x128 tile, 8 warps 64x32, K-chunk 32)
// 3-stage cp.async pipeline, XOR-swizzled 64B rows (no padding):
//   phys_seg = seg ^ ((row >> 1) & 3), seg = 16B column segment (0..3)
// ---------------------------------------------------------------------------
#define TBM 128
#define TBN 128
#define TBK 32
#define T_BYTES   8192u            // 128 rows * 64 B
#define BUF_BYTES (4u * T_BYTES)   // Ahi, Alo, Bhi, Blo = 32768
#define GSMEM     (3u * BUF_BYTES) // 98304 (3 stages)

__device__ __forceinline__ void stage_chunk(
    uint32_t sbase, const __nv_bfloat16* Ahi, const __nv_bfloat16* Alo,
    const __nv_bfloat16* Bhi, const __nv_bfloat16* Blo,
    int rowBase, int colBase, int K, int k0, int tid)
{
    const int quad = tid & 3;          // 16B segment 0..3
    const int r0   = tid >> 2;         // 0..63
#pragma unroll
    for (int p = 0; p < 2; p++) {
        const int row = r0 + p * 64;
        const uint32_t d = (uint32_t)row * 64
                         + (uint32_t)((quad ^ ((row >> 1) & 3)) * 16);
        const size_t ga = (size_t)(rowBase + row) * K + k0 + quad * 8;
        const size_t gb = (size_t)(colBase + row) * K + k0 + quad * 8;
        cpasync16(sbase + d,               Ahi + ga);
        cpasync16(sbase + T_BYTES + d,     Alo + ga);
        cpasync16(sbase + 2 * T_BYTES + d, Bhi + gb);
        cpasync16(sbase + 3 * T_BYTES + d, Blo + gb);
    }
    asm volatile("cp.async.commit_group;" ::: "memory");
}

// 3-stage schedule: prologue stages 0,1; each iter: wait(<=1 pending) -> sync
// -> stage ch+2 into the buffer consumed at iter ch-1 -> compute buf ch%3.
#define GEMM_MAINLOOP(ACC)                                                    \
    const int nchunks = K / TBK;                                              \
    stage_chunk(sbase, Ahi, Alo, Bhi, Blo, rowBase, colBase, K, 0, tid);      \
    stage_chunk(sbase + BUF_BYTES, Ahi, Alo, Bhi, Blo, rowBase, colBase, K,   \
                TBK, tid);                                                    \
    for (int ch = 0; ch < nchunks; ch++) {                                    \
        if (ch + 1 < nchunks) {                                               \
            asm volatile("cp.async.wait_group 1;" ::: "memory");              \
        } else {                                                              \
            asm volatile("cp.async.wait_group 0;" ::: "memory");              \
        }                                                                     \
        __syncthreads();                                                      \
        if (ch + 2 < nchunks)                                                 \
            stage_chunk(sbase + ((ch + 2) % 3) * BUF_BYTES, Ahi, Alo, Bhi,    \
                        Blo, rowBase, colBase, K, (ch + 2) * TBK, tid);       \
        const uint32_t cb = sbase + (ch % 3) * BUF_BYTES;                     \
        _Pragma("unroll")                                                     \
        for (int ks = 0; ks < 2; ks++) {                                      \
            uint32_t ahi[4][4], alo[4][4], bhi[4][2], blo[4][2];              \
            _Pragma("unroll")                                                 \
            for (int mt = 0; mt < 4; mt++) {                                  \
                const int arow = warp_m * 64 + mt * 16 + (lane & 15);         \
                const uint32_t aoff = (uint32_t)arow * 64                     \
                    + (uint32_t)(((ks * 2 + (lane >> 4))                      \
                                  ^ ((arow >> 1) & 3)) * 16);                 \
                ldm_x4(ahi[mt], cb + aoff);                                   \
                ldm_x4(alo[mt], cb + T_BYTES + aoff);                         \
            }                                                                 \
            _Pragma("unroll")                                                 \
            for (int pr = 0; pr < 2; pr++) {                                  \
                uint32_t tmp[4];                                              \
                const int brow = warp_n * 32 + pr * 16 + (lane >> 4) * 8      \
                               + (lane & 7);                                  \
                const uint32_t boff = (uint32_t)brow * 64                     \
                    + (uint32_t)(((ks * 2 + ((lane >> 3) & 1))                \
                                  ^ ((brow >> 1) & 3)) * 16);                 \
                ldm_x4(tmp, cb + 2 * T_BYTES + boff);                         \
                bhi[pr * 2 + 0][0] = tmp[0]; bhi[pr * 2 + 0][1] = tmp[1];     \
                bhi[pr * 2 + 1][0] = tmp[2]; bhi[pr * 2 + 1][1] = tmp[3];     \
                ldm_x4(tmp, cb + 3 * T_BYTES + boff);                         \
                blo[pr * 2 + 0][0] = tmp[0]; blo[pr * 2 + 0][1] = tmp[1];     \
                blo[pr * 2 + 1][0] = tmp[2]; blo[pr * 2 + 1][1] = tmp[3];     \
            }                                                                 \
            _Pragma("unroll")                                                 \
            for (int mt = 0; mt < 4; mt++)                                    \
                _Pragma("unroll")                                             \
                for (int nt = 0; nt < 4; nt++) {                              \
                    mma_bf16(ACC[mt][nt], ahi[mt], bhi[nt]);                  \
                    mma_bf16(ACC[mt][nt], ahi[mt], blo[nt]);                  \
                    mma_bf16(ACC[mt][nt], alo[mt], bhi[nt]);                  \
                }                                                             \
        }                                                                     \
    }

// ---------------------------------------------------------------------------
// QKV GEMM -> head-major bf16 hi/lo splits
// ---------------------------------------------------------------------------
__global__ __launch_bounds__(256, 2) void gemm_qkv_kernel(
    const __nv_bfloat16* __restrict__ Ahi, const __nv_bfloat16* __restrict__ Alo,
    const __nv_bfloat16* __restrict__ Bhi, const __nv_bfloat16* __restrict__ Blo,
    const float* __restrict__ bias,
    __nv_bfloat16* __restrict__ qhi, __nv_bfloat16* __restrict__ qlo,
    __nv_bfloat16* __restrict__ khi, __nv_bfloat16* __restrict__ klo,
    __nv_bfloat16* __restrict__ vhi, __nv_bfloat16* __restrict__ vlo,
    int K)
{
    extern __shared__ __align__(128) char smem[];
    const uint32_t sbase = smem_u32(smem);
    const int tid    = threadIdx.x;
    const int lane   = tid & 31;
    const int wid    = tid >> 5;
    const int warp_m = wid >> 2;
    const int warp_n = wid & 3;
    const int rowBase = blockIdx.y * TBM;
    const int colBase = blockIdx.x * TBN;

    float acc[4][4][4];
#pragma unroll
    for (int i = 0; i < 4; i++)
#pragma unroll
        for (int j = 0; j < 4; j++)
#pragma unroll
            for (int k = 0; k < 4; k++) acc[i][j][k] = 0.f;

    GEMM_MAINLOOP(acc)

    // epilogue: split + scatter to head-major layout
    const int region = colBase >> 10;          // 0=q,1=k,2=v
    __nv_bfloat16* dsthi = (region == 0) ? qhi : ((region == 1) ? khi : vhi);
    __nv_bfloat16* dstlo = (region == 0) ? qlo : ((region == 1) ? klo : vlo);
    const int b  = rowBase >> 10;
    const int tr = lane >> 2;
    const int tc = (lane & 3) * 2;
#pragma unroll
    for (int mt = 0; mt < 4; mt++) {
        const int t0 = (rowBase & 1023) + warp_m * 64 + mt * 16 + tr;
#pragma unroll
        for (int nt = 0; nt < 4; nt++) {
            const int c = colBase + warp_n * 32 + nt * 8 + tc;
            const int head = (c & 1023) >> 6;
            const int dk   = c & 63;
            const float b0 = bias[c], b1 = bias[c + 1];
            const size_t rowb = (size_t)(b * 16 + head) * Tc;
            split_store2(dsthi, dstlo, (rowb + t0) * 64 + dk,
                         acc[mt][nt][0] + b0, acc[mt][nt][1] + b1);
            split_store2(dsthi, dstlo, (rowb + t0 + 8) * 64 + dk,
                         acc[mt][nt][2] + b0, acc[mt][nt][3] + b1);
        }
    }
}

// ---------------------------------------------------------------------------
// Output projection GEMM (fp32 out + bias)
// ---------------------------------------------------------------------------
__global__ __launch_bounds__(256, 2) void gemm_mma_split_kernel(
    const __nv_bfloat16* __restrict__ Ahi, const __nv_bfloat16* __restrict__ Alo,
    const __nv_bfloat16* __restrict__ Bhi, const __nv_bfloat16* __restrict__ Blo,
    const float* __restrict__ bias, float* __restrict__ C, int N, int K)
{
    extern __shared__ __align__(128) char smem[];
    const uint32_t sbase = smem_u32(smem);
    const int tid    = threadIdx.x;
    const int lane   = tid & 31;
    const int wid    = tid >> 5;
    const int warp_m = wid >> 2;
    const int warp_n = wid & 3;
    const int rowBase = blockIdx.y * TBM;
    const int colBase = blockIdx.x * TBN;

    float acc[4][4][4];
#pragma unroll
    for (int i = 0; i < 4; i++)
#pragma unroll
        for (int j = 0; j < 4; j++)
#pragma unroll
            for (int k = 0; k < 4; k++) acc[i][j][k] = 0.f;

    GEMM_MAINLOOP(acc)

    const int tr = lane >> 2;
    const int tc = (lane & 3) * 2;
#pragma unroll
    for (int mt = 0; mt < 4; mt++) {
        const int r0 = rowBase + warp_m * 64 + mt * 16 + tr;
#pragma unroll
        for (int nt = 0; nt < 4; nt++) {
            const int c = colBase + warp_n * 32 + nt * 8 + tc;
            const float b0 = bias[c], b1 = bias[c + 1];
            float2 v0, v1;
            v0.x = acc[mt][nt][0] + b0; v0.y = acc[mt][nt][1] + b1;
            v1.x = acc[mt][nt][2] + b0; v1.y = acc[mt][nt][3] + b1;
            *(float2*)(C + (size_t)r0 * N + c) = v0;
            *(float2*)(C + (size_t)(r0 + 8) * N + c) = v1;
        }
    }
}

// ---------------------------------------------------------------------------
// Scores via mma: raw masked scaled logits -> gmem, plus per-(row, ktile)
// partial softmax stats (max, sumexp) -> g_stats1. (unchanged from R14)
// ---------------------------------------------------------------------------
#define SROW     144u
#define S_TILE   (128u * SROW)       // 18432
#define SM_SCORES (4u * S_TILE)      // 73728

__global__ __launch_bounds__(256) void scores_mma_kernel(
    const __nv_bfloat16* __restrict__ qhi, const __nv_bfloat16* __restrict__ qlo,
    const __nv_bfloat16* __restrict__ khi, const __nv_bfloat16* __restrict__ klo,
    const int* __restrict__ mask, float* __restrict__ logits,
    float2* __restrict__ stats1)
{
    extern __shared__ __align__(128) char smem[];
    const uint32_t sbase = smem_u32(smem);
    const int tid    = threadIdx.x;
    const int lane   = tid & 31;
    const int wid    = tid >> 5;
    const int warp_m = wid >> 2;
    const int warp_n = wid & 3;

    const int k0 = blockIdx.x * 128;
    const int q0 = blockIdx.y * 128;
    const int bh = blockIdx.z;
    const int b  = bh >> 4;

    for (int i = tid; i < 1024; i += 256) {
        const int row = i >> 3;
        const int seg = i & 7;
        const uint32_t d = (uint32_t)row * SROW + seg * 16;
        const size_t gq = ((size_t)bh * Tc + q0 + row) * 64 + seg * 8;
        const size_t gk = ((size_t)bh * Tc + k0 + row) * 64 + seg * 8;
        cpasync16(sbase + d,              qhi + gq);
        cpasync16(sbase + S_TILE + d,     qlo + gq);
        cpasync16(sbase + 2 * S_TILE + d, khi + gk);
        cpasync16(sbase + 3 * S_TILE + d, klo + gk);
    }
    asm volatile("cp.async.commit_group;" ::: "memory");
    asm volatile("cp.async.wait_group 0;" ::: "memory");
    __syncthreads();

    float acc[4][4][4];
#pragma unroll
    for (int i = 0; i < 4; i++)
#pragma unroll
        for (int j = 0; j < 4; j++)
#pragma unroll
            for (int k = 0; k < 4; k++) acc[i][j][k] = 0.f;

#pragma unroll
    for (int ks = 0; ks < 4; ks++) {
        uint32_t ahi[4][4], alo[4][4], bhi[4][2], blo[4][2];
#pragma unroll
        for (int mt = 0; mt < 4; mt++) {
            const uint32_t addr = sbase
                + (uint32_t)(warp_m * 64 + mt * 16 + (lane & 15)) * SROW
                + ks * 32 + (lane >> 4) * 16;
            ldm_x4(ahi[mt], addr);
            ldm_x4(alo[mt], addr + S_TILE);
        }
#pragma unroll
        for (int pr = 0; pr < 2; pr++) {
            uint32_t tmp[4];
            const uint32_t addr = sbase + 2 * S_TILE
                + (uint32_t)(warp_n * 32 + pr * 16 + (lane >> 4) * 8 + (lane & 7)) * SROW
                + ks * 32 + ((lane >> 3) & 1) * 16;
            ldm_x4(tmp, addr);
            bhi[pr * 2 + 0][0] = tmp[0]; bhi[pr * 2 + 0][1] = tmp[1];
            bhi[pr * 2 + 1][0] = tmp[2]; bhi[pr * 2 + 1][1] = tmp[3];
            ldm_x4(tmp, addr + S_TILE);
            blo[pr * 2 + 0][0] = tmp[0]; blo[pr * 2 + 0][1] = tmp[1];
            blo[pr * 2 + 1][0] = tmp[2]; blo[pr * 2 + 1][1] = tmp[3];
        }
#pragma unroll
        for (int mt = 0; mt < 4; mt++)
#pragma unroll
            for (int nt = 0; nt < 4; nt++) {
                mma_bf16(acc[mt][nt], ahi[mt], bhi[nt]);
                mma_bf16(acc[mt][nt], ahi[mt], blo[nt]);
                mma_bf16(acc[mt][nt], alo[mt], bhi[nt]);
            }
    }

    const float NEG_INF = __int_as_float(0xff800000);
    const int tr = lane >> 2;
    const int tc = (lane & 3) * 2;

    // mask + scale in place
    int mk[4][2];
#pragma unroll
    for (int nt = 0; nt < 4; nt++) {
        const int c = k0 + warp_n * 32 + nt * 8 + tc;
        mk[nt][0] = mask[b * Tc + c];
        mk[nt][1] = mask[b * Tc + c + 1];
    }
#pragma unroll
    for (int mt = 0; mt < 4; mt++)
#pragma unroll
        for (int nt = 0; nt < 4; nt++) {
            acc[mt][nt][0] = mk[nt][0] ? acc[mt][nt][0] * 0.125f : NEG_INF;
            acc[mt][nt][1] = mk[nt][1] ? acc[mt][nt][1] * 0.125f : NEG_INF;
            acc[mt][nt][2] = mk[nt][0] ? acc[mt][nt][2] * 0.125f : NEG_INF;
            acc[mt][nt][3] = mk[nt][1] ? acc[mt][nt][3] * 0.125f : NEG_INF;
        }

    // store raw logits
#pragma unroll
    for (int mt = 0; mt < 4; mt++) {
        const int q = q0 + warp_m * 64 + mt * 16 + tr;
#pragma unroll
        for (int nt = 0; nt < 4; nt++) {
            const int c = k0 + warp_n * 32 + nt * 8 + tc;
            float* outp = logits + ((size_t)bh * Tc + q) * Tc + c;
            *(float2*)outp = make_float2(acc[mt][nt][0], acc[mt][nt][1]);
            *(float2*)(outp + 8 * Tc) = make_float2(acc[mt][nt][2], acc[mt][nt][3]);
        }
    }

    // per-row partial max over this 128-col tile
    float rmax[4][2];
#pragma unroll
    for (int mt = 0; mt < 4; mt++) {
        float m0 = NEG_INF, m1 = NEG_INF;
#pragma unroll
        for (int nt = 0; nt < 4; nt++) {
            m0 = fmaxf(m0, fmaxf(acc[mt][nt][0], acc[mt][nt][1]));
            m1 = fmaxf(m1, fmaxf(acc[mt][nt][2], acc[mt][nt][3]));
        }
        rmax[mt][0] = m0; rmax[mt][1] = m1;
    }
#pragma unroll
    for (int o = 1; o <= 2; o <<= 1)
#pragma unroll
        for (int mt = 0; mt < 4; mt++) {
            rmax[mt][0] = fmaxf(rmax[mt][0], __shfl_xor_sync(0xffffffffu, rmax[mt][0], o));
            rmax[mt][1] = fmaxf(rmax[mt][1], __shfl_xor_sync(0xffffffffu, rmax[mt][1], o));
        }

    __syncthreads();                    // tiles no longer needed; reuse smem
    float* redm = (float*)smem;         // [128][4]
    float* rowm = (float*)smem + 512;   // [128]
    float* reds = (float*)smem + 1024;  // [128][4]
    if ((lane & 3) == 0) {
#pragma unroll
        for (int mt = 0; mt < 4; mt++) {
            redm[(warp_m * 64 + mt * 16 + tr) * 4 + warp_n]     = rmax[mt][0];
            redm[(warp_m * 64 + mt * 16 + tr + 8) * 4 + warp_n] = rmax[mt][1];
        }
    }
    __syncthreads();
    if (tid < 128) {
        rowm[tid] = fmaxf(fmaxf(redm[tid * 4], redm[tid * 4 + 1]),
                          fmaxf(redm[tid * 4 + 2], redm[tid * 4 + 3]));
    }
    __syncthreads();

    // per-row partial sumexp
    float rsum[4][2];
#pragma unroll
    for (int mt = 0; mt < 4; mt++) {
        const int r0l = warp_m * 64 + mt * 16 + tr;
        float mr0 = rowm[r0l], mr1 = rowm[r0l + 8];
        const float mm0 = (mr0 == NEG_INF) ? 0.f : mr0;
        const float mm1 = (mr1 == NEG_INF) ? 0.f : mr1;
        float s0 = 0.f, s1 = 0.f;
#pragma unroll
        for (int nt = 0; nt < 4; nt++) {
            s0 += __expf(acc[mt][nt][0] - mm0) + __expf(acc[mt][nt][1] - mm0);
            s1 += __expf(acc[mt][nt][2] - mm1) + __expf(acc[mt][nt][3] - mm1);
        }
        rsum[mt][0] = s0; rsum[mt][1] = s1;
    }
#pragma unroll
    for (int o = 1; o <= 2; o <<= 1)
#pragma unroll
        for (int mt = 0; mt < 4; mt++) {
            rsum[mt][0] += __shfl_xor_sync(0xffffffffu, rsum[mt][0], o);
            rsum[mt][1] += __shfl_xor_sync(0xffffffffu, rsum[mt][1], o);
        }
    if ((lane & 3) == 0) {
#pragma unroll
        for (int mt = 0; mt < 4; mt++) {
            reds[(warp_m * 64 + mt * 16 + tr) * 4 + warp_n]     = rsum[mt][0];
            reds[(warp_m * 64 + mt * 16 + tr + 8) * 4 + warp_n] = rsum[mt][1];
        }
    }
    __syncthreads();
    if (tid < 128) {
        const float s = reds[tid * 4] + reds[tid * 4 + 1]
                      + reds[tid * 4 + 2] + reds[tid * 4 + 3];
        stats1[((size_t)bh * 8 + blockIdx.x) * Tc + q0 + tid] =
            make_float2(rowm[tid], s);
    }
}

// ---------------------------------------------------------------------------
// Fold per-ktile stats -> per-row (max, 1/sum)
// ---------------------------------------------------------------------------
__global__ __launch_bounds__(256) void stats_reduce_kernel(
    const float2* __restrict__ s1, float2* __restrict__ s2)
{
    const int i  = blockIdx.x * 256 + threadIdx.x;   // 0 .. 128*1024-1
    const int bh = i >> 10;
    const int q  = i & 1023;
    float2 v[8];
    float m = -3.4e38f;
#pragma unroll
    for (int t = 0; t < 8; t++) {
        v[t] = s1[((size_t)bh * 8 + t) * Tc + q];
        m = fmaxf(m, v[t].x);
    }
    float s = 0.f;
#pragma unroll
    for (int t = 0; t < 8; t++)
        if (v[t].y != 0.f) s += v[t].y * __expf(v[t].x - m);
    s2[i] = make_float2(m, 1.0f / s);
}

// ---------------------------------------------------------------------------
// ctx via mma, fused softmax-apply (unchanged from R14)
// ---------------------------------------------------------------------------
#define CWF_STRIDE_F 72u
#define CW_TILE_F  (128u * CWF_STRIDE_F * 4u)    // 36864 B
#define CV_TILE    (64u * SROW)                  // 9216 B
#define C_BUF      (CW_TILE_F + 2u * CV_TILE)    // 55296 B
#define SM_CTX     (2u * C_BUF)                  // 110592 B

__global__ __launch_bounds__(256) void ctx_mma_kernel(
    float* __restrict__ w,                       // raw logits in, weights out
    const float2* __restrict__ stats,            // per-row (m, 1/sum)
    const __nv_bfloat16* __restrict__ vhi, const __nv_bfloat16* __restrict__ vlo,
    __nv_bfloat16* __restrict__ ctxhi, __nv_bfloat16* __restrict__ ctxlo)
{
    extern __shared__ __align__(128) char smem[];
    const uint32_t sbase = smem_u32(smem);
    const int tid  = threadIdx.x;
    const int lane = tid & 31;
    const int wid  = tid >> 5;            // warp tile: 16 q-rows x 64 dk

    const int q0 = blockIdx.x * 128;
    const int bh = blockIdx.y;
    const int b  = bh >> 4;
    const int h  = bh & 15;

    const int tr = lane >> 2;
    const int tc = (lane & 3) * 2;

    const float2 st0 = stats[bh * Tc + q0 + wid * 16 + tr];
    const float2 st1 = stats[bh * Tc + q0 + wid * 16 + tr + 8];
    const float m0 = st0.x, i0 = st0.y;
    const float m1 = st1.x, i1 = st1.y;

    float acc[8][4];
#pragma unroll
    for (int i = 0; i < 8; i++)
#pragma unroll
        for (int j = 0; j < 4; j++) acc[i][j] = 0.f;

    auto stage = [&](uint32_t sb, int k0) {
        for (int i = tid; i < 2048; i += 256) {
            const int row = i >> 4;
            const int seg = i & 15;
            const uint32_t d = (uint32_t)row * (CWF_STRIDE_F * 4) + seg * 16;
            const size_t g = ((size_t)bh * Tc + q0 + row) * Tc + k0 + seg * 4;
            cpasync16(sb + d, w + g);
        }
        for (int i = tid; i < 512; i += 256) {
            const int row = i >> 3;
            const int seg = i & 7;
            const uint32_t d = (uint32_t)row * SROW + seg * 16;
            const size_t g = ((size_t)bh * Tc + k0 + row) * 64 + seg * 8;
            cpasync16(sb + CW_TILE_F + d,           vhi + g);
            cpasync16(sb + CW_TILE_F + CV_TILE + d, vlo + g);
        }
        asm volatile("cp.async.commit_group;" ::: "memory");
    };

    stage(sbase, 0);
    stage(sbase + C_BUF, 64);
    for (int ch = 0; ch < 16; ch++) {
        if (ch + 1 < 16) {
            asm volatile("cp.async.wait_group 1;" ::: "memory");
        } else {
            asm volatile("cp.async.wait_group 0;" ::: "memory");
        }
        __syncthreads();

        const uint32_t cb = sbase + (ch & 1) * C_BUF;
        const float* wsm = (const float*)(smem + (ch & 1) * C_BUF);
        float* wout0 = w + ((size_t)bh * Tc + q0 + wid * 16 + tr) * Tc + ch * 64;
        float* wout1 = wout0 + 8 * Tc;
#pragma unroll
        for (int ks = 0; ks < 4; ks++) {
            uint32_t ahi[4], alo[4], bhi[8][2], blo[8][2];
            {
                const uint32_t r0off = (uint32_t)(wid * 16 + tr) * CWF_STRIDE_F
                                       + ks * 16 + tc;
                float2 f00 = *(const float2*)(wsm + r0off);
                float2 f10 = *(const float2*)(wsm + r0off + 8 * CWF_STRIDE_F);
                float2 f01 = *(const float2*)(wsm + r0off + 8);
                float2 f11 = *(const float2*)(wsm + r0off + 8 * CWF_STRIDE_F + 8);
                const float L2E = 1.4426950408889634f;
                f00.x = exp2f((f00.x - m0) * L2E) * i0;
                f00.y = exp2f((f00.y - m0) * L2E) * i0;
                f01.x = exp2f((f01.x - m0) * L2E) * i0;
                f01.y = exp2f((f01.y - m0) * L2E) * i0;
                f10.x = exp2f((f10.x - m1) * L2E) * i1;
                f10.y = exp2f((f10.y - m1) * L2E) * i1;
                f11.x = exp2f((f11.x - m1) * L2E) * i1;
                f11.y = exp2f((f11.y - m1) * L2E) * i1;
                *(float2*)(wout0 + ks * 16 + tc)     = f00;
                *(float2*)(wout0 + ks * 16 + tc + 8) = f01;
                *(float2*)(wout1 + ks * 16 + tc)     = f10;
                *(float2*)(wout1 + ks * 16 + tc + 8) = f11;
                split_pack2(f00.x, f00.y, ahi[0], alo[0]);
                split_pack2(f10.x, f10.y, ahi[1], alo[1]);
                split_pack2(f01.x, f01.y, ahi[2], alo[2]);
                split_pack2(f11.x, f11.y, ahi[3], alo[3]);
            }
#pragma unroll
            for (int nc = 0; nc < 4; nc++) {
                uint32_t tmp[4];
                const uint32_t addr = cb + CW_TILE_F
                    + (uint32_t)(ks * 16 + (lane & 7) + ((lane >> 3) & 1) * 8) * SROW
                    + nc * 32 + (lane >> 4) * 16;
                ldm_x4_trans(tmp, addr);
                bhi[nc * 2 + 0][0] = tmp[0]; bhi[nc * 2 + 0][1] = tmp[1];
                bhi[nc * 2 + 1][0] = tmp[2]; bhi[nc * 2 + 1][1] = tmp[3];
                ldm_x4_trans(tmp, addr + CV_TILE);
                blo[nc * 2 + 0][0] = tmp[0]; blo[nc * 2 + 0][1] = tmp[1];
                blo[nc * 2 + 1][0] = tmp[2]; blo[nc * 2 + 1][1] = tmp[3];
            }
#pragma unroll
            for (int nt = 0; nt < 8; nt++) {
                mma_bf16(acc[nt], ahi, bhi[nt]);
                mma_bf16(acc[nt], ahi, blo[nt]);
                mma_bf16(acc[nt], alo, bhi[nt]);
            }
        }

        if (ch + 2 < 16) {
            __syncthreads();
            stage(sbase + (ch & 1) * C_BUF, (ch + 2) * 64);
        }
    }

    // epilogue: split-store ctx in [b*T+t][D] layout
    const int t0 = q0 + wid * 16 + tr;
#pragma unroll
    for (int nt = 0; nt < 8; nt++) {
        const int dk = nt * 8 + tc;
        const size_t idx0 = ((size_t)(b * Tc + t0)) * Dc + h * 64 + dk;
        const size_t idx1 = ((size_t)(b * Tc + t0 + 8)) * Dc + h * 64 + dk;
        split_store2(ctxhi, ctxlo, idx0, acc[nt][0], acc[nt][1]);
        split_store2(ctxhi, ctxlo, idx1, acc[nt][2], acc[nt][3]);
    }
}

// ---------------------------------------------------------------------------
extern "C" void kernel_launch(void* const* d_in, const int* in_sizes, int n_in,
                              void* d_out, int out_size)
{
    const float* x    = (const float*)d_in[0];
    const int*   mask = (const int*)d_in[1];      // jax bool -> int32
    const float* Wqkv = (const float*)d_in[2];
    const float* bqkv = (const float*)d_in[3];
    const float* Wo   = (const float*)d_in[4];
    const float* bo   = (const float*)d_in[5];

    float* out     = (float*)d_out;
    float* weights = out + (size_t)Bc * Tc * Dc;

    __nv_bfloat16 *xhi, *xlo, *wqhi, *wqlo, *wohi, *wolo;
    __nv_bfloat16 *qhi, *qlo, *khi, *klo, *vhi, *vlo, *ctxhi, *ctxlo;
    float2 *stats1, *stats2;
    cudaGetSymbolAddress((void**)&xhi, g_xhi);
    cudaGetSymbolAddress((void**)&xlo, g_xlo);
    cudaGetSymbolAddress((void**)&wqhi, g_wqkvthi);
    cudaGetSymbolAddress((void**)&wqlo, g_wqkvtlo);
    cudaGetSymbolAddress((void**)&wohi, g_wothi);
    cudaGetSymbolAddress((void**)&wolo, g_wotlo);
    cudaGetSymbolAddress((void**)&qhi, g_qhi);
    cudaGetSymbolAddress((void**)&qlo, g_qlo);
    cudaGetSymbolAddress((void**)&khi, g_khi);
    cudaGetSymbolAddress((void**)&klo, g_klo);
    cudaGetSymbolAddress((void**)&vhi, g_vhi);
    cudaGetSymbolAddress((void**)&vlo, g_vlo);
    cudaGetSymbolAddress((void**)&ctxhi, g_ctxhi);
    cudaGetSymbolAddress((void**)&ctxlo, g_ctxlo);
    cudaGetSymbolAddress((void**)&stats1, g_stats1);
    cudaGetSymbolAddress((void**)&stats2, g_stats2);

    static int attr_set = 0;
    if (!attr_set) {
        cudaFuncSetAttribute(gemm_qkv_kernel,
                             cudaFuncAttributeMaxDynamicSharedMemorySize, GSMEM);
        cudaFuncSetAttribute(gemm_mma_split_kernel,
                             cudaFuncAttributeMaxDynamicSharedMemorySize, GSMEM);
        cudaFuncSetAttribute(scores_mma_kernel,
                             cudaFuncAttributeMaxDynamicSharedMemorySize, SM_SCORES);
        cudaFuncSetAttribute(ctx_mma_kernel,
                             cudaFuncAttributeMaxDynamicSharedMemorySize, SM_CTX);
        attr_set = 1;
    }

    const int nx4 = (Bc * Tc * Dc) / 4;

    // 0) input splits / weight transposes
    split_kernel<<<(nx4 + 255) / 256, 256>>>(x, xhi, xlo, nx4);
    transpose_split_kernel<<<dim3(D3c / 32, Dc / 32), 256>>>(Wqkv, wqhi, wqlo, Dc, D3c);
    transpose_split_kernel<<<dim3(Dc / 32, Dc / 32), 256>>>(Wo, wohi, wolo, Dc, Dc);

    // 1) QKV projection -> head-major bf16 splits
    gemm_qkv_kernel<<<dim3(D3c / TBN, (Bc * Tc) / TBM), 256, GSMEM>>>(
        xhi, xlo, wqhi, wqlo, bqkv, qhi, qlo, khi, klo, vhi, vlo, Dc);

    // 2) scores -> raw masked scaled logits + partial softmax stats
    scores_mma_kernel<<<dim3(Tc / 128, Tc / 128, Bc * NHc), 256, SM_SCORES>>>(
        qhi, qlo, khi, klo, mask, weights, stats1);

    // 3) fold stats -> per-row (m, 1/sum)
    stats_reduce_kernel<<<(128 * Tc) / 256, 256>>>(stats1, stats2);

    // 4) ctx with fused softmax-apply (writes final weights + ctx splits)
    ctx_mma_kernel<<<dim3(Tc / 128, Bc * NHc), 256, SM_CTX>>>(
        weights, stats2, vhi, vlo, ctxhi, ctxlo);

    // 5) output projection
    gemm_mma_split_kernel<<<dim3(Dc / TBN, (Bc * Tc) / TBM), 256, GSMEM>>>(
        ctxhi, ctxlo, wohi, wolo, bo, out, Dc, Dc);
}